// round 2
// baseline (speedup 1.0000x reference)
#include <cuda_runtime.h>
#include <math.h>

#define Bsz  8
#define Ssz  512
#define Hsz  768
#define Lsz  12
#define NHsz 12
#define DHsz 64
#define DFFsz 3072
#define NLsz 19
#define Tsz  (Bsz*Ssz)   // 4096 tokens

// ---------------- scratch (device globals; no allocation) ----------------
__device__ float g_x [Tsz*Hsz];
__device__ float g_t [Tsz*Hsz];
__device__ float g_q [Tsz*Hsz];
__device__ float g_k [Tsz*Hsz];
__device__ float g_v [Tsz*Hsz];
__device__ float g_c [Tsz*Hsz];
__device__ float g_sc[Bsz*NHsz*Ssz*Ssz];   // 25.2M floats
__device__ float g_h [Tsz*DFFsz];
__device__ float g_lg[Tsz*NLsz];

// ---------------- embedding: tok + pos ----------------
__global__ void embed_kernel(const int* __restrict__ ids,
                             const float* __restrict__ tok,
                             const float* __restrict__ pos,
                             float* __restrict__ out)
{
    int t = blockIdx.x;             // 0..4095
    int s = t & (Ssz-1);
    int id = ids[t];
    const float* tp = tok + (size_t)id*Hsz;
    const float* pp = pos + (size_t)s*Hsz;
    float* op = out + (size_t)t*Hsz;
    for (int c = threadIdx.x; c < Hsz; c += blockDim.x)
        op[c] = tp[c] + pp[c];
}

// ---------------- layernorm (block per row, 256 threads, 3 elems/thr) ----------------
__global__ void ln_kernel(const float* __restrict__ in,
                          const float* __restrict__ gamma,
                          const float* __restrict__ beta,
                          float* __restrict__ out)
{
    __shared__ float sh[32];
    int row = blockIdx.x;
    int tid = threadIdx.x;
    const float* p = in + (size_t)row*Hsz;
    float v0 = p[tid], v1 = p[tid+256], v2 = p[tid+512];
    float s = v0+v1+v2;
    // block reduce sum
    int lane = tid & 31, w = tid >> 5;
    for (int o = 16; o; o >>= 1) s += __shfl_xor_sync(0xffffffffu, s, o);
    if (!lane) sh[w] = s;
    __syncthreads();
    if (w == 0) {
        s = (lane < 8) ? sh[lane] : 0.f;
        for (int o = 4; o; o >>= 1) s += __shfl_xor_sync(0xffffffffu, s, o);
        if (!lane) sh[0] = s;
    }
    __syncthreads();
    float mean = sh[0] * (1.0f/Hsz);
    __syncthreads();
    float d0 = v0-mean, d1 = v1-mean, d2 = v2-mean;
    float q = d0*d0 + d1*d1 + d2*d2;
    for (int o = 16; o; o >>= 1) q += __shfl_xor_sync(0xffffffffu, q, o);
    if (!lane) sh[w] = q;
    __syncthreads();
    if (w == 0) {
        q = (lane < 8) ? sh[lane] : 0.f;
        for (int o = 4; o; o >>= 1) q += __shfl_xor_sync(0xffffffffu, q, o);
        if (!lane) sh[0] = q;
    }
    __syncthreads();
    float var = sh[0] * (1.0f/Hsz);
    float inv = rsqrtf(var + 1e-12f);
    float* op = out + (size_t)row*Hsz;
    op[tid    ] = d0*inv*gamma[tid    ] + beta[tid    ];
    op[tid+256] = d1*inv*gamma[tid+256] + beta[tid+256];
    op[tid+512] = d2*inv*gamma[tid+512] + beta[tid+512];
}

// ---------------- SGEMM: C = A[MxK] @ W[KxN] + bias (+gelu | +residual) ----------------
// mode: 0 = bias, 1 = bias+gelu, 2 = bias+residual
#define BM 64
#define BN 64
#define BK 16
__global__ void sgemm_kernel(const float* __restrict__ A, const float* __restrict__ W,
                             const float* __restrict__ bias, const float* __restrict__ res,
                             float* __restrict__ C, int M, int N, int K, int mode)
{
    __shared__ float As[BM][BK+1];
    __shared__ float Ws[BK][BN];
    int m0 = blockIdx.y * BM;
    int n0 = blockIdx.x * BN;
    int tid = threadIdx.x;          // 256
    int ty = tid >> 4, tx = tid & 15;
    float acc[4][4] = {};
    for (int k0 = 0; k0 < K; k0 += BK) {
        #pragma unroll
        for (int i = 0; i < 4; i++) {
            int idx = tid + i*256;
            int r = idx >> 4, c = idx & 15;
            As[r][c] = A[(size_t)(m0+r)*K + (k0+c)];
        }
        #pragma unroll
        for (int i = 0; i < 4; i++) {
            int idx = tid + i*256;
            int r = idx >> 6, c = idx & 63;
            int n = n0 + c;
            Ws[r][c] = (n < N) ? W[(size_t)(k0+r)*N + n] : 0.f;
        }
        __syncthreads();
        #pragma unroll
        for (int kk = 0; kk < BK; kk++) {
            float a[4], b[4];
            #pragma unroll
            for (int i = 0; i < 4; i++) a[i] = As[ty*4+i][kk];
            #pragma unroll
            for (int j = 0; j < 4; j++) b[j] = Ws[kk][tx*4+j];
            #pragma unroll
            for (int i = 0; i < 4; i++)
                #pragma unroll
                for (int j = 0; j < 4; j++)
                    acc[i][j] = fmaf(a[i], b[j], acc[i][j]);
        }
        __syncthreads();
    }
    #pragma unroll
    for (int i = 0; i < 4; i++) {
        int m = m0 + ty*4 + i;
        #pragma unroll
        for (int j = 0; j < 4; j++) {
            int n = n0 + tx*4 + j;
            if (n < N) {
                float v = acc[i][j] + bias[n];
                if (mode == 1) {
                    float x3 = v*v*v;
                    v = 0.5f*v*(1.0f + tanhf(0.7978845608028654f*(v + 0.044715f*x3)));
                } else if (mode == 2) {
                    v += res[(size_t)m*N + n];
                }
                C[(size_t)m*N + n] = v;
            }
        }
    }
}

// ---------------- attention scores: sc[b,h,i,j] = scale*q.k + bias(j) ----------------
__global__ void attn_scores_kernel(const float* __restrict__ q, const float* __restrict__ k,
                                   const int* __restrict__ mask, float* __restrict__ sc)
{
    int bh = blockIdx.z;
    int b = bh / NHsz, h = bh % NHsz;
    int i0 = blockIdx.y * 64, j0 = blockIdx.x * 64;
    __shared__ float Qs[64][65], Ks[64][65];
    int tid = threadIdx.x;
    #pragma unroll
    for (int it = 0; it < 16; it++) {
        int idx = tid + it*256;
        int r = idx >> 6, c = idx & 63;
        Qs[r][c] = q[(size_t)(b*Ssz + i0 + r)*Hsz + h*DHsz + c];
        Ks[r][c] = k[(size_t)(b*Ssz + j0 + r)*Hsz + h*DHsz + c];
    }
    __syncthreads();
    int ty = tid >> 4, tx = tid & 15;
    float acc[4][4] = {};
    #pragma unroll
    for (int d = 0; d < 64; d++) {
        float a[4], bb[4];
        #pragma unroll
        for (int i = 0; i < 4; i++) a[i] = Qs[ty*4+i][d];
        #pragma unroll
        for (int j = 0; j < 4; j++) bb[j] = Ks[tx*4+j][d];
        #pragma unroll
        for (int i = 0; i < 4; i++)
            #pragma unroll
            for (int j = 0; j < 4; j++)
                acc[i][j] = fmaf(a[i], bb[j], acc[i][j]);
    }
    #pragma unroll
    for (int j = 0; j < 4; j++) {
        int jj = j0 + tx*4 + j;
        float bj = mask[b*Ssz + jj] ? 0.f : -1e9f;
        #pragma unroll
        for (int i = 0; i < 4; i++) {
            int ii = i0 + ty*4 + i;
            sc[((size_t)bh*Ssz + ii)*Ssz + jj] = acc[i][j]*0.125f + bj;
        }
    }
}

// ---------------- softmax over last dim (512), block per row ----------------
__global__ void softmax_kernel(float* __restrict__ sc)
{
    __shared__ float sh[32];
    size_t row = blockIdx.x;
    float* p = sc + row*Ssz;
    int tid = threadIdx.x;
    float a = p[tid], b = p[tid+256];
    float m = fmaxf(a, b);
    int lane = tid & 31, w = tid >> 5;
    for (int o = 16; o; o >>= 1) m = fmaxf(m, __shfl_xor_sync(0xffffffffu, m, o));
    if (!lane) sh[w] = m;
    __syncthreads();
    if (w == 0) {
        m = (lane < 8) ? sh[lane] : -1e30f;
        for (int o = 4; o; o >>= 1) m = fmaxf(m, __shfl_xor_sync(0xffffffffu, m, o));
        if (!lane) sh[0] = m;
    }
    __syncthreads();
    m = sh[0];
    __syncthreads();
    float e1 = __expf(a - m), e2 = __expf(b - m);
    float s = e1 + e2;
    for (int o = 16; o; o >>= 1) s += __shfl_xor_sync(0xffffffffu, s, o);
    if (!lane) sh[w] = s;
    __syncthreads();
    if (w == 0) {
        s = (lane < 8) ? sh[lane] : 0.f;
        for (int o = 4; o; o >>= 1) s += __shfl_xor_sync(0xffffffffu, s, o);
        if (!lane) sh[0] = s;
    }
    __syncthreads();
    float inv = 1.0f / sh[0];
    p[tid]     = e1 * inv;
    p[tid+256] = e2 * inv;
}

// ---------------- ctx[b,i,h,:] = sum_j a[b,h,i,j] * v[b,j,h,:] ----------------
__global__ void attn_av_kernel(const float* __restrict__ sc, const float* __restrict__ v,
                               float* __restrict__ ctx)
{
    int bh = blockIdx.y;
    int b = bh / NHsz, h = bh % NHsz;
    int i0 = blockIdx.x * 64;
    __shared__ float As[64][65], Vs[64][65];
    int tid = threadIdx.x;
    int ty = tid >> 4, tx = tid & 15;
    float acc[4][4] = {};
    for (int j0 = 0; j0 < Ssz; j0 += 64) {
        #pragma unroll
        for (int it = 0; it < 16; it++) {
            int idx = tid + it*256;
            int r = idx >> 6, c = idx & 63;
            As[r][c] = sc[((size_t)bh*Ssz + i0 + r)*Ssz + j0 + c];
            Vs[r][c] = v[(size_t)(b*Ssz + j0 + r)*Hsz + h*DHsz + c];
        }
        __syncthreads();
        #pragma unroll
        for (int kk = 0; kk < 64; kk++) {
            float a[4], bb[4];
            #pragma unroll
            for (int i = 0; i < 4; i++) a[i] = As[ty*4+i][kk];
            #pragma unroll
            for (int j = 0; j < 4; j++) bb[j] = Vs[kk][tx*4+j];
            #pragma unroll
            for (int i = 0; i < 4; i++)
                #pragma unroll
                for (int j = 0; j < 4; j++)
                    acc[i][j] = fmaf(a[i], bb[j], acc[i][j]);
        }
        __syncthreads();
    }
    #pragma unroll
    for (int i = 0; i < 4; i++)
        #pragma unroll
        for (int j = 0; j < 4; j++)
            ctx[(size_t)(b*Ssz + i0 + ty*4 + i)*Hsz + h*DHsz + tx*4 + j] = acc[i][j];
}

// ---------------- CRF: numerator + forward algorithm + final scalar ----------------
__global__ void crf_kernel(const float* __restrict__ lg, const int* __restrict__ labels,
                           const int* __restrict__ mask, const float* __restrict__ st,
                           const float* __restrict__ en, const float* __restrict__ tr,
                           float* __restrict__ out)
{
    __shared__ float s_tr[NLsz*NLsz];
    __shared__ float s_res[Bsz];
    for (int i = threadIdx.x; i < NLsz*NLsz; i += blockDim.x) s_tr[i] = tr[i];
    __syncthreads();
    int warp = threadIdx.x >> 5, lane = threadIdx.x & 31;
    if (warp < Bsz) {
        int b = warp;
        const int* lab = labels + b*Ssz;
        const int* mk  = mask + b*Ssz;
        const float* lgb = lg + (size_t)b*Ssz*NLsz;
        // numerator
        float part = 0.f; int cnt = 0;
        for (int t = lane; t < Ssz; t += 32) {
            cnt += mk[t];
            if (t >= 1) {
                float mf = (float)mk[t];
                part += (s_tr[lab[t-1]*NLsz + lab[t]] + lgb[t*NLsz + lab[t]]) * mf;
            }
        }
        for (int o = 16; o; o >>= 1) {
            part += __shfl_xor_sync(0xffffffffu, part, o);
            cnt  += __shfl_xor_sync(0xffffffffu, cnt, o);
        }
        float num = 0.f;
        if (lane == 0) {
            int l0 = lab[0];
            num = st[l0] + lgb[l0] + part + en[lab[cnt-1]];
        }
        // forward algorithm (lane j holds alpha_j)
        int j = lane;
        float alpha = (j < NLsz) ? st[j] + lgb[j] : -1e30f;
        for (int t = 1; t < Ssz; t++) {
            float g[NLsz];
            #pragma unroll
            for (int i = 0; i < NLsz; i++)
                g[i] = __shfl_sync(0xffffffffu, alpha, i) + ((j < NLsz) ? s_tr[i*NLsz + j] : 0.f);
            float mv = g[0];
            #pragma unroll
            for (int i = 1; i < NLsz; i++) mv = fmaxf(mv, g[i]);
            float sum = 0.f;
            #pragma unroll
            for (int i = 0; i < NLsz; i++) sum += expf(g[i] - mv);
            float nxt = mv + logf(sum) + ((j < NLsz) ? lgb[t*NLsz + j] : 0.f);
            if (mk[t] > 0 && j < NLsz) alpha = nxt;
        }
        float v = (j < NLsz) ? alpha + en[j] : -1e30f;
        float mv = v;
        for (int o = 16; o; o >>= 1) mv = fmaxf(mv, __shfl_xor_sync(0xffffffffu, mv, o));
        float s = (j < NLsz) ? expf(v - mv) : 0.f;
        for (int o = 16; o; o >>= 1) s += __shfl_xor_sync(0xffffffffu, s, o);
        if (lane == 0) s_res[b] = (mv + logf(s)) - num;
    }
    __syncthreads();
    if (threadIdx.x == 0) {
        float tot = 0.f;
        for (int b = 0; b < Bsz; b++) tot += s_res[b];
        out[0] = tot;
    }
}

// ---------------- host ----------------
static inline void gemm(const float* A, const float* W, const float* bias,
                        const float* res, float* C, int M, int N, int K, int mode)
{
    dim3 grid((N + BN - 1)/BN, M/BM);
    sgemm_kernel<<<grid, 256>>>(A, W, bias, res, C, M, N, K, mode);
}

extern "C" void kernel_launch(void* const* d_in, const int* in_sizes, int n_in,
                              void* d_out, int out_size)
{
    const int*   input_ids = (const int*)  d_in[0];
    const int*   attn_mask = (const int*)  d_in[1];
    const int*   labels    = (const int*)  d_in[2];
    const float* token_emb = (const float*)d_in[3];
    const float* pos_emb   = (const float*)d_in[4];
    const float* ln_emb_s  = (const float*)d_in[5];
    const float* ln_emb_b  = (const float*)d_in[6];
    const float* Wq        = (const float*)d_in[7];
    const float* bq        = (const float*)d_in[8];
    const float* Wk        = (const float*)d_in[9];
    const float* bk        = (const float*)d_in[10];
    const float* Wv        = (const float*)d_in[11];
    const float* bv        = (const float*)d_in[12];
    const float* Wo        = (const float*)d_in[13];
    const float* bo        = (const float*)d_in[14];
    const float* ln1_s     = (const float*)d_in[15];
    const float* ln1_b     = (const float*)d_in[16];
    const float* W1        = (const float*)d_in[17];
    const float* b1        = (const float*)d_in[18];
    const float* W2        = (const float*)d_in[19];
    const float* b2        = (const float*)d_in[20];
    const float* ln2_s     = (const float*)d_in[21];
    const float* ln2_b     = (const float*)d_in[22];
    const float* cls_W     = (const float*)d_in[23];
    const float* cls_b     = (const float*)d_in[24];
    const float* start_tr  = (const float*)d_in[25];
    const float* end_tr    = (const float*)d_in[26];
    const float* trans     = (const float*)d_in[27];

    float *x, *t, *q, *k, *v, *c, *sc, *h, *lg;
    { void* p; cudaGetSymbolAddress(&p, g_x);  x  = (float*)p; }
    { void* p; cudaGetSymbolAddress(&p, g_t);  t  = (float*)p; }
    { void* p; cudaGetSymbolAddress(&p, g_q);  q  = (float*)p; }
    { void* p; cudaGetSymbolAddress(&p, g_k);  k  = (float*)p; }
    { void* p; cudaGetSymbolAddress(&p, g_v);  v  = (float*)p; }
    { void* p; cudaGetSymbolAddress(&p, g_c);  c  = (float*)p; }
    { void* p; cudaGetSymbolAddress(&p, g_sc); sc = (float*)p; }
    { void* p; cudaGetSymbolAddress(&p, g_h);  h  = (float*)p; }
    { void* p; cudaGetSymbolAddress(&p, g_lg); lg = (float*)p; }

    // embedding + LN
    embed_kernel<<<Tsz, 256>>>(input_ids, token_emb, pos_emb, t);
    ln_kernel<<<Tsz, 256>>>(t, ln_emb_s, ln_emb_b, x);

    for (int l = 0; l < Lsz; l++) {
        const float* wq = Wq + (size_t)l*Hsz*Hsz;
        const float* wk = Wk + (size_t)l*Hsz*Hsz;
        const float* wv = Wv + (size_t)l*Hsz*Hsz;
        const float* wo = Wo + (size_t)l*Hsz*Hsz;
        gemm(x, wq, bq + l*Hsz, nullptr, q, Tsz, Hsz, Hsz, 0);
        gemm(x, wk, bk + l*Hsz, nullptr, k, Tsz, Hsz, Hsz, 0);
        gemm(x, wv, bv + l*Hsz, nullptr, v, Tsz, Hsz, Hsz, 0);

        attn_scores_kernel<<<dim3(Ssz/64, Ssz/64, Bsz*NHsz), 256>>>(q, k, attn_mask, sc);
        softmax_kernel<<<Bsz*NHsz*Ssz, 256>>>(sc);
        attn_av_kernel<<<dim3(Ssz/64, Bsz*NHsz), 256>>>(sc, v, c);

        gemm(c, wo, bo + l*Hsz, x, t, Tsz, Hsz, Hsz, 2);
        ln_kernel<<<Tsz, 256>>>(t, ln1_s + l*Hsz, ln1_b + l*Hsz, x);

        gemm(x, W1 + (size_t)l*Hsz*DFFsz, b1 + l*DFFsz, nullptr, h, Tsz, DFFsz, Hsz, 1);
        gemm(h, W2 + (size_t)l*DFFsz*Hsz, b2 + l*Hsz, x, t, Tsz, Hsz, DFFsz, 2);
        ln_kernel<<<Tsz, 256>>>(t, ln2_s + l*Hsz, ln2_b + l*Hsz, x);
    }

    // classifier logits
    gemm(x, cls_W, cls_b, nullptr, lg, Tsz, NLsz, Hsz, 0);

    // CRF loss
    crf_kernel<<<1, 256>>>(lg, labels, attn_mask, start_tr, end_tr, trans, (float*)d_out);
}

// round 3
// speedup vs baseline: 3.3338x; 3.3338x over previous
#include <cuda_runtime.h>
#include <cuda_bf16.h>
#include <math.h>
#include <stdint.h>

#define Bsz  8
#define Ssz  512
#define Hsz  768
#define Lsz  12
#define NHsz 12
#define DHsz 64
#define DFFsz 3072
#define NLsz 19
#define Tsz  (Bsz*Ssz)   // 4096 tokens

// ---------------- scratch (device globals; no allocation) ----------------
__device__ float g_x [Tsz*Hsz];
__device__ float g_t [Tsz*Hsz];
__device__ float g_q [Tsz*Hsz];
__device__ float g_k [Tsz*Hsz];
__device__ float g_v [Tsz*Hsz];
__device__ float g_c [Tsz*Hsz];
__device__ float g_sc[Bsz*NHsz*Ssz*Ssz];
__device__ float g_h [Tsz*DFFsz];
__device__ float g_lg[Tsz*NLsz];

// ---------------- embedding ----------------
__global__ void embed_kernel(const int* __restrict__ ids,
                             const float* __restrict__ tok,
                             const float* __restrict__ pos,
                             float* __restrict__ out)
{
    int t = blockIdx.x;
    int s = t & (Ssz-1);
    int id = ids[t];
    const float* tp = tok + (size_t)id*Hsz;
    const float* pp = pos + (size_t)s*Hsz;
    float* op = out + (size_t)t*Hsz;
    for (int c = threadIdx.x; c < Hsz; c += blockDim.x)
        op[c] = tp[c] + pp[c];
}

// ---------------- layernorm ----------------
__global__ void ln_kernel(const float* __restrict__ in,
                          const float* __restrict__ gamma,
                          const float* __restrict__ beta,
                          float* __restrict__ out)
{
    __shared__ float sh[32];
    int row = blockIdx.x;
    int tid = threadIdx.x;
    const float* p = in + (size_t)row*Hsz;
    float v0 = p[tid], v1 = p[tid+256], v2 = p[tid+512];
    float s = v0+v1+v2;
    int lane = tid & 31, w = tid >> 5;
    for (int o = 16; o; o >>= 1) s += __shfl_xor_sync(0xffffffffu, s, o);
    if (!lane) sh[w] = s;
    __syncthreads();
    if (w == 0) {
        s = (lane < 8) ? sh[lane] : 0.f;
        for (int o = 4; o; o >>= 1) s += __shfl_xor_sync(0xffffffffu, s, o);
        if (!lane) sh[0] = s;
    }
    __syncthreads();
    float mean = sh[0] * (1.0f/Hsz);
    __syncthreads();
    float d0 = v0-mean, d1 = v1-mean, d2 = v2-mean;
    float q = d0*d0 + d1*d1 + d2*d2;
    for (int o = 16; o; o >>= 1) q += __shfl_xor_sync(0xffffffffu, q, o);
    if (!lane) sh[w] = q;
    __syncthreads();
    if (w == 0) {
        q = (lane < 8) ? sh[lane] : 0.f;
        for (int o = 4; o; o >>= 1) q += __shfl_xor_sync(0xffffffffu, q, o);
        if (!lane) sh[0] = q;
    }
    __syncthreads();
    float var = sh[0] * (1.0f/Hsz);
    float inv = rsqrtf(var + 1e-12f);
    float* op = out + (size_t)row*Hsz;
    op[tid    ] = d0*inv*gamma[tid    ] + beta[tid    ];
    op[tid+256] = d1*inv*gamma[tid+256] + beta[tid+256];
    op[tid+512] = d2*inv*gamma[tid+512] + beta[tid+512];
}

// ================= bf16 MMA GEMM (HMMA) =================
// C[M,N] = A[M,K] @ W[K,N] + bias (+gelu | +residual)
// Block 128x128x32, 256 threads (8 warps, 64x32 warp tiles)
#define APAD 40   // 32 + 8 pad (bf16 elems per smem row of A)
#define WPAD 136  // 128 + 8 pad

__device__ __forceinline__ void ldsm_x4(uint32_t (&r)[4], uint32_t addr) {
    asm volatile("ldmatrix.sync.aligned.m8n8.x4.shared.b16 {%0,%1,%2,%3}, [%4];"
        : "=r"(r[0]),"=r"(r[1]),"=r"(r[2]),"=r"(r[3]) : "r"(addr));
}
__device__ __forceinline__ void ldsm_x4_t(uint32_t (&r)[4], uint32_t addr) {
    asm volatile("ldmatrix.sync.aligned.m8n8.x4.trans.shared.b16 {%0,%1,%2,%3}, [%4];"
        : "=r"(r[0]),"=r"(r[1]),"=r"(r[2]),"=r"(r[3]) : "r"(addr));
}
__device__ __forceinline__ void mma16816(float (&c)[4], const uint32_t (&a)[4],
                                         uint32_t b0, uint32_t b1) {
    asm volatile("mma.sync.aligned.m16n8k16.row.col.f32.bf16.bf16.f32 "
        "{%0,%1,%2,%3}, {%4,%5,%6,%7}, {%8,%9}, {%0,%1,%2,%3};"
        : "+f"(c[0]),"+f"(c[1]),"+f"(c[2]),"+f"(c[3])
        : "r"(a[0]),"r"(a[1]),"r"(a[2]),"r"(a[3]), "r"(b0),"r"(b1));
}

__device__ __forceinline__ void gemm_core(
    const float* __restrict__ A, const float* __restrict__ W,
    const float* __restrict__ bias, const float* __restrict__ res,
    float* __restrict__ C, int N, int K, int mode, int m0, int n0)
{
    __shared__ __nv_bfloat16 As[2][128*APAD];
    __shared__ __nv_bfloat16 Ws[2][32*WPAD];
    int tid = threadIdx.x;
    int warp = tid >> 5, lane = tid & 31;
    int wm = warp >> 2;   // 0..1
    int wn = warp & 3;    // 0..3

    float acc[4][4][4];
    #pragma unroll
    for (int i = 0; i < 4; i++)
        #pragma unroll
        for (int j = 0; j < 4; j++)
            #pragma unroll
            for (int e = 0; e < 4; e++) acc[i][j][e] = 0.f;

    float4 ra[4], rw[4];
    const int KT = K >> 5;   // K/32

    // prologue: load tile 0
    #pragma unroll
    for (int i = 0; i < 4; i++) {
        int idx = tid + i*256;
        int r  = idx >> 3, c4 = idx & 7;
        ra[i] = *(const float4*)(A + (size_t)(m0 + r)*K + c4*4);
        int rr = idx >> 5, cw = idx & 31;
        rw[i] = *(const float4*)(W + (size_t)rr*N + n0 + cw*4);
    }
    #pragma unroll
    for (int i = 0; i < 4; i++) {
        int idx = tid + i*256;
        int r  = idx >> 3, c4 = idx & 7;
        *(__nv_bfloat162*)&As[0][r*APAD + c4*4    ] = __floats2bfloat162_rn(ra[i].x, ra[i].y);
        *(__nv_bfloat162*)&As[0][r*APAD + c4*4 + 2] = __floats2bfloat162_rn(ra[i].z, ra[i].w);
        int rr = idx >> 5, cw = idx & 31;
        *(__nv_bfloat162*)&Ws[0][rr*WPAD + cw*4    ] = __floats2bfloat162_rn(rw[i].x, rw[i].y);
        *(__nv_bfloat162*)&Ws[0][rr*WPAD + cw*4 + 2] = __floats2bfloat162_rn(rw[i].z, rw[i].w);
    }
    __syncthreads();

    for (int kt = 0; kt < KT; kt++) {
        int cur = kt & 1;
        bool has_next = (kt + 1 < KT);
        if (has_next) {
            int k0 = (kt+1) << 5;
            #pragma unroll
            for (int i = 0; i < 4; i++) {
                int idx = tid + i*256;
                int r  = idx >> 3, c4 = idx & 7;
                ra[i] = *(const float4*)(A + (size_t)(m0 + r)*K + k0 + c4*4);
                int rr = idx >> 5, cw = idx & 31;
                rw[i] = *(const float4*)(W + (size_t)(k0 + rr)*N + n0 + cw*4);
            }
        }
        // compute
        #pragma unroll
        for (int ks = 0; ks < 2; ks++) {
            uint32_t af[4][4];
            #pragma unroll
            for (int i = 0; i < 4; i++) {
                int r = wm*64 + i*16 + (lane & 15);
                int c = ks*16 + (lane >> 4)*8;
                uint32_t addr = (uint32_t)__cvta_generic_to_shared(&As[cur][r*APAD + c]);
                ldsm_x4(af[i], addr);
            }
            uint32_t bf[2][4];
            #pragma unroll
            for (int j2 = 0; j2 < 2; j2++) {
                int kk = ks*16 + ((lane>>3)&1)*8 + (lane&7);
                int nn = wn*32 + j2*16 + (lane>>4)*8;
                uint32_t addr = (uint32_t)__cvta_generic_to_shared(&Ws[cur][kk*WPAD + nn]);
                ldsm_x4_t(bf[j2], addr);
            }
            #pragma unroll
            for (int i = 0; i < 4; i++)
                #pragma unroll
                for (int j = 0; j < 4; j++)
                    mma16816(acc[i][j], af[i], bf[j>>1][(j&1)*2], bf[j>>1][(j&1)*2+1]);
        }
        if (has_next) {
            int nxt = cur ^ 1;
            #pragma unroll
            for (int i = 0; i < 4; i++) {
                int idx = tid + i*256;
                int r  = idx >> 3, c4 = idx & 7;
                *(__nv_bfloat162*)&As[nxt][r*APAD + c4*4    ] = __floats2bfloat162_rn(ra[i].x, ra[i].y);
                *(__nv_bfloat162*)&As[nxt][r*APAD + c4*4 + 2] = __floats2bfloat162_rn(ra[i].z, ra[i].w);
                int rr = idx >> 5, cw = idx & 31;
                *(__nv_bfloat162*)&Ws[nxt][rr*WPAD + cw*4    ] = __floats2bfloat162_rn(rw[i].x, rw[i].y);
                *(__nv_bfloat162*)&Ws[nxt][rr*WPAD + cw*4 + 2] = __floats2bfloat162_rn(rw[i].z, rw[i].w);
            }
        }
        __syncthreads();
    }

    // epilogue
    #pragma unroll
    for (int i = 0; i < 4; i++) {
        int mb = m0 + wm*64 + i*16 + (lane >> 2);
        #pragma unroll
        for (int j = 0; j < 4; j++) {
            int nb = n0 + wn*32 + j*8 + (lane & 3)*2;
            float b0 = bias[nb], b1 = bias[nb+1];
            #pragma unroll
            for (int half = 0; half < 2; half++) {
                int m = mb + half*8;
                float v0 = acc[i][j][half*2]   + b0;
                float v1 = acc[i][j][half*2+1] + b1;
                if (mode == 1) {
                    float x3 = v0*v0*v0;
                    v0 = 0.5f*v0*(1.0f + tanhf(0.7978845608028654f*(v0 + 0.044715f*x3)));
                    x3 = v1*v1*v1;
                    v1 = 0.5f*v1*(1.0f + tanhf(0.7978845608028654f*(v1 + 0.044715f*x3)));
                } else if (mode == 2) {
                    float2 r2 = *(const float2*)(res + (size_t)m*N + nb);
                    v0 += r2.x; v1 += r2.y;
                }
                float2 o; o.x = v0; o.y = v1;
                *(float2*)(C + (size_t)m*N + nb) = o;
            }
        }
    }
}

__global__ __launch_bounds__(256) void mma_gemm_kernel(
    const float* __restrict__ A, const float* __restrict__ W,
    const float* __restrict__ bias, const float* __restrict__ res,
    float* __restrict__ C, int N, int K, int mode)
{
    gemm_core(A, W, bias, res, C, N, K, mode, blockIdx.y*128, blockIdx.x*128);
}

// fused QKV: blockIdx.z selects which projection
__global__ __launch_bounds__(256) void mma_qkv_kernel(
    const float* __restrict__ A,
    const float* __restrict__ Wq, const float* __restrict__ Wk, const float* __restrict__ Wv,
    const float* __restrict__ bq, const float* __restrict__ bk, const float* __restrict__ bv,
    float* __restrict__ q, float* __restrict__ k, float* __restrict__ v)
{
    int z = blockIdx.z;
    const float* W  = (z == 0) ? Wq : (z == 1) ? Wk : Wv;
    const float* bb = (z == 0) ? bq : (z == 1) ? bk : bv;
    float* C        = (z == 0) ? q  : (z == 1) ? k  : v;
    gemm_core(A, W, bb, nullptr, C, Hsz, Hsz, 0, blockIdx.y*128, blockIdx.x*128);
}

// ---------------- small SIMT gemm for classifier (N=19) ----------------
#define BM 64
#define BN 64
#define BK 16
__global__ void sgemm_kernel(const float* __restrict__ A, const float* __restrict__ W,
                             const float* __restrict__ bias, float* __restrict__ C,
                             int M, int N, int K)
{
    __shared__ float As[BM][BK+1];
    __shared__ float Ws[BK][BN];
    int m0 = blockIdx.y * BM;
    int n0 = blockIdx.x * BN;
    int tid = threadIdx.x;
    int ty = tid >> 4, tx = tid & 15;
    float acc[4][4] = {};
    for (int k0 = 0; k0 < K; k0 += BK) {
        #pragma unroll
        for (int i = 0; i < 4; i++) {
            int idx = tid + i*256;
            int r = idx >> 4, c = idx & 15;
            As[r][c] = A[(size_t)(m0+r)*K + (k0+c)];
        }
        #pragma unroll
        for (int i = 0; i < 4; i++) {
            int idx = tid + i*256;
            int r = idx >> 6, c = idx & 63;
            int n = n0 + c;
            Ws[r][c] = (n < N) ? W[(size_t)(k0+r)*N + n] : 0.f;
        }
        __syncthreads();
        #pragma unroll
        for (int kk = 0; kk < BK; kk++) {
            float a[4], b[4];
            #pragma unroll
            for (int i = 0; i < 4; i++) a[i] = As[ty*4+i][kk];
            #pragma unroll
            for (int j = 0; j < 4; j++) b[j] = Ws[kk][tx*4+j];
            #pragma unroll
            for (int i = 0; i < 4; i++)
                #pragma unroll
                for (int j = 0; j < 4; j++)
                    acc[i][j] = fmaf(a[i], b[j], acc[i][j]);
        }
        __syncthreads();
    }
    #pragma unroll
    for (int i = 0; i < 4; i++) {
        int m = m0 + ty*4 + i;
        #pragma unroll
        for (int j = 0; j < 4; j++) {
            int n = n0 + tx*4 + j;
            if (n < N) C[(size_t)m*N + n] = acc[i][j] + bias[n];
        }
    }
}

// ---------------- attention scores ----------------
__global__ void attn_scores_kernel(const float* __restrict__ q, const float* __restrict__ k,
                                   const int* __restrict__ mask, float* __restrict__ sc)
{
    int bh = blockIdx.z;
    int b = bh / NHsz, h = bh % NHsz;
    int i0 = blockIdx.y * 64, j0 = blockIdx.x * 64;
    __shared__ float Qs[64][65], Ks[64][65];
    int tid = threadIdx.x;
    #pragma unroll
    for (int it = 0; it < 16; it++) {
        int idx = tid + it*256;
        int r = idx >> 6, c = idx & 63;
        Qs[r][c] = q[(size_t)(b*Ssz + i0 + r)*Hsz + h*DHsz + c];
        Ks[r][c] = k[(size_t)(b*Ssz + j0 + r)*Hsz + h*DHsz + c];
    }
    __syncthreads();
    int ty = tid >> 4, tx = tid & 15;
    float acc[4][4] = {};
    #pragma unroll
    for (int d = 0; d < 64; d++) {
        float a[4], bb[4];
        #pragma unroll
        for (int i = 0; i < 4; i++) a[i] = Qs[ty*4+i][d];
        #pragma unroll
        for (int j = 0; j < 4; j++) bb[j] = Ks[tx*4+j][d];
        #pragma unroll
        for (int i = 0; i < 4; i++)
            #pragma unroll
            for (int j = 0; j < 4; j++)
                acc[i][j] = fmaf(a[i], bb[j], acc[i][j]);
    }
    #pragma unroll
    for (int j = 0; j < 4; j++) {
        int jj = j0 + tx*4 + j;
        float bj = mask[b*Ssz + jj] ? 0.f : -1e9f;
        #pragma unroll
        for (int i = 0; i < 4; i++) {
            int ii = i0 + ty*4 + i;
            sc[((size_t)bh*Ssz + ii)*Ssz + jj] = acc[i][j]*0.125f + bj;
        }
    }
}

// ---------------- softmax ----------------
__global__ void softmax_kernel(float* __restrict__ sc)
{
    __shared__ float sh[32];
    size_t row = blockIdx.x;
    float* p = sc + row*Ssz;
    int tid = threadIdx.x;
    float a = p[tid], b = p[tid+256];
    float m = fmaxf(a, b);
    int lane = tid & 31, w = tid >> 5;
    for (int o = 16; o; o >>= 1) m = fmaxf(m, __shfl_xor_sync(0xffffffffu, m, o));
    if (!lane) sh[w] = m;
    __syncthreads();
    if (w == 0) {
        m = (lane < 8) ? sh[lane] : -1e30f;
        for (int o = 4; o; o >>= 1) m = fmaxf(m, __shfl_xor_sync(0xffffffffu, m, o));
        if (!lane) sh[0] = m;
    }
    __syncthreads();
    m = sh[0];
    __syncthreads();
    float e1 = __expf(a - m), e2 = __expf(b - m);
    float s = e1 + e2;
    for (int o = 16; o; o >>= 1) s += __shfl_xor_sync(0xffffffffu, s, o);
    if (!lane) sh[w] = s;
    __syncthreads();
    if (w == 0) {
        s = (lane < 8) ? sh[lane] : 0.f;
        for (int o = 4; o; o >>= 1) s += __shfl_xor_sync(0xffffffffu, s, o);
        if (!lane) sh[0] = s;
    }
    __syncthreads();
    float inv = 1.0f / sh[0];
    p[tid]     = e1 * inv;
    p[tid+256] = e2 * inv;
}

// ---------------- AV ----------------
__global__ void attn_av_kernel(const float* __restrict__ sc, const float* __restrict__ v,
                               float* __restrict__ ctx)
{
    int bh = blockIdx.y;
    int b = bh / NHsz, h = bh % NHsz;
    int i0 = blockIdx.x * 64;
    __shared__ float As[64][65], Vs[64][65];
    int tid = threadIdx.x;
    int ty = tid >> 4, tx = tid & 15;
    float acc[4][4] = {};
    for (int j0 = 0; j0 < Ssz; j0 += 64) {
        #pragma unroll
        for (int it = 0; it < 16; it++) {
            int idx = tid + it*256;
            int r = idx >> 6, c = idx & 63;
            As[r][c] = sc[((size_t)bh*Ssz + i0 + r)*Ssz + j0 + c];
            Vs[r][c] = v[(size_t)(b*Ssz + j0 + r)*Hsz + h*DHsz + c];
        }
        __syncthreads();
        #pragma unroll
        for (int kk = 0; kk < 64; kk++) {
            float a[4], bb[4];
            #pragma unroll
            for (int i = 0; i < 4; i++) a[i] = As[ty*4+i][kk];
            #pragma unroll
            for (int j = 0; j < 4; j++) bb[j] = Vs[kk][tx*4+j];
            #pragma unroll
            for (int i = 0; i < 4; i++)
                #pragma unroll
                for (int j = 0; j < 4; j++)
                    acc[i][j] = fmaf(a[i], bb[j], acc[i][j]);
        }
        __syncthreads();
    }
    #pragma unroll
    for (int i = 0; i < 4; i++)
        #pragma unroll
        for (int j = 0; j < 4; j++)
            ctx[(size_t)(b*Ssz + i0 + ty*4 + i)*Hsz + h*DHsz + tx*4 + j] = acc[i][j];
}

// ---------------- CRF ----------------
__global__ void crf_kernel(const float* __restrict__ lg, const int* __restrict__ labels,
                           const int* __restrict__ mask, const float* __restrict__ st,
                           const float* __restrict__ en, const float* __restrict__ tr,
                           float* __restrict__ out)
{
    __shared__ float s_tr[NLsz*NLsz];
    __shared__ float s_res[Bsz];
    for (int i = threadIdx.x; i < NLsz*NLsz; i += blockDim.x) s_tr[i] = tr[i];
    __syncthreads();
    int warp = threadIdx.x >> 5, lane = threadIdx.x & 31;
    if (warp < Bsz) {
        int b = warp;
        const int* lab = labels + b*Ssz;
        const int* mk  = mask + b*Ssz;
        const float* lgb = lg + (size_t)b*Ssz*NLsz;
        float part = 0.f; int cnt = 0;
        for (int t = lane; t < Ssz; t += 32) {
            cnt += mk[t];
            if (t >= 1) {
                float mf = (float)mk[t];
                part += (s_tr[lab[t-1]*NLsz + lab[t]] + lgb[t*NLsz + lab[t]]) * mf;
            }
        }
        for (int o = 16; o; o >>= 1) {
            part += __shfl_xor_sync(0xffffffffu, part, o);
            cnt  += __shfl_xor_sync(0xffffffffu, cnt, o);
        }
        float num = 0.f;
        if (lane == 0) {
            int l0 = lab[0];
            num = st[l0] + lgb[l0] + part + en[lab[cnt-1]];
        }
        int j = lane;
        float alpha = (j < NLsz) ? st[j] + lgb[j] : -1e30f;
        for (int t = 1; t < Ssz; t++) {
            float g[NLsz];
            #pragma unroll
            for (int i = 0; i < NLsz; i++)
                g[i] = __shfl_sync(0xffffffffu, alpha, i) + ((j < NLsz) ? s_tr[i*NLsz + j] : 0.f);
            float mv = g[0];
            #pragma unroll
            for (int i = 1; i < NLsz; i++) mv = fmaxf(mv, g[i]);
            float sum = 0.f;
            #pragma unroll
            for (int i = 0; i < NLsz; i++) sum += expf(g[i] - mv);
            float nxt = mv + logf(sum) + ((j < NLsz) ? lgb[t*NLsz + j] : 0.f);
            if (mk[t] > 0 && j < NLsz) alpha = nxt;
        }
        float v = (j < NLsz) ? alpha + en[j] : -1e30f;
        float mv = v;
        for (int o = 16; o; o >>= 1) mv = fmaxf(mv, __shfl_xor_sync(0xffffffffu, mv, o));
        float s = (j < NLsz) ? expf(v - mv) : 0.f;
        for (int o = 16; o; o >>= 1) s += __shfl_xor_sync(0xffffffffu, s, o);
        if (lane == 0) s_res[b] = (mv + logf(s)) - num;
    }
    __syncthreads();
    if (threadIdx.x == 0) {
        float tot = 0.f;
        for (int b = 0; b < Bsz; b++) tot += s_res[b];
        out[0] = tot;
    }
}

// ---------------- host ----------------
extern "C" void kernel_launch(void* const* d_in, const int* in_sizes, int n_in,
                              void* d_out, int out_size)
{
    const int*   input_ids = (const int*)  d_in[0];
    const int*   attn_mask = (const int*)  d_in[1];
    const int*   labels    = (const int*)  d_in[2];
    const float* token_emb = (const float*)d_in[3];
    const float* pos_emb   = (const float*)d_in[4];
    const float* ln_emb_s  = (const float*)d_in[5];
    const float* ln_emb_b  = (const float*)d_in[6];
    const float* Wq        = (const float*)d_in[7];
    const float* bq        = (const float*)d_in[8];
    const float* Wk        = (const float*)d_in[9];
    const float* bk        = (const float*)d_in[10];
    const float* Wv        = (const float*)d_in[11];
    const float* bv        = (const float*)d_in[12];
    const float* Wo        = (const float*)d_in[13];
    const float* bo        = (const float*)d_in[14];
    const float* ln1_s     = (const float*)d_in[15];
    const float* ln1_b     = (const float*)d_in[16];
    const float* W1        = (const float*)d_in[17];
    const float* b1        = (const float*)d_in[18];
    const float* W2        = (const float*)d_in[19];
    const float* b2        = (const float*)d_in[20];
    const float* ln2_s     = (const float*)d_in[21];
    const float* ln2_b     = (const float*)d_in[22];
    const float* cls_W     = (const float*)d_in[23];
    const float* cls_b     = (const float*)d_in[24];
    const float* start_tr  = (const float*)d_in[25];
    const float* end_tr    = (const float*)d_in[26];
    const float* trans     = (const float*)d_in[27];

    float *x, *t, *q, *k, *v, *c, *sc, *h, *lg;
    { void* p; cudaGetSymbolAddress(&p, g_x);  x  = (float*)p; }
    { void* p; cudaGetSymbolAddress(&p, g_t);  t  = (float*)p; }
    { void* p; cudaGetSymbolAddress(&p, g_q);  q  = (float*)p; }
    { void* p; cudaGetSymbolAddress(&p, g_k);  k  = (float*)p; }
    { void* p; cudaGetSymbolAddress(&p, g_v);  v  = (float*)p; }
    { void* p; cudaGetSymbolAddress(&p, g_c);  c  = (float*)p; }
    { void* p; cudaGetSymbolAddress(&p, g_sc); sc = (float*)p; }
    { void* p; cudaGetSymbolAddress(&p, g_h);  h  = (float*)p; }
    { void* p; cudaGetSymbolAddress(&p, g_lg); lg = (float*)p; }

    embed_kernel<<<Tsz, 256>>>(input_ids, token_emb, pos_emb, t);
    ln_kernel<<<Tsz, 256>>>(t, ln_emb_s, ln_emb_b, x);

    for (int l = 0; l < Lsz; l++) {
        const float* wq = Wq + (size_t)l*Hsz*Hsz;
        const float* wk = Wk + (size_t)l*Hsz*Hsz;
        const float* wv = Wv + (size_t)l*Hsz*Hsz;
        const float* wo = Wo + (size_t)l*Hsz*Hsz;

        mma_qkv_kernel<<<dim3(Hsz/128, Tsz/128, 3), 256>>>(
            x, wq, wk, wv, bq + l*Hsz, bk + l*Hsz, bv + l*Hsz, q, k, v);

        attn_scores_kernel<<<dim3(Ssz/64, Ssz/64, Bsz*NHsz), 256>>>(q, k, attn_mask, sc);
        softmax_kernel<<<Bsz*NHsz*Ssz, 256>>>(sc);
        attn_av_kernel<<<dim3(Ssz/64, Bsz*NHsz), 256>>>(sc, v, c);

        mma_gemm_kernel<<<dim3(Hsz/128, Tsz/128), 256>>>(c, wo, bo + l*Hsz, x, t, Hsz, Hsz, 2);
        ln_kernel<<<Tsz, 256>>>(t, ln1_s + l*Hsz, ln1_b + l*Hsz, x);

        mma_gemm_kernel<<<dim3(DFFsz/128, Tsz/128), 256>>>(
            x, W1 + (size_t)l*Hsz*DFFsz, b1 + l*DFFsz, nullptr, h, DFFsz, Hsz, 1);
        mma_gemm_kernel<<<dim3(Hsz/128, Tsz/128), 256>>>(
            h, W2 + (size_t)l*DFFsz*Hsz, b2 + l*Hsz, x, t, Hsz, DFFsz, 2);
        ln_kernel<<<Tsz, 256>>>(t, ln2_s + l*Hsz, ln2_b + l*Hsz, x);
    }

    sgemm_kernel<<<dim3(1, Tsz/64), 256>>>(x, cls_W, cls_b, lg, Tsz, NLsz, Hsz);
    crf_kernel<<<1, 256>>>(lg, labels, attn_mask, start_tr, end_tr, trans, (float*)d_out);
}

// round 7
// speedup vs baseline: 5.8859x; 1.7655x over previous
#include <cuda_runtime.h>
#include <cuda_bf16.h>
#include <math.h>
#include <stdint.h>

#define Bsz  8
#define Ssz  512
#define Hsz  768
#define Lsz  12
#define NHsz 12
#define DHsz 64
#define DFFsz 3072
#define NLsz 19
#define Tsz  (Bsz*Ssz)   // 4096 tokens

// ---------------- scratch ----------------
__device__ float          g_x [Tsz*Hsz];
__device__ float          g_t [Tsz*Hsz];
__device__ __nv_bfloat16  g_qb[Tsz*Hsz];
__device__ __nv_bfloat16  g_kb[Tsz*Hsz];
__device__ __nv_bfloat16  g_vb[Tsz*Hsz];
__device__ __nv_bfloat16  g_cb[Tsz*Hsz];
__device__ __nv_bfloat16  g_hb[Tsz*DFFsz];
__device__ float          g_lg[Tsz*NLsz];

// ---------------- embedding ----------------
__global__ void embed_kernel(const int* __restrict__ ids,
                             const float* __restrict__ tok,
                             const float* __restrict__ pos,
                             float* __restrict__ out)
{
    int t = blockIdx.x;
    int s = t & (Ssz-1);
    int id = ids[t];
    const float* tp = tok + (size_t)id*Hsz;
    const float* pp = pos + (size_t)s*Hsz;
    float* op = out + (size_t)t*Hsz;
    for (int c = threadIdx.x; c < Hsz; c += blockDim.x)
        op[c] = tp[c] + pp[c];
}

// ---------------- layernorm ----------------
__global__ void ln_kernel(const float* __restrict__ in,
                          const float* __restrict__ gamma,
                          const float* __restrict__ beta,
                          float* __restrict__ out)
{
    __shared__ float sh[32];
    int row = blockIdx.x;
    int tid = threadIdx.x;
    const float* p = in + (size_t)row*Hsz;
    float v0 = p[tid], v1 = p[tid+256], v2 = p[tid+512];
    float s = v0+v1+v2;
    int lane = tid & 31, w = tid >> 5;
    for (int o = 16; o; o >>= 1) s += __shfl_xor_sync(0xffffffffu, s, o);
    if (!lane) sh[w] = s;
    __syncthreads();
    if (w == 0) {
        s = (lane < 8) ? sh[lane] : 0.f;
        for (int o = 4; o; o >>= 1) s += __shfl_xor_sync(0xffffffffu, s, o);
        if (!lane) sh[0] = s;
    }
    __syncthreads();
    float mean = sh[0] * (1.0f/Hsz);
    __syncthreads();
    float d0 = v0-mean, d1 = v1-mean, d2 = v2-mean;
    float q = d0*d0 + d1*d1 + d2*d2;
    for (int o = 16; o; o >>= 1) q += __shfl_xor_sync(0xffffffffu, q, o);
    if (!lane) sh[w] = q;
    __syncthreads();
    if (w == 0) {
        q = (lane < 8) ? sh[lane] : 0.f;
        for (int o = 4; o; o >>= 1) q += __shfl_xor_sync(0xffffffffu, q, o);
        if (!lane) sh[0] = q;
    }
    __syncthreads();
    float var = sh[0] * (1.0f/Hsz);
    float inv = rsqrtf(var + 1e-12f);
    float* op = out + (size_t)row*Hsz;
    op[tid    ] = d0*inv*gamma[tid    ] + beta[tid    ];
    op[tid+256] = d1*inv*gamma[tid+256] + beta[tid+256];
    op[tid+512] = d2*inv*gamma[tid+512] + beta[tid+512];
}

// ================= MMA primitives =================
__device__ __forceinline__ void ldsm_x4(uint32_t (&r)[4], uint32_t addr) {
    asm volatile("ldmatrix.sync.aligned.m8n8.x4.shared.b16 {%0,%1,%2,%3}, [%4];"
        : "=r"(r[0]),"=r"(r[1]),"=r"(r[2]),"=r"(r[3]) : "r"(addr));
}
__device__ __forceinline__ void ldsm_x4_t(uint32_t (&r)[4], uint32_t addr) {
    asm volatile("ldmatrix.sync.aligned.m8n8.x4.trans.shared.b16 {%0,%1,%2,%3}, [%4];"
        : "=r"(r[0]),"=r"(r[1]),"=r"(r[2]),"=r"(r[3]) : "r"(addr));
}
__device__ __forceinline__ void mma16816(float (&c)[4], const uint32_t (&a)[4],
                                         uint32_t b0, uint32_t b1) {
    asm volatile("mma.sync.aligned.m16n8k16.row.col.f32.bf16.bf16.f32 "
        "{%0,%1,%2,%3}, {%4,%5,%6,%7}, {%8,%9}, {%0,%1,%2,%3};"
        : "+f"(c[0]),"+f"(c[1]),"+f"(c[2]),"+f"(c[3])
        : "r"(a[0]),"r"(a[1]),"r"(a[2]),"r"(a[3]), "r"(b0),"r"(b1));
}
__device__ __forceinline__ uint32_t pack_bf16(float x, float y) {
    __nv_bfloat162 h = __floats2bfloat162_rn(x, y);
    return *(uint32_t*)&h;
}

// ================= GEMM: C = A[M,K] @ W[K,N] + bias (+epilogue) =================
// Block 128x128x32, 256 threads (8 warps, 64x32 warp tiles)
// MODE: 0 = bias -> fp32, 1 = bias+gelu -> bf16, 2 = bias+residual -> fp32, 3 = bias -> bf16
#define APAD 40
#define WPAD 136

template<typename AT, int MODE>
__device__ __forceinline__ void gemm_core(
    const AT* __restrict__ A, const float* __restrict__ W,
    const float* __restrict__ bias, const float* __restrict__ res,
    void* __restrict__ Cout, int N, int K, int m0, int n0)
{
    __shared__ __nv_bfloat16 As[2][128*APAD];
    __shared__ __nv_bfloat16 Ws[2][32*WPAD];
    int tid = threadIdx.x;
    int warp = tid >> 5, lane = tid & 31;
    int wm = warp >> 2;
    int wn = warp & 3;

    float acc[4][4][4];
    #pragma unroll
    for (int i = 0; i < 4; i++)
        #pragma unroll
        for (int j = 0; j < 4; j++)
            #pragma unroll
            for (int e = 0; e < 4; e++) acc[i][j][e] = 0.f;

    float4 ra[4], rw[4];
    uint4  rab[2];
    const int KT = K >> 5;

    // ---- prologue loads (tile 0) ----
    if (sizeof(AT) == 4) {
        #pragma unroll
        for (int i = 0; i < 4; i++) {
            int idx = tid + i*256;
            int r = idx >> 3, c4 = idx & 7;
            ra[i] = *(const float4*)((const float*)A + (size_t)(m0 + r)*K + c4*4);
        }
    } else {
        #pragma unroll
        for (int i = 0; i < 2; i++) {
            int idx = tid + i*256;
            int r = idx >> 2, c8 = idx & 3;
            rab[i] = *(const uint4*)((const __nv_bfloat16*)A + (size_t)(m0 + r)*K + c8*8);
        }
    }
    #pragma unroll
    for (int i = 0; i < 4; i++) {
        int idx = tid + i*256;
        int rr = idx >> 5, cw = idx & 31;
        rw[i] = *(const float4*)(W + (size_t)rr*N + n0 + cw*4);
    }
    if (sizeof(AT) == 4) {
        #pragma unroll
        for (int i = 0; i < 4; i++) {
            int idx = tid + i*256;
            int r = idx >> 3, c4 = idx & 7;
            *(__nv_bfloat162*)&As[0][r*APAD + c4*4    ] = __floats2bfloat162_rn(ra[i].x, ra[i].y);
            *(__nv_bfloat162*)&As[0][r*APAD + c4*4 + 2] = __floats2bfloat162_rn(ra[i].z, ra[i].w);
        }
    } else {
        #pragma unroll
        for (int i = 0; i < 2; i++) {
            int idx = tid + i*256;
            int r = idx >> 2, c8 = idx & 3;
            *(uint4*)&As[0][r*APAD + c8*8] = rab[i];
        }
    }
    #pragma unroll
    for (int i = 0; i < 4; i++) {
        int idx = tid + i*256;
        int rr = idx >> 5, cw = idx & 31;
        *(__nv_bfloat162*)&Ws[0][rr*WPAD + cw*4    ] = __floats2bfloat162_rn(rw[i].x, rw[i].y);
        *(__nv_bfloat162*)&Ws[0][rr*WPAD + cw*4 + 2] = __floats2bfloat162_rn(rw[i].z, rw[i].w);
    }
    __syncthreads();

    for (int kt = 0; kt < KT; kt++) {
        int cur = kt & 1;
        bool has_next = (kt + 1 < KT);
        if (has_next) {
            int k0 = (kt+1) << 5;
            if (sizeof(AT) == 4) {
                #pragma unroll
                for (int i = 0; i < 4; i++) {
                    int idx = tid + i*256;
                    int r = idx >> 3, c4 = idx & 7;
                    ra[i] = *(const float4*)((const float*)A + (size_t)(m0 + r)*K + k0 + c4*4);
                }
            } else {
                #pragma unroll
                for (int i = 0; i < 2; i++) {
                    int idx = tid + i*256;
                    int r = idx >> 2, c8 = idx & 3;
                    rab[i] = *(const uint4*)((const __nv_bfloat16*)A + (size_t)(m0 + r)*K + k0 + c8*8);
                }
            }
            #pragma unroll
            for (int i = 0; i < 4; i++) {
                int idx = tid + i*256;
                int rr = idx >> 5, cw = idx & 31;
                rw[i] = *(const float4*)(W + (size_t)(k0 + rr)*N + n0 + cw*4);
            }
        }
        #pragma unroll
        for (int ks = 0; ks < 2; ks++) {
            uint32_t af[4][4];
            #pragma unroll
            for (int i = 0; i < 4; i++) {
                int r = wm*64 + i*16 + (lane & 15);
                int c = ks*16 + (lane >> 4)*8;
                uint32_t addr = (uint32_t)__cvta_generic_to_shared(&As[cur][r*APAD + c]);
                ldsm_x4(af[i], addr);
            }
            uint32_t bf[2][4];
            #pragma unroll
            for (int j2 = 0; j2 < 2; j2++) {
                int kk = ks*16 + ((lane>>3)&1)*8 + (lane&7);
                int nn = wn*32 + j2*16 + (lane>>4)*8;
                uint32_t addr = (uint32_t)__cvta_generic_to_shared(&Ws[cur][kk*WPAD + nn]);
                ldsm_x4_t(bf[j2], addr);
            }
            #pragma unroll
            for (int i = 0; i < 4; i++)
                #pragma unroll
                for (int j = 0; j < 4; j++)
                    mma16816(acc[i][j], af[i], bf[j>>1][(j&1)*2], bf[j>>1][(j&1)*2+1]);
        }
        if (has_next) {
            int nxt = cur ^ 1;
            if (sizeof(AT) == 4) {
                #pragma unroll
                for (int i = 0; i < 4; i++) {
                    int idx = tid + i*256;
                    int r = idx >> 3, c4 = idx & 7;
                    *(__nv_bfloat162*)&As[nxt][r*APAD + c4*4    ] = __floats2bfloat162_rn(ra[i].x, ra[i].y);
                    *(__nv_bfloat162*)&As[nxt][r*APAD + c4*4 + 2] = __floats2bfloat162_rn(ra[i].z, ra[i].w);
                }
            } else {
                #pragma unroll
                for (int i = 0; i < 2; i++) {
                    int idx = tid + i*256;
                    int r = idx >> 2, c8 = idx & 3;
                    *(uint4*)&As[nxt][r*APAD + c8*8] = rab[i];
                }
            }
            #pragma unroll
            for (int i = 0; i < 4; i++) {
                int idx = tid + i*256;
                int rr = idx >> 5, cw = idx & 31;
                *(__nv_bfloat162*)&Ws[nxt][rr*WPAD + cw*4    ] = __floats2bfloat162_rn(rw[i].x, rw[i].y);
                *(__nv_bfloat162*)&Ws[nxt][rr*WPAD + cw*4 + 2] = __floats2bfloat162_rn(rw[i].z, rw[i].w);
            }
        }
        __syncthreads();
    }

    // ---- epilogue ----
    #pragma unroll
    for (int i = 0; i < 4; i++) {
        int mb = m0 + wm*64 + i*16 + (lane >> 2);
        #pragma unroll
        for (int j = 0; j < 4; j++) {
            int nb = n0 + wn*32 + j*8 + (lane & 3)*2;
            float b0 = bias[nb], b1 = bias[nb+1];
            #pragma unroll
            for (int half = 0; half < 2; half++) {
                int m = mb + half*8;
                float v0 = acc[i][j][half*2]   + b0;
                float v1 = acc[i][j][half*2+1] + b1;
                if (MODE == 1) {
                    float x3 = v0*v0*v0;
                    v0 = 0.5f*v0*(1.0f + tanhf(0.7978845608028654f*(v0 + 0.044715f*x3)));
                    x3 = v1*v1*v1;
                    v1 = 0.5f*v1*(1.0f + tanhf(0.7978845608028654f*(v1 + 0.044715f*x3)));
                } else if (MODE == 2) {
                    float2 r2 = *(const float2*)(res + (size_t)m*N + nb);
                    v0 += r2.x; v1 += r2.y;
                }
                if (MODE == 1 || MODE == 3) {
                    *(__nv_bfloat162*)((__nv_bfloat16*)Cout + (size_t)m*N + nb) =
                        __floats2bfloat162_rn(v0, v1);
                } else {
                    float2 o; o.x = v0; o.y = v1;
                    *(float2*)((float*)Cout + (size_t)m*N + nb) = o;
                }
            }
        }
    }
}

__global__ __launch_bounds__(256) void gemm_gelu_kernel(
    const float* __restrict__ A, const float* __restrict__ W,
    const float* __restrict__ bias, __nv_bfloat16* __restrict__ C, int N, int K)
{
    gemm_core<float,1>(A, W, bias, nullptr, C, N, K, blockIdx.y*128, blockIdx.x*128);
}
__global__ __launch_bounds__(256) void gemm_res_f32A_kernel(
    const float* __restrict__ A, const float* __restrict__ W,
    const float* __restrict__ bias, const float* __restrict__ res,
    float* __restrict__ C, int N, int K)
{
    gemm_core<float,2>(A, W, bias, res, C, N, K, blockIdx.y*128, blockIdx.x*128);
}
__global__ __launch_bounds__(256) void gemm_res_bf16A_kernel(
    const __nv_bfloat16* __restrict__ A, const float* __restrict__ W,
    const float* __restrict__ bias, const float* __restrict__ res,
    float* __restrict__ C, int N, int K)
{
    gemm_core<__nv_bfloat16,2>(A, W, bias, res, C, N, K, blockIdx.y*128, blockIdx.x*128);
}
__global__ __launch_bounds__(256) void mma_qkv_kernel(
    const float* __restrict__ A,
    const float* __restrict__ Wq, const float* __restrict__ Wk, const float* __restrict__ Wv,
    const float* __restrict__ bq, const float* __restrict__ bk, const float* __restrict__ bv,
    __nv_bfloat16* __restrict__ q, __nv_bfloat16* __restrict__ k, __nv_bfloat16* __restrict__ v)
{
    int z = blockIdx.z;
    const float* W  = (z == 0) ? Wq : (z == 1) ? Wk : Wv;
    const float* bb = (z == 0) ? bq : (z == 1) ? bk : bv;
    __nv_bfloat16* C = (z == 0) ? q : (z == 1) ? k : v;
    gemm_core<float,3>(A, W, bb, nullptr, C, Hsz, Hsz, blockIdx.y*128, blockIdx.x*128);
}

// ================= flash attention =================
// grid (Ssz/64, B*NH), 128 threads (4 warps). Each warp owns 16 Q rows.
#define FPAD 72   // 64 + 8 bf16 pad

__global__ __launch_bounds__(128) void flash_attn_kernel(
    const __nv_bfloat16* __restrict__ q, const __nv_bfloat16* __restrict__ k,
    const __nv_bfloat16* __restrict__ v, const int* __restrict__ mask,
    __nv_bfloat16* __restrict__ ctx)
{
    __shared__ __nv_bfloat16 Qs[64*FPAD];
    __shared__ __nv_bfloat16 Ks[64*FPAD];
    __shared__ __nv_bfloat16 Vs[64*FPAD];
    __shared__ float s_bias[Ssz];

    int bh = blockIdx.y;
    int b = bh / NHsz, h = bh % NHsz;
    int i0 = blockIdx.x * 64;
    int tid = threadIdx.x;
    int warp = tid >> 5, lane = tid & 31;
    int g = lane >> 2, t4 = lane & 3;

    // bias from mask
    #pragma unroll
    for (int it = 0; it < 4; it++) {
        int j = tid + it*128;
        s_bias[j] = mask[b*Ssz + j] ? 0.f : -1e9f;
    }
    // load Q tile
    #pragma unroll
    for (int it = 0; it < 4; it++) {
        int idx = tid + it*128;
        int r = idx >> 3, c8 = idx & 7;
        *(uint4*)&Qs[r*FPAD + c8*8] =
            *(const uint4*)(q + (size_t)(b*Ssz + i0 + r)*Hsz + h*DHsz + c8*8);
    }
    __syncthreads();

    // Q fragments (held in registers for the whole loop)
    uint32_t qf[4][4];
    #pragma unroll
    for (int ks = 0; ks < 4; ks++) {
        int r = warp*16 + (lane & 15);
        int c = ks*16 + (lane >> 4)*8;
        ldsm_x4(qf[ks], (uint32_t)__cvta_generic_to_shared(&Qs[r*FPAD + c]));
    }

    float oacc[8][4];
    #pragma unroll
    for (int n = 0; n < 8; n++)
        #pragma unroll
        for (int e = 0; e < 4; e++) oacc[n][e] = 0.f;
    float m0v = -1e30f, m1v = -1e30f, l0 = 0.f, l1 = 0.f;

    for (int j0 = 0; j0 < Ssz; j0 += 64) {
        __syncthreads();
        // load K, V tiles
        #pragma unroll
        for (int it = 0; it < 4; it++) {
            int idx = tid + it*128;
            int r = idx >> 3, c8 = idx & 7;
            size_t goff = (size_t)(b*Ssz + j0 + r)*Hsz + h*DHsz + c8*8;
            *(uint4*)&Ks[r*FPAD + c8*8] = *(const uint4*)(k + goff);
            *(uint4*)&Vs[r*FPAD + c8*8] = *(const uint4*)(v + goff);
        }
        __syncthreads();

        // S = Q @ K^T  (16x64 per warp)
        float acc[8][4];
        #pragma unroll
        for (int n = 0; n < 8; n++)
            #pragma unroll
            for (int e = 0; e < 4; e++) acc[n][e] = 0.f;
        #pragma unroll
        for (int jj = 0; jj < 4; jj++) {
            #pragma unroll
            for (int ks = 0; ks < 4; ks++) {
                uint32_t bf[4];
                int r = jj*16 + (lane & 15);
                int c = ks*16 + (lane >> 4)*8;
                ldsm_x4(bf, (uint32_t)__cvta_generic_to_shared(&Ks[r*FPAD + c]));
                mma16816(acc[jj*2  ], qf[ks], bf[0], bf[2]);
                mma16816(acc[jj*2+1], qf[ks], bf[1], bf[3]);
            }
        }

        // scale + bias, online softmax
        float p[8][4];
        float mx0 = -1e30f, mx1 = -1e30f;
        #pragma unroll
        for (int n = 0; n < 8; n++) {
            float b0 = s_bias[j0 + n*8 + t4*2];
            float b1 = s_bias[j0 + n*8 + t4*2 + 1];
            p[n][0] = acc[n][0]*0.125f + b0;
            p[n][1] = acc[n][1]*0.125f + b1;
            p[n][2] = acc[n][2]*0.125f + b0;
            p[n][3] = acc[n][3]*0.125f + b1;
            mx0 = fmaxf(mx0, fmaxf(p[n][0], p[n][1]));
            mx1 = fmaxf(mx1, fmaxf(p[n][2], p[n][3]));
        }
        mx0 = fmaxf(mx0, __shfl_xor_sync(0xffffffffu, mx0, 1));
        mx0 = fmaxf(mx0, __shfl_xor_sync(0xffffffffu, mx0, 2));
        mx1 = fmaxf(mx1, __shfl_xor_sync(0xffffffffu, mx1, 1));
        mx1 = fmaxf(mx1, __shfl_xor_sync(0xffffffffu, mx1, 2));
        float mn0 = fmaxf(m0v, mx0);
        float mn1 = fmaxf(m1v, mx1);
        float lt0 = 0.f, lt1 = 0.f;
        #pragma unroll
        for (int n = 0; n < 8; n++) {
            p[n][0] = __expf(p[n][0] - mn0);
            p[n][1] = __expf(p[n][1] - mn0);
            p[n][2] = __expf(p[n][2] - mn1);
            p[n][3] = __expf(p[n][3] - mn1);
            lt0 += p[n][0] + p[n][1];
            lt1 += p[n][2] + p[n][3];
        }
        lt0 += __shfl_xor_sync(0xffffffffu, lt0, 1);
        lt0 += __shfl_xor_sync(0xffffffffu, lt0, 2);
        lt1 += __shfl_xor_sync(0xffffffffu, lt1, 1);
        lt1 += __shfl_xor_sync(0xffffffffu, lt1, 2);
        float sc0 = __expf(m0v - mn0);
        float sc1 = __expf(m1v - mn1);
        l0 = l0*sc0 + lt0;
        l1 = l1*sc1 + lt1;
        m0v = mn0; m1v = mn1;
        #pragma unroll
        for (int n = 0; n < 8; n++) {
            oacc[n][0] *= sc0; oacc[n][1] *= sc0;
            oacc[n][2] *= sc1; oacc[n][3] *= sc1;
        }

        // P fragments (A-operand of PV mma)
        uint32_t pa[4][4];
        #pragma unroll
        for (int c = 0; c < 4; c++) {
            pa[c][0] = pack_bf16(p[2*c  ][0], p[2*c  ][1]);
            pa[c][1] = pack_bf16(p[2*c  ][2], p[2*c  ][3]);
            pa[c][2] = pack_bf16(p[2*c+1][0], p[2*c+1][1]);
            pa[c][3] = pack_bf16(p[2*c+1][2], p[2*c+1][3]);
        }

        // O += P @ V
        #pragma unroll
        for (int db = 0; db < 4; db++) {
            #pragma unroll
            for (int c = 0; c < 4; c++) {
                uint32_t vf[4];
                int kk = c*16 + ((lane>>3)&1)*8 + (lane&7);
                int nn = db*16 + (lane>>4)*8;
                ldsm_x4_t(vf, (uint32_t)__cvta_generic_to_shared(&Vs[kk*FPAD + nn]));
                mma16816(oacc[db*2  ], pa[c], vf[0], vf[1]);
                mma16816(oacc[db*2+1], pa[c], vf[2], vf[3]);
            }
        }
    }

    // write ctx (bf16), normalized
    float inv0 = 1.0f / l0, inv1 = 1.0f / l1;
    #pragma unroll
    for (int n = 0; n < 8; n++) {
        int d = n*8 + t4*2;
        int r0 = i0 + warp*16 + g;
        *(__nv_bfloat162*)(ctx + (size_t)(b*Ssz + r0)*Hsz + h*DHsz + d) =
            __floats2bfloat162_rn(oacc[n][0]*inv0, oacc[n][1]*inv0);
        *(__nv_bfloat162*)(ctx + (size_t)(b*Ssz + r0 + 8)*Hsz + h*DHsz + d) =
            __floats2bfloat162_rn(oacc[n][2]*inv1, oacc[n][3]*inv1);
    }
}

// ---------------- classifier (N=19, SIMT) ----------------
__global__ void sgemm_kernel(const float* __restrict__ A, const float* __restrict__ W,
                             const float* __restrict__ bias, float* __restrict__ C,
                             int M, int N, int K)
{
    __shared__ float As[64][17];
    __shared__ float Ws[16][64];
    int m0 = blockIdx.y * 64;
    int n0 = blockIdx.x * 64;
    int tid = threadIdx.x;
    int ty = tid >> 4, tx = tid & 15;
    float acc[4][4] = {};
    for (int k0 = 0; k0 < K; k0 += 16) {
        #pragma unroll
        for (int i = 0; i < 4; i++) {
            int idx = tid + i*256;
            int r = idx >> 4, c = idx & 15;
            As[r][c] = A[(size_t)(m0+r)*K + (k0+c)];
        }
        #pragma unroll
        for (int i = 0; i < 4; i++) {
            int idx = tid + i*256;
            int r = idx >> 6, c = idx & 63;
            int n = n0 + c;
            Ws[r][c] = (n < N) ? W[(size_t)(k0+r)*N + n] : 0.f;
        }
        __syncthreads();
        #pragma unroll
        for (int kk = 0; kk < 16; kk++) {
            float a[4], b[4];
            #pragma unroll
            for (int i = 0; i < 4; i++) a[i] = As[ty*4+i][kk];
            #pragma unroll
            for (int j = 0; j < 4; j++) b[j] = Ws[kk][tx*4+j];
            #pragma unroll
            for (int i = 0; i < 4; i++)
                #pragma unroll
                for (int j = 0; j < 4; j++)
                    acc[i][j] = fmaf(a[i], b[j], acc[i][j]);
        }
        __syncthreads();
    }
    #pragma unroll
    for (int i = 0; i < 4; i++) {
        int m = m0 + ty*4 + i;
        #pragma unroll
        for (int j = 0; j < 4; j++) {
            int n = n0 + tx*4 + j;
            if (n < N) C[(size_t)m*N + n] = acc[i][j] + bias[n];
        }
    }
}

// ---------------- CRF ----------------
__global__ void crf_kernel(const float* __restrict__ lg, const int* __restrict__ labels,
                           const int* __restrict__ mask, const float* __restrict__ st,
                           const float* __restrict__ en, const float* __restrict__ tr,
                           float* __restrict__ out)
{
    __shared__ float s_tr[NLsz*NLsz];
    __shared__ float s_res[Bsz];
    for (int i = threadIdx.x; i < NLsz*NLsz; i += blockDim.x) s_tr[i] = tr[i];
    __syncthreads();
    int warp = threadIdx.x >> 5, lane = threadIdx.x & 31;
    if (warp < Bsz) {
        int b = warp;
        const int* lab = labels + b*Ssz;
        const int* mk  = mask + b*Ssz;
        const float* lgb = lg + (size_t)b*Ssz*NLsz;
        float part = 0.f; int cnt = 0;
        for (int t = lane; t < Ssz; t += 32) {
            cnt += mk[t];
            if (t >= 1) {
                float mf = (float)mk[t];
                part += (s_tr[lab[t-1]*NLsz + lab[t]] + lgb[t*NLsz + lab[t]]) * mf;
            }
        }
        for (int o = 16; o; o >>= 1) {
            part += __shfl_xor_sync(0xffffffffu, part, o);
            cnt  += __shfl_xor_sync(0xffffffffu, cnt, o);
        }
        float num = 0.f;
        if (lane == 0) {
            int l0 = lab[0];
            num = st[l0] + lgb[l0] + part + en[lab[cnt-1]];
        }
        int j = lane;
        float alpha = (j < NLsz) ? st[j] + lgb[j] : -1e30f;
        for (int t = 1; t < Ssz; t++) {
            float g[NLsz];
            #pragma unroll
            for (int i = 0; i < NLsz; i++)
                g[i] = __shfl_sync(0xffffffffu, alpha, i) + ((j < NLsz) ? s_tr[i*NLsz + j] : 0.f);
            float mv = g[0];
            #pragma unroll
            for (int i = 1; i < NLsz; i++) mv = fmaxf(mv, g[i]);
            float sum = 0.f;
            #pragma unroll
            for (int i = 0; i < NLsz; i++) sum += expf(g[i] - mv);
            float nxt = mv + logf(sum) + ((j < NLsz) ? lgb[t*NLsz + j] : 0.f);
            if (mk[t] > 0 && j < NLsz) alpha = nxt;
        }
        float v = (j < NLsz) ? alpha + en[j] : -1e30f;
        float mv = v;
        for (int o = 16; o; o >>= 1) mv = fmaxf(mv, __shfl_xor_sync(0xffffffffu, mv, o));
        float s = (j < NLsz) ? expf(v - mv) : 0.f;
        for (int o = 16; o; o >>= 1) s += __shfl_xor_sync(0xffffffffu, s, o);
        if (lane == 0) s_res[b] = (mv + logf(s)) - num;
    }
    __syncthreads();
    if (threadIdx.x == 0) {
        float tot = 0.f;
        for (int b = 0; b < Bsz; b++) tot += s_res[b];
        out[0] = tot;
    }
}

// ---------------- host ----------------
extern "C" void kernel_launch(void* const* d_in, const int* in_sizes, int n_in,
                              void* d_out, int out_size)
{
    const int*   input_ids = (const int*)  d_in[0];
    const int*   attn_mask = (const int*)  d_in[1];
    const int*   labels    = (const int*)  d_in[2];
    const float* token_emb = (const float*)d_in[3];
    const float* pos_emb   = (const float*)d_in[4];
    const float* ln_emb_s  = (const float*)d_in[5];
    const float* ln_emb_b  = (const float*)d_in[6];
    const float* Wq        = (const float*)d_in[7];
    const float* bq        = (const float*)d_in[8];
    const float* Wk        = (const float*)d_in[9];
    const float* bk        = (const float*)d_in[10];
    const float* Wv        = (const float*)d_in[11];
    const float* bv        = (const float*)d_in[12];
    const float* Wo        = (const float*)d_in[13];
    const float* bo        = (const float*)d_in[14];
    const float* ln1_s     = (const float*)d_in[15];
    const float* ln1_b     = (const float*)d_in[16];
    const float* W1        = (const float*)d_in[17];
    const float* b1        = (const float*)d_in[18];
    const float* W2        = (const float*)d_in[19];
    const float* b2        = (const float*)d_in[20];
    const float* ln2_s     = (const float*)d_in[21];
    const float* ln2_b     = (const float*)d_in[22];
    const float* cls_W     = (const float*)d_in[23];
    const float* cls_b     = (const float*)d_in[24];
    const float* start_tr  = (const float*)d_in[25];
    const float* end_tr    = (const float*)d_in[26];
    const float* trans     = (const float*)d_in[27];

    float *x, *t, *lg;
    __nv_bfloat16 *qb, *kb, *vb, *cb, *hb;
    { void* p; cudaGetSymbolAddress(&p, g_x);  x  = (float*)p; }
    { void* p; cudaGetSymbolAddress(&p, g_t);  t  = (float*)p; }
    { void* p; cudaGetSymbolAddress(&p, g_lg); lg = (float*)p; }
    { void* p; cudaGetSymbolAddress(&p, g_qb); qb = (__nv_bfloat16*)p; }
    { void* p; cudaGetSymbolAddress(&p, g_kb); kb = (__nv_bfloat16*)p; }
    { void* p; cudaGetSymbolAddress(&p, g_vb); vb = (__nv_bfloat16*)p; }
    { void* p; cudaGetSymbolAddress(&p, g_cb); cb = (__nv_bfloat16*)p; }
    { void* p; cudaGetSymbolAddress(&p, g_hb); hb = (__nv_bfloat16*)p; }

    embed_kernel<<<Tsz, 256>>>(input_ids, token_emb, pos_emb, t);
    ln_kernel<<<Tsz, 256>>>(t, ln_emb_s, ln_emb_b, x);

    for (int l = 0; l < Lsz; l++) {
        const float* wq = Wq + (size_t)l*Hsz*Hsz;
        const float* wk = Wk + (size_t)l*Hsz*Hsz;
        const float* wv = Wv + (size_t)l*Hsz*Hsz;
        const float* wo = Wo + (size_t)l*Hsz*Hsz;

        mma_qkv_kernel<<<dim3(Hsz/128, Tsz/128, 3), 256>>>(
            x, wq, wk, wv, bq + l*Hsz, bk + l*Hsz, bv + l*Hsz, qb, kb, vb);

        flash_attn_kernel<<<dim3(Ssz/64, Bsz*NHsz), 128>>>(qb, kb, vb, attn_mask, cb);

        gemm_res_bf16A_kernel<<<dim3(Hsz/128, Tsz/128), 256>>>(cb, wo, bo + l*Hsz, x, t, Hsz, Hsz);
        ln_kernel<<<Tsz, 256>>>(t, ln1_s + l*Hsz, ln1_b + l*Hsz, x);

        gemm_gelu_kernel<<<dim3(DFFsz/128, Tsz/128), 256>>>(
            x, W1 + (size_t)l*Hsz*DFFsz, b1 + l*DFFsz, hb, DFFsz, Hsz);
        gemm_res_bf16A_kernel<<<dim3(Hsz/128, Tsz/128), 256>>>(
            hb, W2 + (size_t)l*DFFsz*Hsz, b2 + l*Hsz, x, t, Hsz, DFFsz);
        ln_kernel<<<Tsz, 256>>>(t, ln2_s + l*Hsz, ln2_b + l*Hsz, x);
    }

    sgemm_kernel<<<dim3(1, Tsz/64), 256>>>(x, cls_W, cls_b, lg, Tsz, NLsz, Hsz);
    crf_kernel<<<1, 256>>>(lg, labels, attn_mask, start_tr, end_tr, trans, (float*)d_out);
}

// round 12
// speedup vs baseline: 5.8928x; 1.0012x over previous
#include <cuda_runtime.h>
#include <cuda_bf16.h>
#include <math.h>
#include <stdint.h>

#define Bsz  8
#define Ssz  512
#define Hsz  768
#define Lsz  12
#define NHsz 12
#define DHsz 64
#define DFFsz 3072
#define NLsz 19
#define Tsz  (Bsz*Ssz)   // 4096 tokens

// ---------------- scratch ----------------
__device__ float          g_x [Tsz*Hsz];
__device__ float          g_t [Tsz*Hsz];
__device__ __nv_bfloat16  g_qb[Tsz*Hsz];
__device__ __nv_bfloat16  g_kb[Tsz*Hsz];
__device__ __nv_bfloat16  g_vb[Tsz*Hsz];
__device__ __nv_bfloat16  g_cb[Tsz*Hsz];
__device__ __nv_bfloat16  g_hb[Tsz*DFFsz];
__device__ float          g_lg[Tsz*NLsz];

// ---------------- embedding ----------------
__global__ void embed_kernel(const int* __restrict__ ids,
                             const float* __restrict__ tok,
                             const float* __restrict__ pos,
                             float* __restrict__ out)
{
    int t = blockIdx.x;
    int s = t & (Ssz-1);
    int id = ids[t];
    const float* tp = tok + (size_t)id*Hsz;
    const float* pp = pos + (size_t)s*Hsz;
    float* op = out + (size_t)t*Hsz;
    for (int c = threadIdx.x; c < Hsz; c += blockDim.x)
        op[c] = tp[c] + pp[c];
}

// ---------------- layernorm ----------------
__global__ void ln_kernel(const float* __restrict__ in,
                          const float* __restrict__ gamma,
                          const float* __restrict__ beta,
                          float* __restrict__ out)
{
    __shared__ float sh[32];
    int row = blockIdx.x;
    int tid = threadIdx.x;
    const float* p = in + (size_t)row*Hsz;
    float v0 = p[tid], v1 = p[tid+256], v2 = p[tid+512];
    float s = v0+v1+v2;
    int lane = tid & 31, w = tid >> 5;
    for (int o = 16; o; o >>= 1) s += __shfl_xor_sync(0xffffffffu, s, o);
    if (!lane) sh[w] = s;
    __syncthreads();
    if (w == 0) {
        s = (lane < 8) ? sh[lane] : 0.f;
        for (int o = 4; o; o >>= 1) s += __shfl_xor_sync(0xffffffffu, s, o);
        if (!lane) sh[0] = s;
    }
    __syncthreads();
    float mean = sh[0] * (1.0f/Hsz);
    __syncthreads();
    float d0 = v0-mean, d1 = v1-mean, d2 = v2-mean;
    float q = d0*d0 + d1*d1 + d2*d2;
    for (int o = 16; o; o >>= 1) q += __shfl_xor_sync(0xffffffffu, q, o);
    if (!lane) sh[w] = q;
    __syncthreads();
    if (w == 0) {
        q = (lane < 8) ? sh[lane] : 0.f;
        for (int o = 4; o; o >>= 1) q += __shfl_xor_sync(0xffffffffu, q, o);
        if (!lane) sh[0] = q;
    }
    __syncthreads();
    float var = sh[0] * (1.0f/Hsz);
    float inv = rsqrtf(var + 1e-12f);
    float* op = out + (size_t)row*Hsz;
    op[tid    ] = d0*inv*gamma[tid    ] + beta[tid    ];
    op[tid+256] = d1*inv*gamma[tid+256] + beta[tid+256];
    op[tid+512] = d2*inv*gamma[tid+512] + beta[tid+512];
}

// ================= MMA primitives =================
__device__ __forceinline__ void ldsm_x4(uint32_t (&r)[4], uint32_t addr) {
    asm volatile("ldmatrix.sync.aligned.m8n8.x4.shared.b16 {%0,%1,%2,%3}, [%4];"
        : "=r"(r[0]),"=r"(r[1]),"=r"(r[2]),"=r"(r[3]) : "r"(addr));
}
__device__ __forceinline__ void ldsm_x4_t(uint32_t (&r)[4], uint32_t addr) {
    asm volatile("ldmatrix.sync.aligned.m8n8.x4.trans.shared.b16 {%0,%1,%2,%3}, [%4];"
        : "=r"(r[0]),"=r"(r[1]),"=r"(r[2]),"=r"(r[3]) : "r"(addr));
}
__device__ __forceinline__ void mma16816(float (&c)[4], const uint32_t (&a)[4],
                                         uint32_t b0, uint32_t b1) {
    asm volatile("mma.sync.aligned.m16n8k16.row.col.f32.bf16.bf16.f32 "
        "{%0,%1,%2,%3}, {%4,%5,%6,%7}, {%8,%9}, {%0,%1,%2,%3};"
        : "+f"(c[0]),"+f"(c[1]),"+f"(c[2]),"+f"(c[3])
        : "r"(a[0]),"r"(a[1]),"r"(a[2]),"r"(a[3]), "r"(b0),"r"(b1));
}
__device__ __forceinline__ uint32_t pack_bf16(float x, float y) {
    __nv_bfloat162 h = __floats2bfloat162_rn(x, y);
    return *(uint32_t*)&h;
}

// ================= GEMM: C = A[M,K] @ W[K,N] + bias (+epilogue) =================
// Block 128x128x32, 256 threads (8 warps, 64x32 warp tiles)
// MODE: 0 = bias -> fp32, 1 = bias+gelu -> bf16, 2 = bias+residual -> fp32, 3 = bias -> bf16
#define APAD 40
#define WPAD 136

template<typename AT, int MODE>
__device__ __forceinline__ void gemm_core(
    const AT* __restrict__ A, const float* __restrict__ W,
    const float* __restrict__ bias, const float* __restrict__ res,
    void* __restrict__ Cout, int N, int K, int m0, int n0)
{
    __shared__ __nv_bfloat16 As[2][128*APAD];
    __shared__ __nv_bfloat16 Ws[2][32*WPAD];
    int tid = threadIdx.x;
    int warp = tid >> 5, lane = tid & 31;
    int wm = warp >> 2;
    int wn = warp & 3;

    float acc[4][4][4];
    #pragma unroll
    for (int i = 0; i < 4; i++)
        #pragma unroll
        for (int j = 0; j < 4; j++)
            #pragma unroll
            for (int e = 0; e < 4; e++) acc[i][j][e] = 0.f;

    float4 ra[4], rw[4];
    uint4  rab[2];
    const int KT = K >> 5;

    // ---- prologue loads (tile 0) ----
    if (sizeof(AT) == 4) {
        #pragma unroll
        for (int i = 0; i < 4; i++) {
            int idx = tid + i*256;
            int r = idx >> 3, c4 = idx & 7;
            ra[i] = *(const float4*)((const float*)A + (size_t)(m0 + r)*K + c4*4);
        }
    } else {
        #pragma unroll
        for (int i = 0; i < 2; i++) {
            int idx = tid + i*256;
            int r = idx >> 2, c8 = idx & 3;
            rab[i] = *(const uint4*)((const __nv_bfloat16*)A + (size_t)(m0 + r)*K + c8*8);
        }
    }
    #pragma unroll
    for (int i = 0; i < 4; i++) {
        int idx = tid + i*256;
        int rr = idx >> 5, cw = idx & 31;
        rw[i] = *(const float4*)(W + (size_t)rr*N + n0 + cw*4);
    }
    if (sizeof(AT) == 4) {
        #pragma unroll
        for (int i = 0; i < 4; i++) {
            int idx = tid + i*256;
            int r = idx >> 3, c4 = idx & 7;
            *(__nv_bfloat162*)&As[0][r*APAD + c4*4    ] = __floats2bfloat162_rn(ra[i].x, ra[i].y);
            *(__nv_bfloat162*)&As[0][r*APAD + c4*4 + 2] = __floats2bfloat162_rn(ra[i].z, ra[i].w);
        }
    } else {
        #pragma unroll
        for (int i = 0; i < 2; i++) {
            int idx = tid + i*256;
            int r = idx >> 2, c8 = idx & 3;
            *(uint4*)&As[0][r*APAD + c8*8] = rab[i];
        }
    }
    #pragma unroll
    for (int i = 0; i < 4; i++) {
        int idx = tid + i*256;
        int rr = idx >> 5, cw = idx & 31;
        *(__nv_bfloat162*)&Ws[0][rr*WPAD + cw*4    ] = __floats2bfloat162_rn(rw[i].x, rw[i].y);
        *(__nv_bfloat162*)&Ws[0][rr*WPAD + cw*4 + 2] = __floats2bfloat162_rn(rw[i].z, rw[i].w);
    }
    __syncthreads();

    for (int kt = 0; kt < KT; kt++) {
        int cur = kt & 1;
        bool has_next = (kt + 1 < KT);
        if (has_next) {
            int k0 = (kt+1) << 5;
            if (sizeof(AT) == 4) {
                #pragma unroll
                for (int i = 0; i < 4; i++) {
                    int idx = tid + i*256;
                    int r = idx >> 3, c4 = idx & 7;
                    ra[i] = *(const float4*)((const float*)A + (size_t)(m0 + r)*K + k0 + c4*4);
                }
            } else {
                #pragma unroll
                for (int i = 0; i < 2; i++) {
                    int idx = tid + i*256;
                    int r = idx >> 2, c8 = idx & 3;
                    rab[i] = *(const uint4*)((const __nv_bfloat16*)A + (size_t)(m0 + r)*K + k0 + c8*8);
                }
            }
            #pragma unroll
            for (int i = 0; i < 4; i++) {
                int idx = tid + i*256;
                int rr = idx >> 5, cw = idx & 31;
                rw[i] = *(const float4*)(W + (size_t)(k0 + rr)*N + n0 + cw*4);
            }
        }
        #pragma unroll
        for (int ks = 0; ks < 2; ks++) {
            uint32_t af[4][4];
            #pragma unroll
            for (int i = 0; i < 4; i++) {
                int r = wm*64 + i*16 + (lane & 15);
                int c = ks*16 + (lane >> 4)*8;
                uint32_t addr = (uint32_t)__cvta_generic_to_shared(&As[cur][r*APAD + c]);
                ldsm_x4(af[i], addr);
            }
            uint32_t bf[2][4];
            #pragma unroll
            for (int j2 = 0; j2 < 2; j2++) {
                int kk = ks*16 + ((lane>>3)&1)*8 + (lane&7);
                int nn = wn*32 + j2*16 + (lane>>4)*8;
                uint32_t addr = (uint32_t)__cvta_generic_to_shared(&Ws[cur][kk*WPAD + nn]);
                ldsm_x4_t(bf[j2], addr);
            }
            #pragma unroll
            for (int i = 0; i < 4; i++)
                #pragma unroll
                for (int j = 0; j < 4; j++)
                    mma16816(acc[i][j], af[i], bf[j>>1][(j&1)*2], bf[j>>1][(j&1)*2+1]);
        }
        if (has_next) {
            int nxt = cur ^ 1;
            if (sizeof(AT) == 4) {
                #pragma unroll
                for (int i = 0; i < 4; i++) {
                    int idx = tid + i*256;
                    int r = idx >> 3, c4 = idx & 7;
                    *(__nv_bfloat162*)&As[nxt][r*APAD + c4*4    ] = __floats2bfloat162_rn(ra[i].x, ra[i].y);
                    *(__nv_bfloat162*)&As[nxt][r*APAD + c4*4 + 2] = __floats2bfloat162_rn(ra[i].z, ra[i].w);
                }
            } else {
                #pragma unroll
                for (int i = 0; i < 2; i++) {
                    int idx = tid + i*256;
                    int r = idx >> 2, c8 = idx & 3;
                    *(uint4*)&As[nxt][r*APAD + c8*8] = rab[i];
                }
            }
            #pragma unroll
            for (int i = 0; i < 4; i++) {
                int idx = tid + i*256;
                int rr = idx >> 5, cw = idx & 31;
                *(__nv_bfloat162*)&Ws[nxt][rr*WPAD + cw*4    ] = __floats2bfloat162_rn(rw[i].x, rw[i].y);
                *(__nv_bfloat162*)&Ws[nxt][rr*WPAD + cw*4 + 2] = __floats2bfloat162_rn(rw[i].z, rw[i].w);
            }
        }
        __syncthreads();
    }

    // ---- epilogue ----
    #pragma unroll
    for (int i = 0; i < 4; i++) {
        int mb = m0 + wm*64 + i*16 + (lane >> 2);
        #pragma unroll
        for (int j = 0; j < 4; j++) {
            int nb = n0 + wn*32 + j*8 + (lane & 3)*2;
            float b0 = bias[nb], b1 = bias[nb+1];
            #pragma unroll
            for (int half = 0; half < 2; half++) {
                int m = mb + half*8;
                float v0 = acc[i][j][half*2]   + b0;
                float v1 = acc[i][j][half*2+1] + b1;
                if (MODE == 1) {
                    float x3 = v0*v0*v0;
                    v0 = 0.5f*v0*(1.0f + tanhf(0.7978845608028654f*(v0 + 0.044715f*x3)));
                    x3 = v1*v1*v1;
                    v1 = 0.5f*v1*(1.0f + tanhf(0.7978845608028654f*(v1 + 0.044715f*x3)));
                } else if (MODE == 2) {
                    float2 r2 = *(const float2*)(res + (size_t)m*N + nb);
                    v0 += r2.x; v1 += r2.y;
                }
                if (MODE == 1 || MODE == 3) {
                    *(__nv_bfloat162*)((__nv_bfloat16*)Cout + (size_t)m*N + nb) =
                        __floats2bfloat162_rn(v0, v1);
                } else {
                    float2 o; o.x = v0; o.y = v1;
                    *(float2*)((float*)Cout + (size_t)m*N + nb) = o;
                }
            }
        }
    }
}

__global__ __launch_bounds__(256) void gemm_gelu_kernel(
    const float* __restrict__ A, const float* __restrict__ W,
    const float* __restrict__ bias, __nv_bfloat16* __restrict__ C, int N, int K)
{
    gemm_core<float,1>(A, W, bias, nullptr, C, N, K, blockIdx.y*128, blockIdx.x*128);
}
__global__ __launch_bounds__(256) void gemm_res_f32A_kernel(
    const float* __restrict__ A, const float* __restrict__ W,
    const float* __restrict__ bias, const float* __restrict__ res,
    float* __restrict__ C, int N, int K)
{
    gemm_core<float,2>(A, W, bias, res, C, N, K, blockIdx.y*128, blockIdx.x*128);
}
__global__ __launch_bounds__(256) void gemm_res_bf16A_kernel(
    const __nv_bfloat16* __restrict__ A, const float* __restrict__ W,
    const float* __restrict__ bias, const float* __restrict__ res,
    float* __restrict__ C, int N, int K)
{
    gemm_core<__nv_bfloat16,2>(A, W, bias, res, C, N, K, blockIdx.y*128, blockIdx.x*128);
}
__global__ __launch_bounds__(256) void mma_qkv_kernel(
    const float* __restrict__ A,
    const float* __restrict__ Wq, const float* __restrict__ Wk, const float* __restrict__ Wv,
    const float* __restrict__ bq, const float* __restrict__ bk, const float* __restrict__ bv,
    __nv_bfloat16* __restrict__ q, __nv_bfloat16* __restrict__ k, __nv_bfloat16* __restrict__ v)
{
    int z = blockIdx.z;
    const float* W  = (z == 0) ? Wq : (z == 1) ? Wk : Wv;
    const float* bb = (z == 0) ? bq : (z == 1) ? bk : bv;
    __nv_bfloat16* C = (z == 0) ? q : (z == 1) ? k : v;
    gemm_core<float,3>(A, W, bb, nullptr, C, Hsz, Hsz, blockIdx.y*128, blockIdx.x*128);
}

// ================= flash attention =================
// grid (Ssz/64, B*NH), 128 threads (4 warps). Each warp owns 16 Q rows.
#define FPAD 72   // 64 + 8 bf16 pad

__global__ __launch_bounds__(128) void flash_attn_kernel(
    const __nv_bfloat16* __restrict__ q, const __nv_bfloat16* __restrict__ k,
    const __nv_bfloat16* __restrict__ v, const int* __restrict__ mask,
    __nv_bfloat16* __restrict__ ctx)
{
    __shared__ __nv_bfloat16 Qs[64*FPAD];
    __shared__ __nv_bfloat16 Ks[64*FPAD];
    __shared__ __nv_bfloat16 Vs[64*FPAD];
    __shared__ float s_bias[Ssz];

    int bh = blockIdx.y;
    int b = bh / NHsz, h = bh % NHsz;
    int i0 = blockIdx.x * 64;
    int tid = threadIdx.x;
    int warp = tid >> 5, lane = tid & 31;
    int g = lane >> 2, t4 = lane & 3;

    // bias from mask
    #pragma unroll
    for (int it = 0; it < 4; it++) {
        int j = tid + it*128;
        s_bias[j] = mask[b*Ssz + j] ? 0.f : -1e9f;
    }
    // load Q tile
    #pragma unroll
    for (int it = 0; it < 4; it++) {
        int idx = tid + it*128;
        int r = idx >> 3, c8 = idx & 7;
        *(uint4*)&Qs[r*FPAD + c8*8] =
            *(const uint4*)(q + (size_t)(b*Ssz + i0 + r)*Hsz + h*DHsz + c8*8);
    }
    __syncthreads();

    // Q fragments (held in registers for the whole loop)
    uint32_t qf[4][4];
    #pragma unroll
    for (int ks = 0; ks < 4; ks++) {
        int r = warp*16 + (lane & 15);
        int c = ks*16 + (lane >> 4)*8;
        ldsm_x4(qf[ks], (uint32_t)__cvta_generic_to_shared(&Qs[r*FPAD + c]));
    }

    float oacc[8][4];
    #pragma unroll
    for (int n = 0; n < 8; n++)
        #pragma unroll
        for (int e = 0; e < 4; e++) oacc[n][e] = 0.f;
    float m0v = -1e30f, m1v = -1e30f, l0 = 0.f, l1 = 0.f;

    for (int j0 = 0; j0 < Ssz; j0 += 64) {
        __syncthreads();
        // load K, V tiles
        #pragma unroll
        for (int it = 0; it < 4; it++) {
            int idx = tid + it*128;
            int r = idx >> 3, c8 = idx & 7;
            size_t goff = (size_t)(b*Ssz + j0 + r)*Hsz + h*DHsz + c8*8;
            *(uint4*)&Ks[r*FPAD + c8*8] = *(const uint4*)(k + goff);
            *(uint4*)&Vs[r*FPAD + c8*8] = *(const uint4*)(v + goff);
        }
        __syncthreads();

        // S = Q @ K^T  (16x64 per warp)
        float acc[8][4];
        #pragma unroll
        for (int n = 0; n < 8; n++)
            #pragma unroll
            for (int e = 0; e < 4; e++) acc[n][e] = 0.f;
        #pragma unroll
        for (int jj = 0; jj < 4; jj++) {
            #pragma unroll
            for (int ks = 0; ks < 4; ks++) {
                uint32_t bf[4];
                int r = jj*16 + (lane & 15);
                int c = ks*16 + (lane >> 4)*8;
                ldsm_x4(bf, (uint32_t)__cvta_generic_to_shared(&Ks[r*FPAD + c]));
                mma16816(acc[jj*2  ], qf[ks], bf[0], bf[2]);
                mma16816(acc[jj*2+1], qf[ks], bf[1], bf[3]);
            }
        }

        // scale + bias, online softmax
        float p[8][4];
        float mx0 = -1e30f, mx1 = -1e30f;
        #pragma unroll
        for (int n = 0; n < 8; n++) {
            float b0 = s_bias[j0 + n*8 + t4*2];
            float b1 = s_bias[j0 + n*8 + t4*2 + 1];
            p[n][0] = acc[n][0]*0.125f + b0;
            p[n][1] = acc[n][1]*0.125f + b1;
            p[n][2] = acc[n][2]*0.125f + b0;
            p[n][3] = acc[n][3]*0.125f + b1;
            mx0 = fmaxf(mx0, fmaxf(p[n][0], p[n][1]));
            mx1 = fmaxf(mx1, fmaxf(p[n][2], p[n][3]));
        }
        mx0 = fmaxf(mx0, __shfl_xor_sync(0xffffffffu, mx0, 1));
        mx0 = fmaxf(mx0, __shfl_xor_sync(0xffffffffu, mx0, 2));
        mx1 = fmaxf(mx1, __shfl_xor_sync(0xffffffffu, mx1, 1));
        mx1 = fmaxf(mx1, __shfl_xor_sync(0xffffffffu, mx1, 2));
        float mn0 = fmaxf(m0v, mx0);
        float mn1 = fmaxf(m1v, mx1);
        float lt0 = 0.f, lt1 = 0.f;
        #pragma unroll
        for (int n = 0; n < 8; n++) {
            p[n][0] = __expf(p[n][0] - mn0);
            p[n][1] = __expf(p[n][1] - mn0);
            p[n][2] = __expf(p[n][2] - mn1);
            p[n][3] = __expf(p[n][3] - mn1);
            lt0 += p[n][0] + p[n][1];
            lt1 += p[n][2] + p[n][3];
        }
        lt0 += __shfl_xor_sync(0xffffffffu, lt0, 1);
        lt0 += __shfl_xor_sync(0xffffffffu, lt0, 2);
        lt1 += __shfl_xor_sync(0xffffffffu, lt1, 1);
        lt1 += __shfl_xor_sync(0xffffffffu, lt1, 2);
        float sc0 = __expf(m0v - mn0);
        float sc1 = __expf(m1v - mn1);
        l0 = l0*sc0 + lt0;
        l1 = l1*sc1 + lt1;
        m0v = mn0; m1v = mn1;
        #pragma unroll
        for (int n = 0; n < 8; n++) {
            oacc[n][0] *= sc0; oacc[n][1] *= sc0;
            oacc[n][2] *= sc1; oacc[n][3] *= sc1;
        }

        // P fragments (A-operand of PV mma)
        uint32_t pa[4][4];
        #pragma unroll
        for (int c = 0; c < 4; c++) {
            pa[c][0] = pack_bf16(p[2*c  ][0], p[2*c  ][1]);
            pa[c][1] = pack_bf16(p[2*c  ][2], p[2*c  ][3]);
            pa[c][2] = pack_bf16(p[2*c+1][0], p[2*c+1][1]);
            pa[c][3] = pack_bf16(p[2*c+1][2], p[2*c+1][3]);
        }

        // O += P @ V
        #pragma unroll
        for (int db = 0; db < 4; db++) {
            #pragma unroll
            for (int c = 0; c < 4; c++) {
                uint32_t vf[4];
                int kk = c*16 + ((lane>>3)&1)*8 + (lane&7);
                int nn = db*16 + (lane>>4)*8;
                ldsm_x4_t(vf, (uint32_t)__cvta_generic_to_shared(&Vs[kk*FPAD + nn]));
                mma16816(oacc[db*2  ], pa[c], vf[0], vf[1]);
                mma16816(oacc[db*2+1], pa[c], vf[2], vf[3]);
            }
        }
    }

    // write ctx (bf16), normalized
    float inv0 = 1.0f / l0, inv1 = 1.0f / l1;
    #pragma unroll
    for (int n = 0; n < 8; n++) {
        int d = n*8 + t4*2;
        int r0 = i0 + warp*16 + g;
        *(__nv_bfloat162*)(ctx + (size_t)(b*Ssz + r0)*Hsz + h*DHsz + d) =
            __floats2bfloat162_rn(oacc[n][0]*inv0, oacc[n][1]*inv0);
        *(__nv_bfloat162*)(ctx + (size_t)(b*Ssz + r0 + 8)*Hsz + h*DHsz + d) =
            __floats2bfloat162_rn(oacc[n][2]*inv1, oacc[n][3]*inv1);
    }
}

// ---------------- classifier (N=19, SIMT) ----------------
__global__ void sgemm_kernel(const float* __restrict__ A, const float* __restrict__ W,
                             const float* __restrict__ bias, float* __restrict__ C,
                             int M, int N, int K)
{
    __shared__ float As[64][17];
    __shared__ float Ws[16][64];
    int m0 = blockIdx.y * 64;
    int n0 = blockIdx.x * 64;
    int tid = threadIdx.x;
    int ty = tid >> 4, tx = tid & 15;
    float acc[4][4] = {};
    for (int k0 = 0; k0 < K; k0 += 16) {
        #pragma unroll
        for (int i = 0; i < 4; i++) {
            int idx = tid + i*256;
            int r = idx >> 4, c = idx & 15;
            As[r][c] = A[(size_t)(m0+r)*K + (k0+c)];
        }
        #pragma unroll
        for (int i = 0; i < 4; i++) {
            int idx = tid + i*256;
            int r = idx >> 6, c = idx & 63;
            int n = n0 + c;
            Ws[r][c] = (n < N) ? W[(size_t)(k0+r)*N + n] : 0.f;
        }
        __syncthreads();
        #pragma unroll
        for (int kk = 0; kk < 16; kk++) {
            float a[4], b[4];
            #pragma unroll
            for (int i = 0; i < 4; i++) a[i] = As[ty*4+i][kk];
            #pragma unroll
            for (int j = 0; j < 4; j++) b[j] = Ws[kk][tx*4+j];
            #pragma unroll
            for (int i = 0; i < 4; i++)
                #pragma unroll
                for (int j = 0; j < 4; j++)
                    acc[i][j] = fmaf(a[i], b[j], acc[i][j]);
        }
        __syncthreads();
    }
    #pragma unroll
    for (int i = 0; i < 4; i++) {
        int m = m0 + ty*4 + i;
        #pragma unroll
        for (int j = 0; j < 4; j++) {
            int n = n0 + tx*4 + j;
            if (n < N) C[(size_t)m*N + n] = acc[i][j] + bias[n];
        }
    }
}

// ---------------- CRF ----------------
__global__ void crf_kernel(const float* __restrict__ lg, const int* __restrict__ labels,
                           const int* __restrict__ mask, const float* __restrict__ st,
                           const float* __restrict__ en, const float* __restrict__ tr,
                           float* __restrict__ out)
{
    __shared__ float s_tr[NLsz*NLsz];
    __shared__ float s_res[Bsz];
    for (int i = threadIdx.x; i < NLsz*NLsz; i += blockDim.x) s_tr[i] = tr[i];
    __syncthreads();
    int warp = threadIdx.x >> 5, lane = threadIdx.x & 31;
    if (warp < Bsz) {
        int b = warp;
        const int* lab = labels + b*Ssz;
        const int* mk  = mask + b*Ssz;
        const float* lgb = lg + (size_t)b*Ssz*NLsz;
        float part = 0.f; int cnt = 0;
        for (int t = lane; t < Ssz; t += 32) {
            cnt += mk[t];
            if (t >= 1) {
                float mf = (float)mk[t];
                part += (s_tr[lab[t-1]*NLsz + lab[t]] + lgb[t*NLsz + lab[t]]) * mf;
            }
        }
        for (int o = 16; o; o >>= 1) {
            part += __shfl_xor_sync(0xffffffffu, part, o);
            cnt  += __shfl_xor_sync(0xffffffffu, cnt, o);
        }
        float num = 0.f;
        if (lane == 0) {
            int l0 = lab[0];
            num = st[l0] + lgb[l0] + part + en[lab[cnt-1]];
        }
        int j = lane;
        float alpha = (j < NLsz) ? st[j] + lgb[j] : -1e30f;
        for (int t = 1; t < Ssz; t++) {
            float g[NLsz];
            #pragma unroll
            for (int i = 0; i < NLsz; i++)
                g[i] = __shfl_sync(0xffffffffu, alpha, i) + ((j < NLsz) ? s_tr[i*NLsz + j] : 0.f);
            float mv = g[0];
            #pragma unroll
            for (int i = 1; i < NLsz; i++) mv = fmaxf(mv, g[i]);
            float sum = 0.f;
            #pragma unroll
            for (int i = 0; i < NLsz; i++) sum += expf(g[i] - mv);
            float nxt = mv + logf(sum) + ((j < NLsz) ? lgb[t*NLsz + j] : 0.f);
            if (mk[t] > 0 && j < NLsz) alpha = nxt;
        }
        float v = (j < NLsz) ? alpha + en[j] : -1e30f;
        float mv = v;
        for (int o = 16; o; o >>= 1) mv = fmaxf(mv, __shfl_xor_sync(0xffffffffu, mv, o));
        float s = (j < NLsz) ? expf(v - mv) : 0.f;
        for (int o = 16; o; o >>= 1) s += __shfl_xor_sync(0xffffffffu, s, o);
        if (lane == 0) s_res[b] = (mv + logf(s)) - num;
    }
    __syncthreads();
    if (threadIdx.x == 0) {
        float tot = 0.f;
        for (int b = 0; b < Bsz; b++) tot += s_res[b];
        out[0] = tot;
    }
}

// ---------------- host ----------------
extern "C" void kernel_launch(void* const* d_in, const int* in_sizes, int n_in,
                              void* d_out, int out_size)
{
    const int*   input_ids = (const int*)  d_in[0];
    const int*   attn_mask = (const int*)  d_in[1];
    const int*   labels    = (const int*)  d_in[2];
    const float* token_emb = (const float*)d_in[3];
    const float* pos_emb   = (const float*)d_in[4];
    const float* ln_emb_s  = (const float*)d_in[5];
    const float* ln_emb_b  = (const float*)d_in[6];
    const float* Wq        = (const float*)d_in[7];
    const float* bq        = (const float*)d_in[8];
    const float* Wk        = (const float*)d_in[9];
    const float* bk        = (const float*)d_in[10];
    const float* Wv        = (const float*)d_in[11];
    const float* bv        = (const float*)d_in[12];
    const float* Wo        = (const float*)d_in[13];
    const float* bo        = (const float*)d_in[14];
    const float* ln1_s     = (const float*)d_in[15];
    const float* ln1_b     = (const float*)d_in[16];
    const float* W1        = (const float*)d_in[17];
    const float* b1        = (const float*)d_in[18];
    const float* W2        = (const float*)d_in[19];
    const float* b2        = (const float*)d_in[20];
    const float* ln2_s     = (const float*)d_in[21];
    const float* ln2_b     = (const float*)d_in[22];
    const float* cls_W     = (const float*)d_in[23];
    const float* cls_b     = (const float*)d_in[24];
    const float* start_tr  = (const float*)d_in[25];
    const float* end_tr    = (const float*)d_in[26];
    const float* trans     = (const float*)d_in[27];

    float *x, *t, *lg;
    __nv_bfloat16 *qb, *kb, *vb, *cb, *hb;
    { void* p; cudaGetSymbolAddress(&p, g_x);  x  = (float*)p; }
    { void* p; cudaGetSymbolAddress(&p, g_t);  t  = (float*)p; }
    { void* p; cudaGetSymbolAddress(&p, g_lg); lg = (float*)p; }
    { void* p; cudaGetSymbolAddress(&p, g_qb); qb = (__nv_bfloat16*)p; }
    { void* p; cudaGetSymbolAddress(&p, g_kb); kb = (__nv_bfloat16*)p; }
    { void* p; cudaGetSymbolAddress(&p, g_vb); vb = (__nv_bfloat16*)p; }
    { void* p; cudaGetSymbolAddress(&p, g_cb); cb = (__nv_bfloat16*)p; }
    { void* p; cudaGetSymbolAddress(&p, g_hb); hb = (__nv_bfloat16*)p; }

    embed_kernel<<<Tsz, 256>>>(input_ids, token_emb, pos_emb, t);
    ln_kernel<<<Tsz, 256>>>(t, ln_emb_s, ln_emb_b, x);

    for (int l = 0; l < Lsz; l++) {
        const float* wq = Wq + (size_t)l*Hsz*Hsz;
        const float* wk = Wk + (size_t)l*Hsz*Hsz;
        const float* wv = Wv + (size_t)l*Hsz*Hsz;
        const float* wo = Wo + (size_t)l*Hsz*Hsz;

        mma_qkv_kernel<<<dim3(Hsz/128, Tsz/128, 3), 256>>>(
            x, wq, wk, wv, bq + l*Hsz, bk + l*Hsz, bv + l*Hsz, qb, kb, vb);

        flash_attn_kernel<<<dim3(Ssz/64, Bsz*NHsz), 128>>>(qb, kb, vb, attn_mask, cb);

        gemm_res_bf16A_kernel<<<dim3(Hsz/128, Tsz/128), 256>>>(cb, wo, bo + l*Hsz, x, t, Hsz, Hsz);
        ln_kernel<<<Tsz, 256>>>(t, ln1_s + l*Hsz, ln1_b + l*Hsz, x);

        gemm_gelu_kernel<<<dim3(DFFsz/128, Tsz/128), 256>>>(
            x, W1 + (size_t)l*Hsz*DFFsz, b1 + l*DFFsz, hb, DFFsz, Hsz);
        gemm_res_bf16A_kernel<<<dim3(Hsz/128, Tsz/128), 256>>>(
            hb, W2 + (size_t)l*DFFsz*Hsz, b2 + l*Hsz, x, t, Hsz, DFFsz);
        ln_kernel<<<Tsz, 256>>>(t, ln2_s + l*Hsz, ln2_b + l*Hsz, x);
    }

    sgemm_kernel<<<dim3(1, Tsz/64), 256>>>(x, cls_W, cls_b, lg, Tsz, NLsz, Hsz);
    crf_kernel<<<1, 256>>>(lg, labels, attn_mask, start_tr, end_tr, trans, (float*)d_out);
}

// round 13
// speedup vs baseline: 5.8975x; 1.0008x over previous
#include <cuda_runtime.h>
#include <cuda_bf16.h>
#include <math.h>
#include <stdint.h>

#define Bsz  8
#define Ssz  512
#define Hsz  768
#define Lsz  12
#define NHsz 12
#define DHsz 64
#define DFFsz 3072
#define NLsz 19
#define Tsz  (Bsz*Ssz)   // 4096 tokens

// ---------------- scratch ----------------
__device__ float          g_x [Tsz*Hsz];
__device__ float          g_t [Tsz*Hsz];
__device__ __nv_bfloat16  g_qb[Tsz*Hsz];
__device__ __nv_bfloat16  g_kb[Tsz*Hsz];
__device__ __nv_bfloat16  g_vb[Tsz*Hsz];
__device__ __nv_bfloat16  g_cb[Tsz*Hsz];
__device__ __nv_bfloat16  g_hb[Tsz*DFFsz];
__device__ float          g_lg[Tsz*NLsz];

// ---------------- embedding ----------------
__global__ void embed_kernel(const int* __restrict__ ids,
                             const float* __restrict__ tok,
                             const float* __restrict__ pos,
                             float* __restrict__ out)
{
    int t = blockIdx.x;
    int s = t & (Ssz-1);
    int id = ids[t];
    const float* tp = tok + (size_t)id*Hsz;
    const float* pp = pos + (size_t)s*Hsz;
    float* op = out + (size_t)t*Hsz;
    for (int c = threadIdx.x; c < Hsz; c += blockDim.x)
        op[c] = tp[c] + pp[c];
}

// ---------------- layernorm ----------------
__global__ void ln_kernel(const float* __restrict__ in,
                          const float* __restrict__ gamma,
                          const float* __restrict__ beta,
                          float* __restrict__ out)
{
    __shared__ float sh[32];
    int row = blockIdx.x;
    int tid = threadIdx.x;
    const float* p = in + (size_t)row*Hsz;
    float v0 = p[tid], v1 = p[tid+256], v2 = p[tid+512];
    float s = v0+v1+v2;
    int lane = tid & 31, w = tid >> 5;
    for (int o = 16; o; o >>= 1) s += __shfl_xor_sync(0xffffffffu, s, o);
    if (!lane) sh[w] = s;
    __syncthreads();
    if (w == 0) {
        s = (lane < 8) ? sh[lane] : 0.f;
        for (int o = 4; o; o >>= 1) s += __shfl_xor_sync(0xffffffffu, s, o);
        if (!lane) sh[0] = s;
    }
    __syncthreads();
    float mean = sh[0] * (1.0f/Hsz);
    __syncthreads();
    float d0 = v0-mean, d1 = v1-mean, d2 = v2-mean;
    float q = d0*d0 + d1*d1 + d2*d2;
    for (int o = 16; o; o >>= 1) q += __shfl_xor_sync(0xffffffffu, q, o);
    if (!lane) sh[w] = q;
    __syncthreads();
    if (w == 0) {
        q = (lane < 8) ? sh[lane] : 0.f;
        for (int o = 4; o; o >>= 1) q += __shfl_xor_sync(0xffffffffu, q, o);
        if (!lane) sh[0] = q;
    }
    __syncthreads();
    float var = sh[0] * (1.0f/Hsz);
    float inv = rsqrtf(var + 1e-12f);
    float* op = out + (size_t)row*Hsz;
    op[tid    ] = d0*inv*gamma[tid    ] + beta[tid    ];
    op[tid+256] = d1*inv*gamma[tid+256] + beta[tid+256];
    op[tid+512] = d2*inv*gamma[tid+512] + beta[tid+512];
}

// ================= MMA primitives =================
__device__ __forceinline__ void ldsm_x4(uint32_t (&r)[4], uint32_t addr) {
    asm volatile("ldmatrix.sync.aligned.m8n8.x4.shared.b16 {%0,%1,%2,%3}, [%4];"
        : "=r"(r[0]),"=r"(r[1]),"=r"(r[2]),"=r"(r[3]) : "r"(addr));
}
__device__ __forceinline__ void ldsm_x4_t(uint32_t (&r)[4], uint32_t addr) {
    asm volatile("ldmatrix.sync.aligned.m8n8.x4.trans.shared.b16 {%0,%1,%2,%3}, [%4];"
        : "=r"(r[0]),"=r"(r[1]),"=r"(r[2]),"=r"(r[3]) : "r"(addr));
}
__device__ __forceinline__ void mma16816(float (&c)[4], const uint32_t (&a)[4],
                                         uint32_t b0, uint32_t b1) {
    asm volatile("mma.sync.aligned.m16n8k16.row.col.f32.bf16.bf16.f32 "
        "{%0,%1,%2,%3}, {%4,%5,%6,%7}, {%8,%9}, {%0,%1,%2,%3};"
        : "+f"(c[0]),"+f"(c[1]),"+f"(c[2]),"+f"(c[3])
        : "r"(a[0]),"r"(a[1]),"r"(a[2]),"r"(a[3]), "r"(b0),"r"(b1));
}
__device__ __forceinline__ uint32_t pack_bf16(float x, float y) {
    __nv_bfloat162 h = __floats2bfloat162_rn(x, y);
    return *(uint32_t*)&h;
}

// ================= GEMM: C = A[M,K] @ W[K,N] + bias (+epilogue) =================
// Block 128x128x32, 256 threads (8 warps, 64x32 warp tiles)
// MODE: 0 = bias -> fp32, 1 = bias+gelu -> bf16, 2 = bias+residual -> fp32, 3 = bias -> bf16
#define APAD 40
#define WPAD 136

template<typename AT, int MODE>
__device__ __forceinline__ void gemm_core(
    const AT* __restrict__ A, const float* __restrict__ W,
    const float* __restrict__ bias, const float* __restrict__ res,
    void* __restrict__ Cout, int N, int K, int m0, int n0)
{
    __shared__ __nv_bfloat16 As[2][128*APAD];
    __shared__ __nv_bfloat16 Ws[2][32*WPAD];
    int tid = threadIdx.x;
    int warp = tid >> 5, lane = tid & 31;
    int wm = warp >> 2;
    int wn = warp & 3;

    float acc[4][4][4];
    #pragma unroll
    for (int i = 0; i < 4; i++)
        #pragma unroll
        for (int j = 0; j < 4; j++)
            #pragma unroll
            for (int e = 0; e < 4; e++) acc[i][j][e] = 0.f;

    float4 ra[4], rw[4];
    uint4  rab[2];
    const int KT = K >> 5;

    // ---- prologue loads (tile 0) ----
    if (sizeof(AT) == 4) {
        #pragma unroll
        for (int i = 0; i < 4; i++) {
            int idx = tid + i*256;
            int r = idx >> 3, c4 = idx & 7;
            ra[i] = *(const float4*)((const float*)A + (size_t)(m0 + r)*K + c4*4);
        }
    } else {
        #pragma unroll
        for (int i = 0; i < 2; i++) {
            int idx = tid + i*256;
            int r = idx >> 2, c8 = idx & 3;
            rab[i] = *(const uint4*)((const __nv_bfloat16*)A + (size_t)(m0 + r)*K + c8*8);
        }
    }
    #pragma unroll
    for (int i = 0; i < 4; i++) {
        int idx = tid + i*256;
        int rr = idx >> 5, cw = idx & 31;
        rw[i] = *(const float4*)(W + (size_t)rr*N + n0 + cw*4);
    }
    if (sizeof(AT) == 4) {
        #pragma unroll
        for (int i = 0; i < 4; i++) {
            int idx = tid + i*256;
            int r = idx >> 3, c4 = idx & 7;
            *(__nv_bfloat162*)&As[0][r*APAD + c4*4    ] = __floats2bfloat162_rn(ra[i].x, ra[i].y);
            *(__nv_bfloat162*)&As[0][r*APAD + c4*4 + 2] = __floats2bfloat162_rn(ra[i].z, ra[i].w);
        }
    } else {
        #pragma unroll
        for (int i = 0; i < 2; i++) {
            int idx = tid + i*256;
            int r = idx >> 2, c8 = idx & 3;
            *(uint4*)&As[0][r*APAD + c8*8] = rab[i];
        }
    }
    #pragma unroll
    for (int i = 0; i < 4; i++) {
        int idx = tid + i*256;
        int rr = idx >> 5, cw = idx & 31;
        *(__nv_bfloat162*)&Ws[0][rr*WPAD + cw*4    ] = __floats2bfloat162_rn(rw[i].x, rw[i].y);
        *(__nv_bfloat162*)&Ws[0][rr*WPAD + cw*4 + 2] = __floats2bfloat162_rn(rw[i].z, rw[i].w);
    }
    __syncthreads();

    for (int kt = 0; kt < KT; kt++) {
        int cur = kt & 1;
        bool has_next = (kt + 1 < KT);
        if (has_next) {
            int k0 = (kt+1) << 5;
            if (sizeof(AT) == 4) {
                #pragma unroll
                for (int i = 0; i < 4; i++) {
                    int idx = tid + i*256;
                    int r = idx >> 3, c4 = idx & 7;
                    ra[i] = *(const float4*)((const float*)A + (size_t)(m0 + r)*K + k0 + c4*4);
                }
            } else {
                #pragma unroll
                for (int i = 0; i < 2; i++) {
                    int idx = tid + i*256;
                    int r = idx >> 2, c8 = idx & 3;
                    rab[i] = *(const uint4*)((const __nv_bfloat16*)A + (size_t)(m0 + r)*K + k0 + c8*8);
                }
            }
            #pragma unroll
            for (int i = 0; i < 4; i++) {
                int idx = tid + i*256;
                int rr = idx >> 5, cw = idx & 31;
                rw[i] = *(const float4*)(W + (size_t)(k0 + rr)*N + n0 + cw*4);
            }
        }
        #pragma unroll
        for (int ks = 0; ks < 2; ks++) {
            uint32_t af[4][4];
            #pragma unroll
            for (int i = 0; i < 4; i++) {
                int r = wm*64 + i*16 + (lane & 15);
                int c = ks*16 + (lane >> 4)*8;
                uint32_t addr = (uint32_t)__cvta_generic_to_shared(&As[cur][r*APAD + c]);
                ldsm_x4(af[i], addr);
            }
            uint32_t bf[2][4];
            #pragma unroll
            for (int j2 = 0; j2 < 2; j2++) {
                int kk = ks*16 + ((lane>>3)&1)*8 + (lane&7);
                int nn = wn*32 + j2*16 + (lane>>4)*8;
                uint32_t addr = (uint32_t)__cvta_generic_to_shared(&Ws[cur][kk*WPAD + nn]);
                ldsm_x4_t(bf[j2], addr);
            }
            #pragma unroll
            for (int i = 0; i < 4; i++)
                #pragma unroll
                for (int j = 0; j < 4; j++)
                    mma16816(acc[i][j], af[i], bf[j>>1][(j&1)*2], bf[j>>1][(j&1)*2+1]);
        }
        if (has_next) {
            int nxt = cur ^ 1;
            if (sizeof(AT) == 4) {
                #pragma unroll
                for (int i = 0; i < 4; i++) {
                    int idx = tid + i*256;
                    int r = idx >> 3, c4 = idx & 7;
                    *(__nv_bfloat162*)&As[nxt][r*APAD + c4*4    ] = __floats2bfloat162_rn(ra[i].x, ra[i].y);
                    *(__nv_bfloat162*)&As[nxt][r*APAD + c4*4 + 2] = __floats2bfloat162_rn(ra[i].z, ra[i].w);
                }
            } else {
                #pragma unroll
                for (int i = 0; i < 2; i++) {
                    int idx = tid + i*256;
                    int r = idx >> 2, c8 = idx & 3;
                    *(uint4*)&As[nxt][r*APAD + c8*8] = rab[i];
                }
            }
            #pragma unroll
            for (int i = 0; i < 4; i++) {
                int idx = tid + i*256;
                int rr = idx >> 5, cw = idx & 31;
                *(__nv_bfloat162*)&Ws[nxt][rr*WPAD + cw*4    ] = __floats2bfloat162_rn(rw[i].x, rw[i].y);
                *(__nv_bfloat162*)&Ws[nxt][rr*WPAD + cw*4 + 2] = __floats2bfloat162_rn(rw[i].z, rw[i].w);
            }
        }
        __syncthreads();
    }

    // ---- epilogue ----
    #pragma unroll
    for (int i = 0; i < 4; i++) {
        int mb = m0 + wm*64 + i*16 + (lane >> 2);
        #pragma unroll
        for (int j = 0; j < 4; j++) {
            int nb = n0 + wn*32 + j*8 + (lane & 3)*2;
            float b0 = bias[nb], b1 = bias[nb+1];
            #pragma unroll
            for (int half = 0; half < 2; half++) {
                int m = mb + half*8;
                float v0 = acc[i][j][half*2]   + b0;
                float v1 = acc[i][j][half*2+1] + b1;
                if (MODE == 1) {
                    float x3 = v0*v0*v0;
                    v0 = 0.5f*v0*(1.0f + tanhf(0.7978845608028654f*(v0 + 0.044715f*x3)));
                    x3 = v1*v1*v1;
                    v1 = 0.5f*v1*(1.0f + tanhf(0.7978845608028654f*(v1 + 0.044715f*x3)));
                } else if (MODE == 2) {
                    float2 r2 = *(const float2*)(res + (size_t)m*N + nb);
                    v0 += r2.x; v1 += r2.y;
                }
                if (MODE == 1 || MODE == 3) {
                    *(__nv_bfloat162*)((__nv_bfloat16*)Cout + (size_t)m*N + nb) =
                        __floats2bfloat162_rn(v0, v1);
                } else {
                    float2 o; o.x = v0; o.y = v1;
                    *(float2*)((float*)Cout + (size_t)m*N + nb) = o;
                }
            }
        }
    }
}

__global__ __launch_bounds__(256) void gemm_gelu_kernel(
    const float* __restrict__ A, const float* __restrict__ W,
    const float* __restrict__ bias, __nv_bfloat16* __restrict__ C, int N, int K)
{
    gemm_core<float,1>(A, W, bias, nullptr, C, N, K, blockIdx.y*128, blockIdx.x*128);
}
__global__ __launch_bounds__(256) void gemm_res_f32A_kernel(
    const float* __restrict__ A, const float* __restrict__ W,
    const float* __restrict__ bias, const float* __restrict__ res,
    float* __restrict__ C, int N, int K)
{
    gemm_core<float,2>(A, W, bias, res, C, N, K, blockIdx.y*128, blockIdx.x*128);
}
__global__ __launch_bounds__(256) void gemm_res_bf16A_kernel(
    const __nv_bfloat16* __restrict__ A, const float* __restrict__ W,
    const float* __restrict__ bias, const float* __restrict__ res,
    float* __restrict__ C, int N, int K)
{
    gemm_core<__nv_bfloat16,2>(A, W, bias, res, C, N, K, blockIdx.y*128, blockIdx.x*128);
}
__global__ __launch_bounds__(256) void mma_qkv_kernel(
    const float* __restrict__ A,
    const float* __restrict__ Wq, const float* __restrict__ Wk, const float* __restrict__ Wv,
    const float* __restrict__ bq, const float* __restrict__ bk, const float* __restrict__ bv,
    __nv_bfloat16* __restrict__ q, __nv_bfloat16* __restrict__ k, __nv_bfloat16* __restrict__ v)
{
    int z = blockIdx.z;
    const float* W  = (z == 0) ? Wq : (z == 1) ? Wk : Wv;
    const float* bb = (z == 0) ? bq : (z == 1) ? bk : bv;
    __nv_bfloat16* C = (z == 0) ? q : (z == 1) ? k : v;
    gemm_core<float,3>(A, W, bb, nullptr, C, Hsz, Hsz, blockIdx.y*128, blockIdx.x*128);
}

// ================= flash attention =================
// grid (Ssz/64, B*NH), 128 threads (4 warps). Each warp owns 16 Q rows.
#define FPAD 72   // 64 + 8 bf16 pad

__global__ __launch_bounds__(128) void flash_attn_kernel(
    const __nv_bfloat16* __restrict__ q, const __nv_bfloat16* __restrict__ k,
    const __nv_bfloat16* __restrict__ v, const int* __restrict__ mask,
    __nv_bfloat16* __restrict__ ctx)
{
    __shared__ __nv_bfloat16 Qs[64*FPAD];
    __shared__ __nv_bfloat16 Ks[64*FPAD];
    __shared__ __nv_bfloat16 Vs[64*FPAD];
    __shared__ float s_bias[Ssz];

    int bh = blockIdx.y;
    int b = bh / NHsz, h = bh % NHsz;
    int i0 = blockIdx.x * 64;
    int tid = threadIdx.x;
    int warp = tid >> 5, lane = tid & 31;
    int g = lane >> 2, t4 = lane & 3;

    // bias from mask
    #pragma unroll
    for (int it = 0; it < 4; it++) {
        int j = tid + it*128;
        s_bias[j] = mask[b*Ssz + j] ? 0.f : -1e9f;
    }
    // load Q tile
    #pragma unroll
    for (int it = 0; it < 4; it++) {
        int idx = tid + it*128;
        int r = idx >> 3, c8 = idx & 7;
        *(uint4*)&Qs[r*FPAD + c8*8] =
            *(const uint4*)(q + (size_t)(b*Ssz + i0 + r)*Hsz + h*DHsz + c8*8);
    }
    __syncthreads();

    // Q fragments (held in registers for the whole loop)
    uint32_t qf[4][4];
    #pragma unroll
    for (int ks = 0; ks < 4; ks++) {
        int r = warp*16 + (lane & 15);
        int c = ks*16 + (lane >> 4)*8;
        ldsm_x4(qf[ks], (uint32_t)__cvta_generic_to_shared(&Qs[r*FPAD + c]));
    }

    float oacc[8][4];
    #pragma unroll
    for (int n = 0; n < 8; n++)
        #pragma unroll
        for (int e = 0; e < 4; e++) oacc[n][e] = 0.f;
    float m0v = -1e30f, m1v = -1e30f, l0 = 0.f, l1 = 0.f;

    for (int j0 = 0; j0 < Ssz; j0 += 64) {
        __syncthreads();
        // load K, V tiles
        #pragma unroll
        for (int it = 0; it < 4; it++) {
            int idx = tid + it*128;
            int r = idx >> 3, c8 = idx & 7;
            size_t goff = (size_t)(b*Ssz + j0 + r)*Hsz + h*DHsz + c8*8;
            *(uint4*)&Ks[r*FPAD + c8*8] = *(const uint4*)(k + goff);
            *(uint4*)&Vs[r*FPAD + c8*8] = *(const uint4*)(v + goff);
        }
        __syncthreads();

        // S = Q @ K^T  (16x64 per warp)
        float acc[8][4];
        #pragma unroll
        for (int n = 0; n < 8; n++)
            #pragma unroll
            for (int e = 0; e < 4; e++) acc[n][e] = 0.f;
        #pragma unroll
        for (int jj = 0; jj < 4; jj++) {
            #pragma unroll
            for (int ks = 0; ks < 4; ks++) {
                uint32_t bf[4];
                int r = jj*16 + (lane & 15);
                int c = ks*16 + (lane >> 4)*8;
                ldsm_x4(bf, (uint32_t)__cvta_generic_to_shared(&Ks[r*FPAD + c]));
                mma16816(acc[jj*2  ], qf[ks], bf[0], bf[2]);
                mma16816(acc[jj*2+1], qf[ks], bf[1], bf[3]);
            }
        }

        // scale + bias, online softmax
        float p[8][4];
        float mx0 = -1e30f, mx1 = -1e30f;
        #pragma unroll
        for (int n = 0; n < 8; n++) {
            float b0 = s_bias[j0 + n*8 + t4*2];
            float b1 = s_bias[j0 + n*8 + t4*2 + 1];
            p[n][0] = acc[n][0]*0.125f + b0;
            p[n][1] = acc[n][1]*0.125f + b1;
            p[n][2] = acc[n][2]*0.125f + b0;
            p[n][3] = acc[n][3]*0.125f + b1;
            mx0 = fmaxf(mx0, fmaxf(p[n][0], p[n][1]));
            mx1 = fmaxf(mx1, fmaxf(p[n][2], p[n][3]));
        }
        mx0 = fmaxf(mx0, __shfl_xor_sync(0xffffffffu, mx0, 1));
        mx0 = fmaxf(mx0, __shfl_xor_sync(0xffffffffu, mx0, 2));
        mx1 = fmaxf(mx1, __shfl_xor_sync(0xffffffffu, mx1, 1));
        mx1 = fmaxf(mx1, __shfl_xor_sync(0xffffffffu, mx1, 2));
        float mn0 = fmaxf(m0v, mx0);
        float mn1 = fmaxf(m1v, mx1);
        float lt0 = 0.f, lt1 = 0.f;
        #pragma unroll
        for (int n = 0; n < 8; n++) {
            p[n][0] = __expf(p[n][0] - mn0);
            p[n][1] = __expf(p[n][1] - mn0);
            p[n][2] = __expf(p[n][2] - mn1);
            p[n][3] = __expf(p[n][3] - mn1);
            lt0 += p[n][0] + p[n][1];
            lt1 += p[n][2] + p[n][3];
        }
        lt0 += __shfl_xor_sync(0xffffffffu, lt0, 1);
        lt0 += __shfl_xor_sync(0xffffffffu, lt0, 2);
        lt1 += __shfl_xor_sync(0xffffffffu, lt1, 1);
        lt1 += __shfl_xor_sync(0xffffffffu, lt1, 2);
        float sc0 = __expf(m0v - mn0);
        float sc1 = __expf(m1v - mn1);
        l0 = l0*sc0 + lt0;
        l1 = l1*sc1 + lt1;
        m0v = mn0; m1v = mn1;
        #pragma unroll
        for (int n = 0; n < 8; n++) {
            oacc[n][0] *= sc0; oacc[n][1] *= sc0;
            oacc[n][2] *= sc1; oacc[n][3] *= sc1;
        }

        // P fragments (A-operand of PV mma)
        uint32_t pa[4][4];
        #pragma unroll
        for (int c = 0; c < 4; c++) {
            pa[c][0] = pack_bf16(p[2*c  ][0], p[2*c  ][1]);
            pa[c][1] = pack_bf16(p[2*c  ][2], p[2*c  ][3]);
            pa[c][2] = pack_bf16(p[2*c+1][0], p[2*c+1][1]);
            pa[c][3] = pack_bf16(p[2*c+1][2], p[2*c+1][3]);
        }

        // O += P @ V
        #pragma unroll
        for (int db = 0; db < 4; db++) {
            #pragma unroll
            for (int c = 0; c < 4; c++) {
                uint32_t vf[4];
                int kk = c*16 + ((lane>>3)&1)*8 + (lane&7);
                int nn = db*16 + (lane>>4)*8;
                ldsm_x4_t(vf, (uint32_t)__cvta_generic_to_shared(&Vs[kk*FPAD + nn]));
                mma16816(oacc[db*2  ], pa[c], vf[0], vf[1]);
                mma16816(oacc[db*2+1], pa[c], vf[2], vf[3]);
            }
        }
    }

    // write ctx (bf16), normalized
    float inv0 = 1.0f / l0, inv1 = 1.0f / l1;
    #pragma unroll
    for (int n = 0; n < 8; n++) {
        int d = n*8 + t4*2;
        int r0 = i0 + warp*16 + g;
        *(__nv_bfloat162*)(ctx + (size_t)(b*Ssz + r0)*Hsz + h*DHsz + d) =
            __floats2bfloat162_rn(oacc[n][0]*inv0, oacc[n][1]*inv0);
        *(__nv_bfloat162*)(ctx + (size_t)(b*Ssz + r0 + 8)*Hsz + h*DHsz + d) =
            __floats2bfloat162_rn(oacc[n][2]*inv1, oacc[n][3]*inv1);
    }
}

// ---------------- classifier (N=19, SIMT) ----------------
__global__ void sgemm_kernel(const float* __restrict__ A, const float* __restrict__ W,
                             const float* __restrict__ bias, float* __restrict__ C,
                             int M, int N, int K)
{
    __shared__ float As[64][17];
    __shared__ float Ws[16][64];
    int m0 = blockIdx.y * 64;
    int n0 = blockIdx.x * 64;
    int tid = threadIdx.x;
    int ty = tid >> 4, tx = tid & 15;
    float acc[4][4] = {};
    for (int k0 = 0; k0 < K; k0 += 16) {
        #pragma unroll
        for (int i = 0; i < 4; i++) {
            int idx = tid + i*256;
            int r = idx >> 4, c = idx & 15;
            As[r][c] = A[(size_t)(m0+r)*K + (k0+c)];
        }
        #pragma unroll
        for (int i = 0; i < 4; i++) {
            int idx = tid + i*256;
            int r = idx >> 6, c = idx & 63;
            int n = n0 + c;
            Ws[r][c] = (n < N) ? W[(size_t)(k0+r)*N + n] : 0.f;
        }
        __syncthreads();
        #pragma unroll
        for (int kk = 0; kk < 16; kk++) {
            float a[4], b[4];
            #pragma unroll
            for (int i = 0; i < 4; i++) a[i] = As[ty*4+i][kk];
            #pragma unroll
            for (int j = 0; j < 4; j++) b[j] = Ws[kk][tx*4+j];
            #pragma unroll
            for (int i = 0; i < 4; i++)
                #pragma unroll
                for (int j = 0; j < 4; j++)
                    acc[i][j] = fmaf(a[i], b[j], acc[i][j]);
        }
        __syncthreads();
    }
    #pragma unroll
    for (int i = 0; i < 4; i++) {
        int m = m0 + ty*4 + i;
        #pragma unroll
        for (int j = 0; j < 4; j++) {
            int n = n0 + tx*4 + j;
            if (n < N) C[(size_t)m*N + n] = acc[i][j] + bias[n];
        }
    }
}

// ---------------- CRF ----------------
__global__ void crf_kernel(const float* __restrict__ lg, const int* __restrict__ labels,
                           const int* __restrict__ mask, const float* __restrict__ st,
                           const float* __restrict__ en, const float* __restrict__ tr,
                           float* __restrict__ out)
{
    __shared__ float s_tr[NLsz*NLsz];
    __shared__ float s_res[Bsz];
    for (int i = threadIdx.x; i < NLsz*NLsz; i += blockDim.x) s_tr[i] = tr[i];
    __syncthreads();
    int warp = threadIdx.x >> 5, lane = threadIdx.x & 31;
    if (warp < Bsz) {
        int b = warp;
        const int* lab = labels + b*Ssz;
        const int* mk  = mask + b*Ssz;
        const float* lgb = lg + (size_t)b*Ssz*NLsz;
        float part = 0.f; int cnt = 0;
        for (int t = lane; t < Ssz; t += 32) {
            cnt += mk[t];
            if (t >= 1) {
                float mf = (float)mk[t];
                part += (s_tr[lab[t-1]*NLsz + lab[t]] + lgb[t*NLsz + lab[t]]) * mf;
            }
        }
        for (int o = 16; o; o >>= 1) {
            part += __shfl_xor_sync(0xffffffffu, part, o);
            cnt  += __shfl_xor_sync(0xffffffffu, cnt, o);
        }
        float num = 0.f;
        if (lane == 0) {
            int l0 = lab[0];
            num = st[l0] + lgb[l0] + part + en[lab[cnt-1]];
        }
        int j = lane;
        float alpha = (j < NLsz) ? st[j] + lgb[j] : -1e30f;
        for (int t = 1; t < Ssz; t++) {
            float g[NLsz];
            #pragma unroll
            for (int i = 0; i < NLsz; i++)
                g[i] = __shfl_sync(0xffffffffu, alpha, i) + ((j < NLsz) ? s_tr[i*NLsz + j] : 0.f);
            float mv = g[0];
            #pragma unroll
            for (int i = 1; i < NLsz; i++) mv = fmaxf(mv, g[i]);
            float sum = 0.f;
            #pragma unroll
            for (int i = 0; i < NLsz; i++) sum += expf(g[i] - mv);
            float nxt = mv + logf(sum) + ((j < NLsz) ? lgb[t*NLsz + j] : 0.f);
            if (mk[t] > 0 && j < NLsz) alpha = nxt;
        }
        float v = (j < NLsz) ? alpha + en[j] : -1e30f;
        float mv = v;
        for (int o = 16; o; o >>= 1) mv = fmaxf(mv, __shfl_xor_sync(0xffffffffu, mv, o));
        float s = (j < NLsz) ? expf(v - mv) : 0.f;
        for (int o = 16; o; o >>= 1) s += __shfl_xor_sync(0xffffffffu, s, o);
        if (lane == 0) s_res[b] = (mv + logf(s)) - num;
    }
    __syncthreads();
    if (threadIdx.x == 0) {
        float tot = 0.f;
        for (int b = 0; b < Bsz; b++) tot += s_res[b];
        out[0] = tot;
    }
}

// ---------------- host ----------------
extern "C" void kernel_launch(void* const* d_in, const int* in_sizes, int n_in,
                              void* d_out, int out_size)
{
    const int*   input_ids = (const int*)  d_in[0];
    const int*   attn_mask = (const int*)  d_in[1];
    const int*   labels    = (const int*)  d_in[2];
    const float* token_emb = (const float*)d_in[3];
    const float* pos_emb   = (const float*)d_in[4];
    const float* ln_emb_s  = (const float*)d_in[5];
    const float* ln_emb_b  = (const float*)d_in[6];
    const float* Wq        = (const float*)d_in[7];
    const float* bq        = (const float*)d_in[8];
    const float* Wk        = (const float*)d_in[9];
    const float* bk        = (const float*)d_in[10];
    const float* Wv        = (const float*)d_in[11];
    const float* bv        = (const float*)d_in[12];
    const float* Wo        = (const float*)d_in[13];
    const float* bo        = (const float*)d_in[14];
    const float* ln1_s     = (const float*)d_in[15];
    const float* ln1_b     = (const float*)d_in[16];
    const float* W1        = (const float*)d_in[17];
    const float* b1        = (const float*)d_in[18];
    const float* W2        = (const float*)d_in[19];
    const float* b2        = (const float*)d_in[20];
    const float* ln2_s     = (const float*)d_in[21];
    const float* ln2_b     = (const float*)d_in[22];
    const float* cls_W     = (const float*)d_in[23];
    const float* cls_b     = (const float*)d_in[24];
    const float* start_tr  = (const float*)d_in[25];
    const float* end_tr    = (const float*)d_in[26];
    const float* trans     = (const float*)d_in[27];

    float *x, *t, *lg;
    __nv_bfloat16 *qb, *kb, *vb, *cb, *hb;
    { void* p; cudaGetSymbolAddress(&p, g_x);  x  = (float*)p; }
    { void* p; cudaGetSymbolAddress(&p, g_t);  t  = (float*)p; }
    { void* p; cudaGetSymbolAddress(&p, g_lg); lg = (float*)p; }
    { void* p; cudaGetSymbolAddress(&p, g_qb); qb = (__nv_bfloat16*)p; }
    { void* p; cudaGetSymbolAddress(&p, g_kb); kb = (__nv_bfloat16*)p; }
    { void* p; cudaGetSymbolAddress(&p, g_vb); vb = (__nv_bfloat16*)p; }
    { void* p; cudaGetSymbolAddress(&p, g_cb); cb = (__nv_bfloat16*)p; }
    { void* p; cudaGetSymbolAddress(&p, g_hb); hb = (__nv_bfloat16*)p; }

    embed_kernel<<<Tsz, 256>>>(input_ids, token_emb, pos_emb, t);
    ln_kernel<<<Tsz, 256>>>(t, ln_emb_s, ln_emb_b, x);

    for (int l = 0; l < Lsz; l++) {
        const float* wq = Wq + (size_t)l*Hsz*Hsz;
        const float* wk = Wk + (size_t)l*Hsz*Hsz;
        const float* wv = Wv + (size_t)l*Hsz*Hsz;
        const float* wo = Wo + (size_t)l*Hsz*Hsz;

        mma_qkv_kernel<<<dim3(Hsz/128, Tsz/128, 3), 256>>>(
            x, wq, wk, wv, bq + l*Hsz, bk + l*Hsz, bv + l*Hsz, qb, kb, vb);

        flash_attn_kernel<<<dim3(Ssz/64, Bsz*NHsz), 128>>>(qb, kb, vb, attn_mask, cb);

        gemm_res_bf16A_kernel<<<dim3(Hsz/128, Tsz/128), 256>>>(cb, wo, bo + l*Hsz, x, t, Hsz, Hsz);
        ln_kernel<<<Tsz, 256>>>(t, ln1_s + l*Hsz, ln1_b + l*Hsz, x);

        gemm_gelu_kernel<<<dim3(DFFsz/128, Tsz/128), 256>>>(
            x, W1 + (size_t)l*Hsz*DFFsz, b1 + l*DFFsz, hb, DFFsz, Hsz);
        gemm_res_bf16A_kernel<<<dim3(Hsz/128, Tsz/128), 256>>>(
            hb, W2 + (size_t)l*DFFsz*Hsz, b2 + l*Hsz, x, t, Hsz, DFFsz);
        ln_kernel<<<Tsz, 256>>>(t, ln2_s + l*Hsz, ln2_b + l*Hsz, x);
    }

    sgemm_kernel<<<dim3(1, Tsz/64), 256>>>(x, cls_W, cls_b, lg, Tsz, NLsz, Hsz);
    crf_kernel<<<1, 256>>>(lg, labels, attn_mask, start_tr, end_tr, trans, (float*)d_out);
}

// round 14
// speedup vs baseline: 6.4309x; 1.0904x over previous
#include <cuda_runtime.h>
#include <cuda_bf16.h>
#include <math.h>
#include <stdint.h>

#define Bsz  8
#define Ssz  512
#define Hsz  768
#define Lsz  12
#define NHsz 12
#define DHsz 64
#define DFFsz 3072
#define NLsz 19
#define Tsz  (Bsz*Ssz)   // 4096 tokens

// ---------------- scratch ----------------
__device__ float          g_x [Tsz*Hsz];
__device__ float          g_t [Tsz*Hsz];
__device__ __nv_bfloat16  g_xb[Tsz*Hsz];
__device__ __nv_bfloat16  g_qb[Tsz*Hsz];
__device__ __nv_bfloat16  g_kb[Tsz*Hsz];
__device__ __nv_bfloat16  g_vb[Tsz*Hsz];
__device__ __nv_bfloat16  g_cb[Tsz*Hsz];
__device__ __nv_bfloat16  g_hb[Tsz*DFFsz];
__device__ float          g_lg[Tsz*NLsz];
// bf16 weights (pre-converted each launch)
__device__ __nv_bfloat16  g_wq[Lsz*Hsz*Hsz];
__device__ __nv_bfloat16  g_wk[Lsz*Hsz*Hsz];
__device__ __nv_bfloat16  g_wv[Lsz*Hsz*Hsz];
__device__ __nv_bfloat16  g_wo[Lsz*Hsz*Hsz];
__device__ __nv_bfloat16  g_w1[Lsz*Hsz*DFFsz];
__device__ __nv_bfloat16  g_w2[Lsz*DFFsz*Hsz];

// ---------------- fp32 -> bf16 convert ----------------
__global__ void cvt_bf16_kernel(const float* __restrict__ in,
                                __nv_bfloat16* __restrict__ out, int n4)
{
    int i = blockIdx.x*blockDim.x + threadIdx.x;
    if (i < n4) {
        float4 f = ((const float4*)in)[i];
        __nv_bfloat162 a = __floats2bfloat162_rn(f.x, f.y);
        __nv_bfloat162 b = __floats2bfloat162_rn(f.z, f.w);
        uint2 o; o.x = *(uint32_t*)&a; o.y = *(uint32_t*)&b;
        ((uint2*)out)[i] = o;
    }
}

// ---------------- embedding ----------------
__global__ void embed_kernel(const int* __restrict__ ids,
                             const float* __restrict__ tok,
                             const float* __restrict__ pos,
                             float* __restrict__ out)
{
    int t = blockIdx.x;
    int s = t & (Ssz-1);
    int id = ids[t];
    const float* tp = tok + (size_t)id*Hsz;
    const float* pp = pos + (size_t)s*Hsz;
    float* op = out + (size_t)t*Hsz;
    for (int c = threadIdx.x; c < Hsz; c += blockDim.x)
        op[c] = tp[c] + pp[c];
}

// ---------------- layernorm (writes fp32 + bf16) ----------------
__global__ void ln_kernel(const float* __restrict__ in,
                          const float* __restrict__ gamma,
                          const float* __restrict__ beta,
                          float* __restrict__ out,
                          __nv_bfloat16* __restrict__ outb)
{
    __shared__ float sh[32];
    int row = blockIdx.x;
    int tid = threadIdx.x;
    const float* p = in + (size_t)row*Hsz;
    float v0 = p[tid], v1 = p[tid+256], v2 = p[tid+512];
    float s = v0+v1+v2;
    int lane = tid & 31, w = tid >> 5;
    for (int o = 16; o; o >>= 1) s += __shfl_xor_sync(0xffffffffu, s, o);
    if (!lane) sh[w] = s;
    __syncthreads();
    if (w == 0) {
        s = (lane < 8) ? sh[lane] : 0.f;
        for (int o = 4; o; o >>= 1) s += __shfl_xor_sync(0xffffffffu, s, o);
        if (!lane) sh[0] = s;
    }
    __syncthreads();
    float mean = sh[0] * (1.0f/Hsz);
    __syncthreads();
    float d0 = v0-mean, d1 = v1-mean, d2 = v2-mean;
    float q = d0*d0 + d1*d1 + d2*d2;
    for (int o = 16; o; o >>= 1) q += __shfl_xor_sync(0xffffffffu, q, o);
    if (!lane) sh[w] = q;
    __syncthreads();
    if (w == 0) {
        q = (lane < 8) ? sh[lane] : 0.f;
        for (int o = 4; o; o >>= 1) q += __shfl_xor_sync(0xffffffffu, q, o);
        if (!lane) sh[0] = q;
    }
    __syncthreads();
    float var = sh[0] * (1.0f/Hsz);
    float inv = rsqrtf(var + 1e-12f);
    float* op = out + (size_t)row*Hsz;
    __nv_bfloat16* ob = outb + (size_t)row*Hsz;
    float r0 = d0*inv*gamma[tid    ] + beta[tid    ];
    float r1 = d1*inv*gamma[tid+256] + beta[tid+256];
    float r2 = d2*inv*gamma[tid+512] + beta[tid+512];
    op[tid] = r0; op[tid+256] = r1; op[tid+512] = r2;
    ob[tid] = __float2bfloat16(r0);
    ob[tid+256] = __float2bfloat16(r1);
    ob[tid+512] = __float2bfloat16(r2);
}

// ================= MMA / async primitives =================
__device__ __forceinline__ void ldsm_x4(uint32_t (&r)[4], uint32_t addr) {
    asm volatile("ldmatrix.sync.aligned.m8n8.x4.shared.b16 {%0,%1,%2,%3}, [%4];"
        : "=r"(r[0]),"=r"(r[1]),"=r"(r[2]),"=r"(r[3]) : "r"(addr));
}
__device__ __forceinline__ void ldsm_x4_t(uint32_t (&r)[4], uint32_t addr) {
    asm volatile("ldmatrix.sync.aligned.m8n8.x4.trans.shared.b16 {%0,%1,%2,%3}, [%4];"
        : "=r"(r[0]),"=r"(r[1]),"=r"(r[2]),"=r"(r[3]) : "r"(addr));
}
__device__ __forceinline__ void mma16816(float (&c)[4], const uint32_t (&a)[4],
                                         uint32_t b0, uint32_t b1) {
    asm volatile("mma.sync.aligned.m16n8k16.row.col.f32.bf16.bf16.f32 "
        "{%0,%1,%2,%3}, {%4,%5,%6,%7}, {%8,%9}, {%0,%1,%2,%3};"
        : "+f"(c[0]),"+f"(c[1]),"+f"(c[2]),"+f"(c[3])
        : "r"(a[0]),"r"(a[1]),"r"(a[2]),"r"(a[3]), "r"(b0),"r"(b1));
}
__device__ __forceinline__ uint32_t pack_bf16(float x, float y) {
    __nv_bfloat162 h = __floats2bfloat162_rn(x, y);
    return *(uint32_t*)&h;
}
__device__ __forceinline__ void cp16(uint32_t smem, const void* g) {
    asm volatile("cp.async.cg.shared.global [%0], [%1], 16;" :: "r"(smem), "l"(g));
}
__device__ __forceinline__ void cp_commit() {
    asm volatile("cp.async.commit_group;");
}
__device__ __forceinline__ void cp_wait1() {
    asm volatile("cp.async.wait_group 1;");
}
__device__ __forceinline__ void cp_wait0() {
    asm volatile("cp.async.wait_group 0;");
}
__device__ __forceinline__ float fast_gelu(float v) {
    float z = 0.7978845608028654f*(v + 0.044715f*v*v*v);
    float t; asm("tanh.approx.f32 %0, %1;" : "=f"(t) : "f"(z));
    return 0.5f*v*(1.0f + t);
}

// ================= bf16 GEMM, cp.async pipelined =================
// C = A[M,K](bf16) @ W[K,N](bf16) + bias; MODE: 1=gelu->bf16, 2=residual->fp32, 3=bias->bf16
#define APAD 40   // 80B row stride (16B aligned)
#define WPAD 136  // 272B row stride (16B aligned)

template<int MODE>
__device__ __forceinline__ void gemm_core(
    const __nv_bfloat16* __restrict__ A, const __nv_bfloat16* __restrict__ W,
    const float* __restrict__ bias, const float* __restrict__ res,
    void* __restrict__ Cout, int N, int K, int m0, int n0)
{
    __shared__ __nv_bfloat16 As[2][128*APAD];
    __shared__ __nv_bfloat16 Ws[2][32*WPAD];
    int tid = threadIdx.x;
    int warp = tid >> 5, lane = tid & 31;
    int wm = warp >> 2;
    int wn = warp & 3;
    uint32_t as_base = (uint32_t)__cvta_generic_to_shared(&As[0][0]);
    uint32_t ws_base = (uint32_t)__cvta_generic_to_shared(&Ws[0][0]);

    float acc[4][4][4];
    #pragma unroll
    for (int i = 0; i < 4; i++)
        #pragma unroll
        for (int j = 0; j < 4; j++)
            #pragma unroll
            for (int e = 0; e < 4; e++) acc[i][j][e] = 0.f;

    const int KT = K >> 5;

    // stage-0 loads
    {
        #pragma unroll
        for (int i = 0; i < 2; i++) {
            int idx = tid + i*256;
            int r = idx >> 2, c8 = idx & 3;
            cp16(as_base + (r*APAD + c8*8)*2, A + (size_t)(m0 + r)*K + c8*8);
        }
        #pragma unroll
        for (int i = 0; i < 2; i++) {
            int idx = tid + i*256;
            int r = idx >> 4, c8 = idx & 15;
            cp16(ws_base + (r*WPAD + c8*8)*2, W + (size_t)r*N + n0 + c8*8);
        }
        cp_commit();
    }

    for (int kt = 0; kt < KT; kt++) {
        int cur = kt & 1;
        if (kt + 1 < KT) {
            int k0 = (kt+1) << 5;
            int st = cur ^ 1;
            #pragma unroll
            for (int i = 0; i < 2; i++) {
                int idx = tid + i*256;
                int r = idx >> 2, c8 = idx & 3;
                cp16(as_base + (st*128*APAD + r*APAD + c8*8)*2,
                     A + (size_t)(m0 + r)*K + k0 + c8*8);
            }
            #pragma unroll
            for (int i = 0; i < 2; i++) {
                int idx = tid + i*256;
                int r = idx >> 4, c8 = idx & 15;
                cp16(ws_base + (st*32*WPAD + r*WPAD + c8*8)*2,
                     W + (size_t)(k0 + r)*N + n0 + c8*8);
            }
            cp_commit();
            cp_wait1();
        } else {
            cp_wait0();
        }
        __syncthreads();

        #pragma unroll
        for (int ks = 0; ks < 2; ks++) {
            uint32_t af[4][4];
            #pragma unroll
            for (int i = 0; i < 4; i++) {
                int r = wm*64 + i*16 + (lane & 15);
                int c = ks*16 + (lane >> 4)*8;
                uint32_t addr = (uint32_t)__cvta_generic_to_shared(&As[cur][r*APAD + c]);
                ldsm_x4(af[i], addr);
            }
            uint32_t bf[2][4];
            #pragma unroll
            for (int j2 = 0; j2 < 2; j2++) {
                int kk = ks*16 + ((lane>>3)&1)*8 + (lane&7);
                int nn = wn*32 + j2*16 + (lane>>4)*8;
                uint32_t addr = (uint32_t)__cvta_generic_to_shared(&Ws[cur][kk*WPAD + nn]);
                ldsm_x4_t(bf[j2], addr);
            }
            #pragma unroll
            for (int i = 0; i < 4; i++)
                #pragma unroll
                for (int j = 0; j < 4; j++)
                    mma16816(acc[i][j], af[i], bf[j>>1][(j&1)*2], bf[j>>1][(j&1)*2+1]);
        }
        __syncthreads();
    }

    // epilogue
    #pragma unroll
    for (int i = 0; i < 4; i++) {
        int mb = m0 + wm*64 + i*16 + (lane >> 2);
        #pragma unroll
        for (int j = 0; j < 4; j++) {
            int nb = n0 + wn*32 + j*8 + (lane & 3)*2;
            float b0 = bias[nb], b1 = bias[nb+1];
            #pragma unroll
            for (int half = 0; half < 2; half++) {
                int m = mb + half*8;
                float v0 = acc[i][j][half*2]   + b0;
                float v1 = acc[i][j][half*2+1] + b1;
                if (MODE == 1) {
                    v0 = fast_gelu(v0);
                    v1 = fast_gelu(v1);
                } else if (MODE == 2) {
                    float2 r2 = *(const float2*)(res + (size_t)m*N + nb);
                    v0 += r2.x; v1 += r2.y;
                }
                if (MODE == 1 || MODE == 3) {
                    *(__nv_bfloat162*)((__nv_bfloat16*)Cout + (size_t)m*N + nb) =
                        __floats2bfloat162_rn(v0, v1);
                } else {
                    float2 o; o.x = v0; o.y = v1;
                    *(float2*)((float*)Cout + (size_t)m*N + nb) = o;
                }
            }
        }
    }
}

__global__ __launch_bounds__(256) void gemm_gelu_kernel(
    const __nv_bfloat16* __restrict__ A, const __nv_bfloat16* __restrict__ W,
    const float* __restrict__ bias, __nv_bfloat16* __restrict__ C, int N, int K)
{
    gemm_core<1>(A, W, bias, nullptr, C, N, K, blockIdx.y*128, blockIdx.x*128);
}
__global__ __launch_bounds__(256) void gemm_res_kernel(
    const __nv_bfloat16* __restrict__ A, const __nv_bfloat16* __restrict__ W,
    const float* __restrict__ bias, const float* __restrict__ res,
    float* __restrict__ C, int N, int K)
{
    gemm_core<2>(A, W, bias, res, C, N, K, blockIdx.y*128, blockIdx.x*128);
}
__global__ __launch_bounds__(256) void mma_qkv_kernel(
    const __nv_bfloat16* __restrict__ A,
    const __nv_bfloat16* __restrict__ Wq, const __nv_bfloat16* __restrict__ Wk,
    const __nv_bfloat16* __restrict__ Wv,
    const float* __restrict__ bq, const float* __restrict__ bk, const float* __restrict__ bv,
    __nv_bfloat16* __restrict__ q, __nv_bfloat16* __restrict__ k, __nv_bfloat16* __restrict__ v)
{
    int z = blockIdx.z;
    const __nv_bfloat16* W = (z == 0) ? Wq : (z == 1) ? Wk : Wv;
    const float* bb = (z == 0) ? bq : (z == 1) ? bk : bv;
    __nv_bfloat16* C = (z == 0) ? q : (z == 1) ? k : v;
    gemm_core<3>(A, W, bb, nullptr, C, Hsz, Hsz, blockIdx.y*128, blockIdx.x*128);
}

// ================= flash attention (cp.async double-buffered KV) =================
#define FPAD 72   // 144B row stride (16B aligned)

__global__ __launch_bounds__(128) void flash_attn_kernel(
    const __nv_bfloat16* __restrict__ q, const __nv_bfloat16* __restrict__ k,
    const __nv_bfloat16* __restrict__ v, const int* __restrict__ mask,
    __nv_bfloat16* __restrict__ ctx)
{
    __shared__ __nv_bfloat16 Qs[64*FPAD];
    __shared__ __nv_bfloat16 Ks[2][64*FPAD];
    __shared__ __nv_bfloat16 Vs[2][64*FPAD];
    __shared__ float s_bias[Ssz];

    int bh = blockIdx.y;
    int b = bh / NHsz, h = bh % NHsz;
    int i0 = blockIdx.x * 64;
    int tid = threadIdx.x;
    int warp = tid >> 5, lane = tid & 31;
    int g = lane >> 2, t4 = lane & 3;
    uint32_t ks_base = (uint32_t)__cvta_generic_to_shared(&Ks[0][0]);
    uint32_t vs_base = (uint32_t)__cvta_generic_to_shared(&Vs[0][0]);

    #pragma unroll
    for (int it = 0; it < 4; it++) {
        int j = tid + it*128;
        s_bias[j] = mask[b*Ssz + j] ? 0.f : -1e9f;
    }
    #pragma unroll
    for (int it = 0; it < 4; it++) {
        int idx = tid + it*128;
        int r = idx >> 3, c8 = idx & 7;
        *(uint4*)&Qs[r*FPAD + c8*8] =
            *(const uint4*)(q + (size_t)(b*Ssz + i0 + r)*Hsz + h*DHsz + c8*8);
    }
    __syncthreads();

    uint32_t qf[4][4];
    #pragma unroll
    for (int ks = 0; ks < 4; ks++) {
        int r = warp*16 + (lane & 15);
        int c = ks*16 + (lane >> 4)*8;
        ldsm_x4(qf[ks], (uint32_t)__cvta_generic_to_shared(&Qs[r*FPAD + c]));
    }

    // stage-0 KV loads
    #pragma unroll
    for (int it = 0; it < 4; it++) {
        int idx = tid + it*128;
        int r = idx >> 3, c8 = idx & 7;
        size_t goff = (size_t)(b*Ssz + r)*Hsz + h*DHsz + c8*8;
        cp16(ks_base + (r*FPAD + c8*8)*2, k + goff);
        cp16(vs_base + (r*FPAD + c8*8)*2, v + goff);
    }
    cp_commit();

    float oacc[8][4];
    #pragma unroll
    for (int n = 0; n < 8; n++)
        #pragma unroll
        for (int e = 0; e < 4; e++) oacc[n][e] = 0.f;
    float m0v = -1e30f, m1v = -1e30f, l0 = 0.f, l1 = 0.f;

    const int NT = Ssz/64;
    for (int jt = 0; jt < NT; jt++) {
        int cur = jt & 1;
        int j0 = jt*64;
        if (jt + 1 < NT) {
            int st = cur ^ 1;
            int j0n = j0 + 64;
            #pragma unroll
            for (int it = 0; it < 4; it++) {
                int idx = tid + it*128;
                int r = idx >> 3, c8 = idx & 7;
                size_t goff = (size_t)(b*Ssz + j0n + r)*Hsz + h*DHsz + c8*8;
                cp16(ks_base + (st*64*FPAD + r*FPAD + c8*8)*2, k + goff);
                cp16(vs_base + (st*64*FPAD + r*FPAD + c8*8)*2, v + goff);
            }
            cp_commit();
            cp_wait1();
        } else {
            cp_wait0();
        }
        __syncthreads();

        // S = Q @ K^T
        float acc[8][4];
        #pragma unroll
        for (int n = 0; n < 8; n++)
            #pragma unroll
            for (int e = 0; e < 4; e++) acc[n][e] = 0.f;
        #pragma unroll
        for (int jj = 0; jj < 4; jj++) {
            #pragma unroll
            for (int ks = 0; ks < 4; ks++) {
                uint32_t bf[4];
                int r = jj*16 + (lane & 15);
                int c = ks*16 + (lane >> 4)*8;
                ldsm_x4(bf, (uint32_t)__cvta_generic_to_shared(&Ks[cur][r*FPAD + c]));
                mma16816(acc[jj*2  ], qf[ks], bf[0], bf[2]);
                mma16816(acc[jj*2+1], qf[ks], bf[1], bf[3]);
            }
        }

        // online softmax
        float p[8][4];
        float mx0 = -1e30f, mx1 = -1e30f;
        #pragma unroll
        for (int n = 0; n < 8; n++) {
            float b0 = s_bias[j0 + n*8 + t4*2];
            float b1 = s_bias[j0 + n*8 + t4*2 + 1];
            p[n][0] = acc[n][0]*0.125f + b0;
            p[n][1] = acc[n][1]*0.125f + b1;
            p[n][2] = acc[n][2]*0.125f + b0;
            p[n][3] = acc[n][3]*0.125f + b1;
            mx0 = fmaxf(mx0, fmaxf(p[n][0], p[n][1]));
            mx1 = fmaxf(mx1, fmaxf(p[n][2], p[n][3]));
        }
        mx0 = fmaxf(mx0, __shfl_xor_sync(0xffffffffu, mx0, 1));
        mx0 = fmaxf(mx0, __shfl_xor_sync(0xffffffffu, mx0, 2));
        mx1 = fmaxf(mx1, __shfl_xor_sync(0xffffffffu, mx1, 1));
        mx1 = fmaxf(mx1, __shfl_xor_sync(0xffffffffu, mx1, 2));
        float mn0 = fmaxf(m0v, mx0);
        float mn1 = fmaxf(m1v, mx1);
        float lt0 = 0.f, lt1 = 0.f;
        #pragma unroll
        for (int n = 0; n < 8; n++) {
            p[n][0] = __expf(p[n][0] - mn0);
            p[n][1] = __expf(p[n][1] - mn0);
            p[n][2] = __expf(p[n][2] - mn1);
            p[n][3] = __expf(p[n][3] - mn1);
            lt0 += p[n][0] + p[n][1];
            lt1 += p[n][2] + p[n][3];
        }
        lt0 += __shfl_xor_sync(0xffffffffu, lt0, 1);
        lt0 += __shfl_xor_sync(0xffffffffu, lt0, 2);
        lt1 += __shfl_xor_sync(0xffffffffu, lt1, 1);
        lt1 += __shfl_xor_sync(0xffffffffu, lt1, 2);
        float sc0 = __expf(m0v - mn0);
        float sc1 = __expf(m1v - mn1);
        l0 = l0*sc0 + lt0;
        l1 = l1*sc1 + lt1;
        m0v = mn0; m1v = mn1;
        #pragma unroll
        for (int n = 0; n < 8; n++) {
            oacc[n][0] *= sc0; oacc[n][1] *= sc0;
            oacc[n][2] *= sc1; oacc[n][3] *= sc1;
        }

        uint32_t pa[4][4];
        #pragma unroll
        for (int c = 0; c < 4; c++) {
            pa[c][0] = pack_bf16(p[2*c  ][0], p[2*c  ][1]);
            pa[c][1] = pack_bf16(p[2*c  ][2], p[2*c  ][3]);
            pa[c][2] = pack_bf16(p[2*c+1][0], p[2*c+1][1]);
            pa[c][3] = pack_bf16(p[2*c+1][2], p[2*c+1][3]);
        }

        // O += P @ V
        #pragma unroll
        for (int db = 0; db < 4; db++) {
            #pragma unroll
            for (int c = 0; c < 4; c++) {
                uint32_t vf[4];
                int kk = c*16 + ((lane>>3)&1)*8 + (lane&7);
                int nn = db*16 + (lane>>4)*8;
                ldsm_x4_t(vf, (uint32_t)__cvta_generic_to_shared(&Vs[cur][kk*FPAD + nn]));
                mma16816(oacc[db*2  ], pa[c], vf[0], vf[1]);
                mma16816(oacc[db*2+1], pa[c], vf[2], vf[3]);
            }
        }
        __syncthreads();
    }

    float inv0 = 1.0f / l0, inv1 = 1.0f / l1;
    #pragma unroll
    for (int n = 0; n < 8; n++) {
        int d = n*8 + t4*2;
        int r0 = i0 + warp*16 + g;
        *(__nv_bfloat162*)(ctx + (size_t)(b*Ssz + r0)*Hsz + h*DHsz + d) =
            __floats2bfloat162_rn(oacc[n][0]*inv0, oacc[n][1]*inv0);
        *(__nv_bfloat162*)(ctx + (size_t)(b*Ssz + r0 + 8)*Hsz + h*DHsz + d) =
            __floats2bfloat162_rn(oacc[n][2]*inv1, oacc[n][3]*inv1);
    }
}

// ---------------- classifier (N=19, SIMT) ----------------
__global__ void sgemm_kernel(const float* __restrict__ A, const float* __restrict__ W,
                             const float* __restrict__ bias, float* __restrict__ C,
                             int M, int N, int K)
{
    __shared__ float As[64][17];
    __shared__ float Ws[16][64];
    int m0 = blockIdx.y * 64;
    int n0 = blockIdx.x * 64;
    int tid = threadIdx.x;
    int ty = tid >> 4, tx = tid & 15;
    float acc[4][4] = {};
    for (int k0 = 0; k0 < K; k0 += 16) {
        #pragma unroll
        for (int i = 0; i < 4; i++) {
            int idx = tid + i*256;
            int r = idx >> 4, c = idx & 15;
            As[r][c] = A[(size_t)(m0+r)*K + (k0+c)];
        }
        #pragma unroll
        for (int i = 0; i < 4; i++) {
            int idx = tid + i*256;
            int r = idx >> 6, c = idx & 63;
            int n = n0 + c;
            Ws[r][c] = (n < N) ? W[(size_t)(k0+r)*N + n] : 0.f;
        }
        __syncthreads();
        #pragma unroll
        for (int kk = 0; kk < 16; kk++) {
            float a[4], b[4];
            #pragma unroll
            for (int i = 0; i < 4; i++) a[i] = As[ty*4+i][kk];
            #pragma unroll
            for (int j = 0; j < 4; j++) b[j] = Ws[kk][tx*4+j];
            #pragma unroll
            for (int i = 0; i < 4; i++)
                #pragma unroll
                for (int j = 0; j < 4; j++)
                    acc[i][j] = fmaf(a[i], b[j], acc[i][j]);
        }
        __syncthreads();
    }
    #pragma unroll
    for (int i = 0; i < 4; i++) {
        int m = m0 + ty*4 + i;
        #pragma unroll
        for (int j = 0; j < 4; j++) {
            int n = n0 + tx*4 + j;
            if (n < N) C[(size_t)m*N + n] = acc[i][j] + bias[n];
        }
    }
}

// ---------------- CRF ----------------
__global__ void crf_kernel(const float* __restrict__ lg, const int* __restrict__ labels,
                           const int* __restrict__ mask, const float* __restrict__ st,
                           const float* __restrict__ en, const float* __restrict__ tr,
                           float* __restrict__ out)
{
    __shared__ float s_tr[NLsz*NLsz];
    __shared__ float s_res[Bsz];
    for (int i = threadIdx.x; i < NLsz*NLsz; i += blockDim.x) s_tr[i] = tr[i];
    __syncthreads();
    int warp = threadIdx.x >> 5, lane = threadIdx.x & 31;
    if (warp < Bsz) {
        int b = warp;
        const int* lab = labels + b*Ssz;
        const int* mk  = mask + b*Ssz;
        const float* lgb = lg + (size_t)b*Ssz*NLsz;
        float part = 0.f; int cnt = 0;
        for (int t = lane; t < Ssz; t += 32) {
            cnt += mk[t];
            if (t >= 1) {
                float mf = (float)mk[t];
                part += (s_tr[lab[t-1]*NLsz + lab[t]] + lgb[t*NLsz + lab[t]]) * mf;
            }
        }
        for (int o = 16; o; o >>= 1) {
            part += __shfl_xor_sync(0xffffffffu, part, o);
            cnt  += __shfl_xor_sync(0xffffffffu, cnt, o);
        }
        float num = 0.f;
        if (lane == 0) {
            int l0 = lab[0];
            num = st[l0] + lgb[l0] + part + en[lab[cnt-1]];
        }
        int j = lane;
        float alpha = (j < NLsz) ? st[j] + lgb[j] : -1e30f;
        for (int t = 1; t < Ssz; t++) {
            float g[NLsz];
            #pragma unroll
            for (int i = 0; i < NLsz; i++)
                g[i] = __shfl_sync(0xffffffffu, alpha, i) + ((j < NLsz) ? s_tr[i*NLsz + j] : 0.f);
            float mv = g[0];
            #pragma unroll
            for (int i = 1; i < NLsz; i++) mv = fmaxf(mv, g[i]);
            float sum = 0.f;
            #pragma unroll
            for (int i = 0; i < NLsz; i++) sum += expf(g[i] - mv);
            float nxt = mv + logf(sum) + ((j < NLsz) ? lgb[t*NLsz + j] : 0.f);
            if (mk[t] > 0 && j < NLsz) alpha = nxt;
        }
        float v = (j < NLsz) ? alpha + en[j] : -1e30f;
        float mv = v;
        for (int o = 16; o; o >>= 1) mv = fmaxf(mv, __shfl_xor_sync(0xffffffffu, mv, o));
        float s = (j < NLsz) ? expf(v - mv) : 0.f;
        for (int o = 16; o; o >>= 1) s += __shfl_xor_sync(0xffffffffu, s, o);
        if (lane == 0) s_res[b] = (mv + logf(s)) - num;
    }
    __syncthreads();
    if (threadIdx.x == 0) {
        float tot = 0.f;
        for (int b = 0; b < Bsz; b++) tot += s_res[b];
        out[0] = tot;
    }
}

// ---------------- host ----------------
extern "C" void kernel_launch(void* const* d_in, const int* in_sizes, int n_in,
                              void* d_out, int out_size)
{
    const int*   input_ids = (const int*)  d_in[0];
    const int*   attn_mask = (const int*)  d_in[1];
    const int*   labels    = (const int*)  d_in[2];
    const float* token_emb = (const float*)d_in[3];
    const float* pos_emb   = (const float*)d_in[4];
    const float* ln_emb_s  = (const float*)d_in[5];
    const float* ln_emb_b  = (const float*)d_in[6];
    const float* Wq        = (const float*)d_in[7];
    const float* bq        = (const float*)d_in[8];
    const float* Wk        = (const float*)d_in[9];
    const float* bk        = (const float*)d_in[10];
    const float* Wv        = (const float*)d_in[11];
    const float* bv        = (const float*)d_in[12];
    const float* Wo        = (const float*)d_in[13];
    const float* bo        = (const float*)d_in[14];
    const float* ln1_s     = (const float*)d_in[15];
    const float* ln1_b     = (const float*)d_in[16];
    const float* W1        = (const float*)d_in[17];
    const float* b1        = (const float*)d_in[18];
    const float* W2        = (const float*)d_in[19];
    const float* b2        = (const float*)d_in[20];
    const float* ln2_s     = (const float*)d_in[21];
    const float* ln2_b     = (const float*)d_in[22];
    const float* cls_W     = (const float*)d_in[23];
    const float* cls_b     = (const float*)d_in[24];
    const float* start_tr  = (const float*)d_in[25];
    const float* end_tr    = (const float*)d_in[26];
    const float* trans     = (const float*)d_in[27];

    float *x, *t, *lg;
    __nv_bfloat16 *xb, *qb, *kb, *vb, *cb, *hb;
    __nv_bfloat16 *wqb, *wkb, *wvb, *wob, *w1b, *w2b;
    { void* p; cudaGetSymbolAddress(&p, g_x);  x  = (float*)p; }
    { void* p; cudaGetSymbolAddress(&p, g_t);  t  = (float*)p; }
    { void* p; cudaGetSymbolAddress(&p, g_lg); lg = (float*)p; }
    { void* p; cudaGetSymbolAddress(&p, g_xb); xb = (__nv_bfloat16*)p; }
    { void* p; cudaGetSymbolAddress(&p, g_qb); qb = (__nv_bfloat16*)p; }
    { void* p; cudaGetSymbolAddress(&p, g_kb); kb = (__nv_bfloat16*)p; }
    { void* p; cudaGetSymbolAddress(&p, g_vb); vb = (__nv_bfloat16*)p; }
    { void* p; cudaGetSymbolAddress(&p, g_cb); cb = (__nv_bfloat16*)p; }
    { void* p; cudaGetSymbolAddress(&p, g_hb); hb = (__nv_bfloat16*)p; }
    { void* p; cudaGetSymbolAddress(&p, g_wq); wqb = (__nv_bfloat16*)p; }
    { void* p; cudaGetSymbolAddress(&p, g_wk); wkb = (__nv_bfloat16*)p; }
    { void* p; cudaGetSymbolAddress(&p, g_wv); wvb = (__nv_bfloat16*)p; }
    { void* p; cudaGetSymbolAddress(&p, g_wo); wob = (__nv_bfloat16*)p; }
    { void* p; cudaGetSymbolAddress(&p, g_w1); w1b = (__nv_bfloat16*)p; }
    { void* p; cudaGetSymbolAddress(&p, g_w2); w2b = (__nv_bfloat16*)p; }

    // weight pre-conversion (runs each launch; ~90us)
    {
        int n4a = Lsz*Hsz*Hsz/4;       // 1,769,472
        int n4f = Lsz*Hsz*DFFsz/4;     // 7,077,888
        cvt_bf16_kernel<<<(n4a+255)/256, 256>>>(Wq, wqb, n4a);
        cvt_bf16_kernel<<<(n4a+255)/256, 256>>>(Wk, wkb, n4a);
        cvt_bf16_kernel<<<(n4a+255)/256, 256>>>(Wv, wvb, n4a);
        cvt_bf16_kernel<<<(n4a+255)/256, 256>>>(Wo, wob, n4a);
        cvt_bf16_kernel<<<(n4f+255)/256, 256>>>(W1, w1b, n4f);
        cvt_bf16_kernel<<<(n4f+255)/256, 256>>>(W2, w2b, n4f);
    }

    embed_kernel<<<Tsz, 256>>>(input_ids, token_emb, pos_emb, t);
    ln_kernel<<<Tsz, 256>>>(t, ln_emb_s, ln_emb_b, x, xb);

    for (int l = 0; l < Lsz; l++) {
        const __nv_bfloat16* wq = wqb + (size_t)l*Hsz*Hsz;
        const __nv_bfloat16* wk = wkb + (size_t)l*Hsz*Hsz;
        const __nv_bfloat16* wv = wvb + (size_t)l*Hsz*Hsz;
        const __nv_bfloat16* wo = wob + (size_t)l*Hsz*Hsz;

        mma_qkv_kernel<<<dim3(Hsz/128, Tsz/128, 3), 256>>>(
            xb, wq, wk, wv, bq + l*Hsz, bk + l*Hsz, bv + l*Hsz, qb, kb, vb);

        flash_attn_kernel<<<dim3(Ssz/64, Bsz*NHsz), 128>>>(qb, kb, vb, attn_mask, cb);

        gemm_res_kernel<<<dim3(Hsz/128, Tsz/128), 256>>>(cb, wo, bo + l*Hsz, x, t, Hsz, Hsz);
        ln_kernel<<<Tsz, 256>>>(t, ln1_s + l*Hsz, ln1_b + l*Hsz, x, xb);

        gemm_gelu_kernel<<<dim3(DFFsz/128, Tsz/128), 256>>>(
            xb, w1b + (size_t)l*Hsz*DFFsz, b1 + l*DFFsz, hb, DFFsz, Hsz);
        gemm_res_kernel<<<dim3(Hsz/128, Tsz/128), 256>>>(
            hb, w2b + (size_t)l*DFFsz*Hsz, b2 + l*Hsz, x, t, Hsz, DFFsz);
        ln_kernel<<<Tsz, 256>>>(t, ln2_s + l*Hsz, ln2_b + l*Hsz, x, xb);
    }

    sgemm_kernel<<<dim3(1, Tsz/64), 256>>>(x, cls_W, cls_b, lg, Tsz, NLsz, Hsz);
    crf_kernel<<<1, 256>>>(lg, labels, attn_mask, start_tr, end_tr, trans, (float*)d_out);
}

// round 15
// speedup vs baseline: 7.1829x; 1.1169x over previous
#include <cuda_runtime.h>
#include <cuda_bf16.h>
#include <math.h>
#include <stdint.h>

#define Bsz  8
#define Ssz  512
#define Hsz  768
#define Lsz  12
#define NHsz 12
#define DHsz 64
#define DFFsz 3072
#define NLsz 19
#define Tsz  (Bsz*Ssz)   // 4096 tokens

// ---------------- scratch ----------------
__device__ float          g_x [Tsz*Hsz];
__device__ float          g_t [Tsz*Hsz];
__device__ __nv_bfloat16  g_xb[Tsz*Hsz];
__device__ __nv_bfloat16  g_qb[Tsz*Hsz];
__device__ __nv_bfloat16  g_kb[Tsz*Hsz];
__device__ __nv_bfloat16  g_vb[Tsz*Hsz];
__device__ __nv_bfloat16  g_cb[Tsz*Hsz];
__device__ __nv_bfloat16  g_hb[Tsz*DFFsz];
__device__ float          g_lg[Tsz*NLsz];
// bf16 weights (pre-converted each launch)
__device__ __nv_bfloat16  g_wq[Lsz*Hsz*Hsz];
__device__ __nv_bfloat16  g_wk[Lsz*Hsz*Hsz];
__device__ __nv_bfloat16  g_wv[Lsz*Hsz*Hsz];
__device__ __nv_bfloat16  g_wo[Lsz*Hsz*Hsz];
__device__ __nv_bfloat16  g_w1[Lsz*Hsz*DFFsz];
__device__ __nv_bfloat16  g_w2[Lsz*DFFsz*Hsz];

// ---------------- fp32 -> bf16 convert (batched over 4 / 2 tensors) ----------------
__device__ __forceinline__ void cvt_body(const float* __restrict__ in,
                                         __nv_bfloat16* __restrict__ out, int n4)
{
    int i = blockIdx.x*blockDim.x + threadIdx.x;
    if (i < n4) {
        float4 f = ((const float4*)in)[i];
        __nv_bfloat162 a = __floats2bfloat162_rn(f.x, f.y);
        __nv_bfloat162 b = __floats2bfloat162_rn(f.z, f.w);
        uint2 o; o.x = *(uint32_t*)&a; o.y = *(uint32_t*)&b;
        ((uint2*)out)[i] = o;
    }
}
__global__ void cvt4_kernel(const float* __restrict__ w0, const float* __restrict__ w1,
                            const float* __restrict__ w2, const float* __restrict__ w3,
                            __nv_bfloat16* __restrict__ o0, __nv_bfloat16* __restrict__ o1,
                            __nv_bfloat16* __restrict__ o2, __nv_bfloat16* __restrict__ o3,
                            int n4)
{
    int z = blockIdx.y;
    const float* in = (z == 0) ? w0 : (z == 1) ? w1 : (z == 2) ? w2 : w3;
    __nv_bfloat16* out = (z == 0) ? o0 : (z == 1) ? o1 : (z == 2) ? o2 : o3;
    cvt_body(in, out, n4);
}
__global__ void cvt2_kernel(const float* __restrict__ w0, const float* __restrict__ w1,
                            __nv_bfloat16* __restrict__ o0, __nv_bfloat16* __restrict__ o1,
                            int n4)
{
    int z = blockIdx.y;
    cvt_body(z ? w1 : w0, z ? o1 : o0, n4);
}

// ---------------- embedding ----------------
__global__ void embed_kernel(const int* __restrict__ ids,
                             const float* __restrict__ tok,
                             const float* __restrict__ pos,
                             float* __restrict__ out)
{
    int t = blockIdx.x;
    int s = t & (Ssz-1);
    int id = ids[t];
    const float* tp = tok + (size_t)id*Hsz;
    const float* pp = pos + (size_t)s*Hsz;
    float* op = out + (size_t)t*Hsz;
    for (int c = threadIdx.x; c < Hsz; c += blockDim.x)
        op[c] = tp[c] + pp[c];
}

// ---------------- layernorm (writes fp32 + bf16) ----------------
__global__ void ln_kernel(const float* __restrict__ in,
                          const float* __restrict__ gamma,
                          const float* __restrict__ beta,
                          float* __restrict__ out,
                          __nv_bfloat16* __restrict__ outb)
{
    __shared__ float sh[32];
    int row = blockIdx.x;
    int tid = threadIdx.x;
    const float* p = in + (size_t)row*Hsz;
    float v0 = p[tid], v1 = p[tid+256], v2 = p[tid+512];
    float s = v0+v1+v2;
    int lane = tid & 31, w = tid >> 5;
    for (int o = 16; o; o >>= 1) s += __shfl_xor_sync(0xffffffffu, s, o);
    if (!lane) sh[w] = s;
    __syncthreads();
    if (w == 0) {
        s = (lane < 8) ? sh[lane] : 0.f;
        for (int o = 4; o; o >>= 1) s += __shfl_xor_sync(0xffffffffu, s, o);
        if (!lane) sh[0] = s;
    }
    __syncthreads();
    float mean = sh[0] * (1.0f/Hsz);
    __syncthreads();
    float d0 = v0-mean, d1 = v1-mean, d2 = v2-mean;
    float q = d0*d0 + d1*d1 + d2*d2;
    for (int o = 16; o; o >>= 1) q += __shfl_xor_sync(0xffffffffu, q, o);
    if (!lane) sh[w] = q;
    __syncthreads();
    if (w == 0) {
        q = (lane < 8) ? sh[lane] : 0.f;
        for (int o = 4; o; o >>= 1) q += __shfl_xor_sync(0xffffffffu, q, o);
        if (!lane) sh[0] = q;
    }
    __syncthreads();
    float var = sh[0] * (1.0f/Hsz);
    float inv = rsqrtf(var + 1e-12f);
    float* op = out + (size_t)row*Hsz;
    __nv_bfloat16* ob = outb + (size_t)row*Hsz;
    float r0 = d0*inv*gamma[tid    ] + beta[tid    ];
    float r1 = d1*inv*gamma[tid+256] + beta[tid+256];
    float r2 = d2*inv*gamma[tid+512] + beta[tid+512];
    op[tid] = r0; op[tid+256] = r1; op[tid+512] = r2;
    ob[tid] = __float2bfloat16(r0);
    ob[tid+256] = __float2bfloat16(r1);
    ob[tid+512] = __float2bfloat16(r2);
}

// ================= MMA / async primitives =================
__device__ __forceinline__ void ldsm_x4(uint32_t (&r)[4], uint32_t addr) {
    asm volatile("ldmatrix.sync.aligned.m8n8.x4.shared.b16 {%0,%1,%2,%3}, [%4];"
        : "=r"(r[0]),"=r"(r[1]),"=r"(r[2]),"=r"(r[3]) : "r"(addr));
}
__device__ __forceinline__ void ldsm_x4_t(uint32_t (&r)[4], uint32_t addr) {
    asm volatile("ldmatrix.sync.aligned.m8n8.x4.trans.shared.b16 {%0,%1,%2,%3}, [%4];"
        : "=r"(r[0]),"=r"(r[1]),"=r"(r[2]),"=r"(r[3]) : "r"(addr));
}
__device__ __forceinline__ void mma16816(float (&c)[4], const uint32_t (&a)[4],
                                         uint32_t b0, uint32_t b1) {
    asm volatile("mma.sync.aligned.m16n8k16.row.col.f32.bf16.bf16.f32 "
        "{%0,%1,%2,%3}, {%4,%5,%6,%7}, {%8,%9}, {%0,%1,%2,%3};"
        : "+f"(c[0]),"+f"(c[1]),"+f"(c[2]),"+f"(c[3])
        : "r"(a[0]),"r"(a[1]),"r"(a[2]),"r"(a[3]), "r"(b0),"r"(b1));
}
__device__ __forceinline__ uint32_t pack_bf16(float x, float y) {
    __nv_bfloat162 h = __floats2bfloat162_rn(x, y);
    return *(uint32_t*)&h;
}
__device__ __forceinline__ void cp16(uint32_t smem, const void* g) {
    asm volatile("cp.async.cg.shared.global [%0], [%1], 16;" :: "r"(smem), "l"(g));
}
__device__ __forceinline__ void cp_commit() { asm volatile("cp.async.commit_group;"); }
__device__ __forceinline__ void cp_wait2()  { asm volatile("cp.async.wait_group 2;"); }
__device__ __forceinline__ void cp_wait1()  { asm volatile("cp.async.wait_group 1;"); }
__device__ __forceinline__ void cp_wait0()  { asm volatile("cp.async.wait_group 0;"); }
__device__ __forceinline__ float fast_gelu(float v) {
    float z = 0.7978845608028654f*(v + 0.044715f*v*v*v);
    float t; asm("tanh.approx.f32 %0, %1;" : "=f"(t) : "f"(z));
    return 0.5f*v*(1.0f + t);
}

// ================= bf16 GEMM, 4-stage cp.async pipeline =================
// C = A[M,K](bf16) @ W[K,N](bf16) + bias; MODE: 1=gelu->bf16, 2=residual->fp32, 3=bias->bf16
#define APAD 40    // A smem row stride (bf16 elems), 80B
#define WPAD 136   // W smem row stride, 272B
#define NSTG 4
#define A_STG (128*APAD)
#define W_STG (32*WPAD)
#define GEMM_SMEM ((NSTG*(A_STG + W_STG))*2)   // 75776 bytes

template<int MODE>
__device__ __forceinline__ void gemm_core(
    const __nv_bfloat16* __restrict__ A, const __nv_bfloat16* __restrict__ W,
    const float* __restrict__ bias, const float* __restrict__ res,
    void* __restrict__ Cout, int N, int K, int m0, int n0)
{
    extern __shared__ __nv_bfloat16 dsm[];
    __nv_bfloat16* As = dsm;                 // NSTG stages of 128*APAD
    __nv_bfloat16* Ws = dsm + NSTG*A_STG;    // NSTG stages of 32*WPAD
    int tid = threadIdx.x;
    int warp = tid >> 5, lane = tid & 31;
    int wm = warp >> 2;
    int wn = warp & 3;
    uint32_t as_base = (uint32_t)__cvta_generic_to_shared(As);
    uint32_t ws_base = (uint32_t)__cvta_generic_to_shared(Ws);

    float acc[4][4][4];
    #pragma unroll
    for (int i = 0; i < 4; i++)
        #pragma unroll
        for (int j = 0; j < 4; j++)
            #pragma unroll
            for (int e = 0; e < 4; e++) acc[i][j][e] = 0.f;

    const int KT = K >> 5;

    // row/col assignments for loads (2 cp16 each for A and W)
    int ar0 = tid >> 2,          ac0 = (tid & 3)*8;
    int ar1 = (tid+256) >> 2,    ac1 = (tid & 3)*8;
    int wr0 = tid >> 4,          wc0 = (tid & 15)*8;
    int wr1 = (tid+256) >> 4,    wc1 = (tid & 15)*8;

    // prologue: stages 0..2
    #pragma unroll
    for (int st = 0; st < NSTG-1; st++) {
        int k0 = st << 5;
        cp16(as_base + (st*A_STG + ar0*APAD + ac0)*2, A + (size_t)(m0 + ar0)*K + k0 + ac0);
        cp16(as_base + (st*A_STG + ar1*APAD + ac1)*2, A + (size_t)(m0 + ar1)*K + k0 + ac1);
        cp16(ws_base + (st*W_STG + wr0*WPAD + wc0)*2, W + (size_t)(k0 + wr0)*N + n0 + wc0);
        cp16(ws_base + (st*W_STG + wr1*WPAD + wc1)*2, W + (size_t)(k0 + wr1)*N + n0 + wc1);
        cp_commit();
    }

    for (int kt = 0; kt < KT; kt++) {
        if (kt < KT-2)      cp_wait2();
        else if (kt == KT-2) cp_wait1();
        else                 cp_wait0();
        __syncthreads();

        int cur = kt & (NSTG-1);
        const __nv_bfloat16* Ac = As + cur*A_STG;
        const __nv_bfloat16* Wc = Ws + cur*W_STG;
        #pragma unroll
        for (int ks = 0; ks < 2; ks++) {
            uint32_t af[4][4];
            #pragma unroll
            for (int i = 0; i < 4; i++) {
                int r = wm*64 + i*16 + (lane & 15);
                int c = ks*16 + (lane >> 4)*8;
                ldsm_x4(af[i], (uint32_t)__cvta_generic_to_shared(Ac + r*APAD + c));
            }
            uint32_t bf[2][4];
            #pragma unroll
            for (int j2 = 0; j2 < 2; j2++) {
                int kk = ks*16 + ((lane>>3)&1)*8 + (lane&7);
                int nn = wn*32 + j2*16 + (lane>>4)*8;
                ldsm_x4_t(bf[j2], (uint32_t)__cvta_generic_to_shared(Wc + kk*WPAD + nn));
            }
            #pragma unroll
            for (int i = 0; i < 4; i++)
                #pragma unroll
                for (int j = 0; j < 4; j++)
                    mma16816(acc[i][j], af[i], bf[j>>1][(j&1)*2], bf[j>>1][(j&1)*2+1]);
        }

        if (kt + NSTG-1 < KT) {
            int st = (kt + NSTG-1) & (NSTG-1);
            int k0 = (kt + NSTG-1) << 5;
            cp16(as_base + (st*A_STG + ar0*APAD + ac0)*2, A + (size_t)(m0 + ar0)*K + k0 + ac0);
            cp16(as_base + (st*A_STG + ar1*APAD + ac1)*2, A + (size_t)(m0 + ar1)*K + k0 + ac1);
            cp16(ws_base + (st*W_STG + wr0*WPAD + wc0)*2, W + (size_t)(k0 + wr0)*N + n0 + wc0);
            cp16(ws_base + (st*W_STG + wr1*WPAD + wc1)*2, W + (size_t)(k0 + wr1)*N + n0 + wc1);
            cp_commit();
        }
    }

    // epilogue
    #pragma unroll
    for (int i = 0; i < 4; i++) {
        int mb = m0 + wm*64 + i*16 + (lane >> 2);
        #pragma unroll
        for (int j = 0; j < 4; j++) {
            int nb = n0 + wn*32 + j*8 + (lane & 3)*2;
            float b0 = bias[nb], b1 = bias[nb+1];
            #pragma unroll
            for (int half = 0; half < 2; half++) {
                int m = mb + half*8;
                float v0 = acc[i][j][half*2]   + b0;
                float v1 = acc[i][j][half*2+1] + b1;
                if (MODE == 1) {
                    v0 = fast_gelu(v0);
                    v1 = fast_gelu(v1);
                } else if (MODE == 2) {
                    float2 r2 = *(const float2*)(res + (size_t)m*N + nb);
                    v0 += r2.x; v1 += r2.y;
                }
                if (MODE == 1 || MODE == 3) {
                    *(__nv_bfloat162*)((__nv_bfloat16*)Cout + (size_t)m*N + nb) =
                        __floats2bfloat162_rn(v0, v1);
                } else {
                    float2 o; o.x = v0; o.y = v1;
                    *(float2*)((float*)Cout + (size_t)m*N + nb) = o;
                }
            }
        }
    }
}

__global__ __launch_bounds__(256,2) void gemm_gelu_kernel(
    const __nv_bfloat16* __restrict__ A, const __nv_bfloat16* __restrict__ W,
    const float* __restrict__ bias, __nv_bfloat16* __restrict__ C, int N, int K)
{
    gemm_core<1>(A, W, bias, nullptr, C, N, K, blockIdx.y*128, blockIdx.x*128);
}
__global__ __launch_bounds__(256,2) void gemm_res_kernel(
    const __nv_bfloat16* __restrict__ A, const __nv_bfloat16* __restrict__ W,
    const float* __restrict__ bias, const float* __restrict__ res,
    float* __restrict__ C, int N, int K)
{
    gemm_core<2>(A, W, bias, res, C, N, K, blockIdx.y*128, blockIdx.x*128);
}
__global__ __launch_bounds__(256,2) void mma_qkv_kernel(
    const __nv_bfloat16* __restrict__ A,
    const __nv_bfloat16* __restrict__ Wq, const __nv_bfloat16* __restrict__ Wk,
    const __nv_bfloat16* __restrict__ Wv,
    const float* __restrict__ bq, const float* __restrict__ bk, const float* __restrict__ bv,
    __nv_bfloat16* __restrict__ q, __nv_bfloat16* __restrict__ k, __nv_bfloat16* __restrict__ v)
{
    int z = blockIdx.z;
    const __nv_bfloat16* W = (z == 0) ? Wq : (z == 1) ? Wk : Wv;
    const float* bb = (z == 0) ? bq : (z == 1) ? bk : bv;
    __nv_bfloat16* C = (z == 0) ? q : (z == 1) ? k : v;
    gemm_core<3>(A, W, bb, nullptr, C, Hsz, Hsz, blockIdx.y*128, blockIdx.x*128);
}

// ================= flash attention (cp.async double-buffered KV) =================
#define FPAD 72

__global__ __launch_bounds__(128) void flash_attn_kernel(
    const __nv_bfloat16* __restrict__ q, const __nv_bfloat16* __restrict__ k,
    const __nv_bfloat16* __restrict__ v, const int* __restrict__ mask,
    __nv_bfloat16* __restrict__ ctx)
{
    __shared__ __nv_bfloat16 Qs[64*FPAD];
    __shared__ __nv_bfloat16 Ks[2][64*FPAD];
    __shared__ __nv_bfloat16 Vs[2][64*FPAD];
    __shared__ float s_bias[Ssz];

    int bh = blockIdx.y;
    int b = bh / NHsz, h = bh % NHsz;
    int i0 = blockIdx.x * 64;
    int tid = threadIdx.x;
    int warp = tid >> 5, lane = tid & 31;
    int g = lane >> 2, t4 = lane & 3;
    uint32_t ks_base = (uint32_t)__cvta_generic_to_shared(&Ks[0][0]);
    uint32_t vs_base = (uint32_t)__cvta_generic_to_shared(&Vs[0][0]);

    #pragma unroll
    for (int it = 0; it < 4; it++) {
        int j = tid + it*128;
        s_bias[j] = mask[b*Ssz + j] ? 0.f : -1e9f;
    }
    #pragma unroll
    for (int it = 0; it < 4; it++) {
        int idx = tid + it*128;
        int r = idx >> 3, c8 = idx & 7;
        *(uint4*)&Qs[r*FPAD + c8*8] =
            *(const uint4*)(q + (size_t)(b*Ssz + i0 + r)*Hsz + h*DHsz + c8*8);
    }
    __syncthreads();

    uint32_t qf[4][4];
    #pragma unroll
    for (int ks = 0; ks < 4; ks++) {
        int r = warp*16 + (lane & 15);
        int c = ks*16 + (lane >> 4)*8;
        ldsm_x4(qf[ks], (uint32_t)__cvta_generic_to_shared(&Qs[r*FPAD + c]));
    }

    #pragma unroll
    for (int it = 0; it < 4; it++) {
        int idx = tid + it*128;
        int r = idx >> 3, c8 = idx & 7;
        size_t goff = (size_t)(b*Ssz + r)*Hsz + h*DHsz + c8*8;
        cp16(ks_base + (r*FPAD + c8*8)*2, k + goff);
        cp16(vs_base + (r*FPAD + c8*8)*2, v + goff);
    }
    cp_commit();

    float oacc[8][4];
    #pragma unroll
    for (int n = 0; n < 8; n++)
        #pragma unroll
        for (int e = 0; e < 4; e++) oacc[n][e] = 0.f;
    float m0v = -1e30f, m1v = -1e30f, l0 = 0.f, l1 = 0.f;

    const int NT = Ssz/64;
    for (int jt = 0; jt < NT; jt++) {
        int cur = jt & 1;
        int j0 = jt*64;
        if (jt + 1 < NT) {
            int st = cur ^ 1;
            int j0n = j0 + 64;
            #pragma unroll
            for (int it = 0; it < 4; it++) {
                int idx = tid + it*128;
                int r = idx >> 3, c8 = idx & 7;
                size_t goff = (size_t)(b*Ssz + j0n + r)*Hsz + h*DHsz + c8*8;
                cp16(ks_base + (st*64*FPAD + r*FPAD + c8*8)*2, k + goff);
                cp16(vs_base + (st*64*FPAD + r*FPAD + c8*8)*2, v + goff);
            }
            cp_commit();
            cp_wait1();
        } else {
            cp_wait0();
        }
        __syncthreads();

        float acc[8][4];
        #pragma unroll
        for (int n = 0; n < 8; n++)
            #pragma unroll
            for (int e = 0; e < 4; e++) acc[n][e] = 0.f;
        #pragma unroll
        for (int jj = 0; jj < 4; jj++) {
            #pragma unroll
            for (int ks = 0; ks < 4; ks++) {
                uint32_t bf[4];
                int r = jj*16 + (lane & 15);
                int c = ks*16 + (lane >> 4)*8;
                ldsm_x4(bf, (uint32_t)__cvta_generic_to_shared(&Ks[cur][r*FPAD + c]));
                mma16816(acc[jj*2  ], qf[ks], bf[0], bf[2]);
                mma16816(acc[jj*2+1], qf[ks], bf[1], bf[3]);
            }
        }

        float p[8][4];
        float mx0 = -1e30f, mx1 = -1e30f;
        #pragma unroll
        for (int n = 0; n < 8; n++) {
            float b0 = s_bias[j0 + n*8 + t4*2];
            float b1 = s_bias[j0 + n*8 + t4*2 + 1];
            p[n][0] = acc[n][0]*0.125f + b0;
            p[n][1] = acc[n][1]*0.125f + b1;
            p[n][2] = acc[n][2]*0.125f + b0;
            p[n][3] = acc[n][3]*0.125f + b1;
            mx0 = fmaxf(mx0, fmaxf(p[n][0], p[n][1]));
            mx1 = fmaxf(mx1, fmaxf(p[n][2], p[n][3]));
        }
        mx0 = fmaxf(mx0, __shfl_xor_sync(0xffffffffu, mx0, 1));
        mx0 = fmaxf(mx0, __shfl_xor_sync(0xffffffffu, mx0, 2));
        mx1 = fmaxf(mx1, __shfl_xor_sync(0xffffffffu, mx1, 1));
        mx1 = fmaxf(mx1, __shfl_xor_sync(0xffffffffu, mx1, 2));
        float mn0 = fmaxf(m0v, mx0);
        float mn1 = fmaxf(m1v, mx1);
        float lt0 = 0.f, lt1 = 0.f;
        #pragma unroll
        for (int n = 0; n < 8; n++) {
            p[n][0] = __expf(p[n][0] - mn0);
            p[n][1] = __expf(p[n][1] - mn0);
            p[n][2] = __expf(p[n][2] - mn1);
            p[n][3] = __expf(p[n][3] - mn1);
            lt0 += p[n][0] + p[n][1];
            lt1 += p[n][2] + p[n][3];
        }
        lt0 += __shfl_xor_sync(0xffffffffu, lt0, 1);
        lt0 += __shfl_xor_sync(0xffffffffu, lt0, 2);
        lt1 += __shfl_xor_sync(0xffffffffu, lt1, 1);
        lt1 += __shfl_xor_sync(0xffffffffu, lt1, 2);
        float sc0 = __expf(m0v - mn0);
        float sc1 = __expf(m1v - mn1);
        l0 = l0*sc0 + lt0;
        l1 = l1*sc1 + lt1;
        m0v = mn0; m1v = mn1;
        #pragma unroll
        for (int n = 0; n < 8; n++) {
            oacc[n][0] *= sc0; oacc[n][1] *= sc0;
            oacc[n][2] *= sc1; oacc[n][3] *= sc1;
        }

        uint32_t pa[4][4];
        #pragma unroll
        for (int c = 0; c < 4; c++) {
            pa[c][0] = pack_bf16(p[2*c  ][0], p[2*c  ][1]);
            pa[c][1] = pack_bf16(p[2*c  ][2], p[2*c  ][3]);
            pa[c][2] = pack_bf16(p[2*c+1][0], p[2*c+1][1]);
            pa[c][3] = pack_bf16(p[2*c+1][2], p[2*c+1][3]);
        }

        #pragma unroll
        for (int db = 0; db < 4; db++) {
            #pragma unroll
            for (int c = 0; c < 4; c++) {
                uint32_t vf[4];
                int kk = c*16 + ((lane>>3)&1)*8 + (lane&7);
                int nn = db*16 + (lane>>4)*8;
                ldsm_x4_t(vf, (uint32_t)__cvta_generic_to_shared(&Vs[cur][kk*FPAD + nn]));
                mma16816(oacc[db*2  ], pa[c], vf[0], vf[1]);
                mma16816(oacc[db*2+1], pa[c], vf[2], vf[3]);
            }
        }
        __syncthreads();
    }

    float inv0 = 1.0f / l0, inv1 = 1.0f / l1;
    #pragma unroll
    for (int n = 0; n < 8; n++) {
        int d = n*8 + t4*2;
        int r0 = i0 + warp*16 + g;
        *(__nv_bfloat162*)(ctx + (size_t)(b*Ssz + r0)*Hsz + h*DHsz + d) =
            __floats2bfloat162_rn(oacc[n][0]*inv0, oacc[n][1]*inv0);
        *(__nv_bfloat162*)(ctx + (size_t)(b*Ssz + r0 + 8)*Hsz + h*DHsz + d) =
            __floats2bfloat162_rn(oacc[n][2]*inv1, oacc[n][3]*inv1);
    }
}

// ---------------- classifier (N=19, SIMT) ----------------
__global__ void sgemm_kernel(const float* __restrict__ A, const float* __restrict__ W,
                             const float* __restrict__ bias, float* __restrict__ C,
                             int M, int N, int K)
{
    __shared__ float As[64][17];
    __shared__ float Ws[16][64];
    int m0 = blockIdx.y * 64;
    int n0 = blockIdx.x * 64;
    int tid = threadIdx.x;
    int ty = tid >> 4, tx = tid & 15;
    float acc[4][4] = {};
    for (int k0 = 0; k0 < K; k0 += 16) {
        #pragma unroll
        for (int i = 0; i < 4; i++) {
            int idx = tid + i*256;
            int r = idx >> 4, c = idx & 15;
            As[r][c] = A[(size_t)(m0+r)*K + (k0+c)];
        }
        #pragma unroll
        for (int i = 0; i < 4; i++) {
            int idx = tid + i*256;
            int r = idx >> 6, c = idx & 63;
            int n = n0 + c;
            Ws[r][c] = (n < N) ? W[(size_t)(k0+r)*N + n] : 0.f;
        }
        __syncthreads();
        #pragma unroll
        for (int kk = 0; kk < 16; kk++) {
            float a[4], b[4];
            #pragma unroll
            for (int i = 0; i < 4; i++) a[i] = As[ty*4+i][kk];
            #pragma unroll
            for (int j = 0; j < 4; j++) b[j] = Ws[kk][tx*4+j];
            #pragma unroll
            for (int i = 0; i < 4; i++)
                #pragma unroll
                for (int j = 0; j < 4; j++)
                    acc[i][j] = fmaf(a[i], b[j], acc[i][j]);
        }
        __syncthreads();
    }
    #pragma unroll
    for (int i = 0; i < 4; i++) {
        int m = m0 + ty*4 + i;
        #pragma unroll
        for (int j = 0; j < 4; j++) {
            int n = n0 + tx*4 + j;
            if (n < N) C[(size_t)m*N + n] = acc[i][j] + bias[n];
        }
    }
}

// ---------------- CRF ----------------
__global__ void crf_kernel(const float* __restrict__ lg, const int* __restrict__ labels,
                           const int* __restrict__ mask, const float* __restrict__ st,
                           const float* __restrict__ en, const float* __restrict__ tr,
                           float* __restrict__ out)
{
    __shared__ float s_tr[NLsz*NLsz];
    __shared__ float s_res[Bsz];
    for (int i = threadIdx.x; i < NLsz*NLsz; i += blockDim.x) s_tr[i] = tr[i];
    __syncthreads();
    int warp = threadIdx.x >> 5, lane = threadIdx.x & 31;
    if (warp < Bsz) {
        int b = warp;
        const int* lab = labels + b*Ssz;
        const int* mk  = mask + b*Ssz;
        const float* lgb = lg + (size_t)b*Ssz*NLsz;
        float part = 0.f; int cnt = 0;
        for (int t = lane; t < Ssz; t += 32) {
            cnt += mk[t];
            if (t >= 1) {
                float mf = (float)mk[t];
                part += (s_tr[lab[t-1]*NLsz + lab[t]] + lgb[t*NLsz + lab[t]]) * mf;
            }
        }
        for (int o = 16; o; o >>= 1) {
            part += __shfl_xor_sync(0xffffffffu, part, o);
            cnt  += __shfl_xor_sync(0xffffffffu, cnt, o);
        }
        float num = 0.f;
        if (lane == 0) {
            int l0 = lab[0];
            num = st[l0] + lgb[l0] + part + en[lab[cnt-1]];
        }
        int j = lane;
        float alpha = (j < NLsz) ? st[j] + lgb[j] : -1e30f;
        for (int t = 1; t < Ssz; t++) {
            float g[NLsz];
            #pragma unroll
            for (int i = 0; i < NLsz; i++)
                g[i] = __shfl_sync(0xffffffffu, alpha, i) + ((j < NLsz) ? s_tr[i*NLsz + j] : 0.f);
            float mv = g[0];
            #pragma unroll
            for (int i = 1; i < NLsz; i++) mv = fmaxf(mv, g[i]);
            float sum = 0.f;
            #pragma unroll
            for (int i = 0; i < NLsz; i++) sum += expf(g[i] - mv);
            float nxt = mv + logf(sum) + ((j < NLsz) ? lgb[t*NLsz + j] : 0.f);
            if (mk[t] > 0 && j < NLsz) alpha = nxt;
        }
        float v = (j < NLsz) ? alpha + en[j] : -1e30f;
        float mv = v;
        for (int o = 16; o; o >>= 1) mv = fmaxf(mv, __shfl_xor_sync(0xffffffffu, mv, o));
        float s = (j < NLsz) ? expf(v - mv) : 0.f;
        for (int o = 16; o; o >>= 1) s += __shfl_xor_sync(0xffffffffu, s, o);
        if (lane == 0) s_res[b] = (mv + logf(s)) - num;
    }
    __syncthreads();
    if (threadIdx.x == 0) {
        float tot = 0.f;
        for (int b = 0; b < Bsz; b++) tot += s_res[b];
        out[0] = tot;
    }
}

// ---------------- host ----------------
extern "C" void kernel_launch(void* const* d_in, const int* in_sizes, int n_in,
                              void* d_out, int out_size)
{
    const int*   input_ids = (const int*)  d_in[0];
    const int*   attn_mask = (const int*)  d_in[1];
    const int*   labels    = (const int*)  d_in[2];
    const float* token_emb = (const float*)d_in[3];
    const float* pos_emb   = (const float*)d_in[4];
    const float* ln_emb_s  = (const float*)d_in[5];
    const float* ln_emb_b  = (const float*)d_in[6];
    const float* Wq        = (const float*)d_in[7];
    const float* bq        = (const float*)d_in[8];
    const float* Wk        = (const float*)d_in[9];
    const float* bk        = (const float*)d_in[10];
    const float* Wv        = (const float*)d_in[11];
    const float* bv        = (const float*)d_in[12];
    const float* Wo        = (const float*)d_in[13];
    const float* bo        = (const float*)d_in[14];
    const float* ln1_s     = (const float*)d_in[15];
    const float* ln1_b     = (const float*)d_in[16];
    const float* W1        = (const float*)d_in[17];
    const float* b1        = (const float*)d_in[18];
    const float* W2        = (const float*)d_in[19];
    const float* b2        = (const float*)d_in[20];
    const float* ln2_s     = (const float*)d_in[21];
    const float* ln2_b     = (const float*)d_in[22];
    const float* cls_W     = (const float*)d_in[23];
    const float* cls_b     = (const float*)d_in[24];
    const float* start_tr  = (const float*)d_in[25];
    const float* end_tr    = (const float*)d_in[26];
    const float* trans     = (const float*)d_in[27];

    float *x, *t, *lg;
    __nv_bfloat16 *xb, *qb, *kb, *vb, *cb, *hb;
    __nv_bfloat16 *wqb, *wkb, *wvb, *wob, *w1b, *w2b;
    { void* p; cudaGetSymbolAddress(&p, g_x);  x  = (float*)p; }
    { void* p; cudaGetSymbolAddress(&p, g_t);  t  = (float*)p; }
    { void* p; cudaGetSymbolAddress(&p, g_lg); lg = (float*)p; }
    { void* p; cudaGetSymbolAddress(&p, g_xb); xb = (__nv_bfloat16*)p; }
    { void* p; cudaGetSymbolAddress(&p, g_qb); qb = (__nv_bfloat16*)p; }
    { void* p; cudaGetSymbolAddress(&p, g_kb); kb = (__nv_bfloat16*)p; }
    { void* p; cudaGetSymbolAddress(&p, g_vb); vb = (__nv_bfloat16*)p; }
    { void* p; cudaGetSymbolAddress(&p, g_cb); cb = (__nv_bfloat16*)p; }
    { void* p; cudaGetSymbolAddress(&p, g_hb); hb = (__nv_bfloat16*)p; }
    { void* p; cudaGetSymbolAddress(&p, g_wq); wqb = (__nv_bfloat16*)p; }
    { void* p; cudaGetSymbolAddress(&p, g_wk); wkb = (__nv_bfloat16*)p; }
    { void* p; cudaGetSymbolAddress(&p, g_wv); wvb = (__nv_bfloat16*)p; }
    { void* p; cudaGetSymbolAddress(&p, g_wo); wob = (__nv_bfloat16*)p; }
    { void* p; cudaGetSymbolAddress(&p, g_w1); w1b = (__nv_bfloat16*)p; }
    { void* p; cudaGetSymbolAddress(&p, g_w2); w2b = (__nv_bfloat16*)p; }

    // allow >48KB dynamic smem on the gemm kernels (idempotent)
    cudaFuncSetAttribute(gemm_gelu_kernel, cudaFuncAttributeMaxDynamicSharedMemorySize, GEMM_SMEM);
    cudaFuncSetAttribute(gemm_res_kernel,  cudaFuncAttributeMaxDynamicSharedMemorySize, GEMM_SMEM);
    cudaFuncSetAttribute(mma_qkv_kernel,   cudaFuncAttributeMaxDynamicSharedMemorySize, GEMM_SMEM);

    // weight pre-conversion (2 batched launches)
    {
        int n4a = Lsz*Hsz*Hsz/4;
        int n4f = Lsz*Hsz*DFFsz/4;
        cvt4_kernel<<<dim3((n4a+255)/256, 4), 256>>>(Wq, Wk, Wv, Wo, wqb, wkb, wvb, wob, n4a);
        cvt2_kernel<<<dim3((n4f+255)/256, 2), 256>>>(W1, W2, w1b, w2b, n4f);
    }

    embed_kernel<<<Tsz, 256>>>(input_ids, token_emb, pos_emb, t);
    ln_kernel<<<Tsz, 256>>>(t, ln_emb_s, ln_emb_b, x, xb);

    for (int l = 0; l < Lsz; l++) {
        const __nv_bfloat16* wq = wqb + (size_t)l*Hsz*Hsz;
        const __nv_bfloat16* wk = wkb + (size_t)l*Hsz*Hsz;
        const __nv_bfloat16* wv = wvb + (size_t)l*Hsz*Hsz;
        const __nv_bfloat16* wo = wob + (size_t)l*Hsz*Hsz;

        mma_qkv_kernel<<<dim3(Hsz/128, Tsz/128, 3), 256, GEMM_SMEM>>>(
            xb, wq, wk, wv, bq + l*Hsz, bk + l*Hsz, bv + l*Hsz, qb, kb, vb);

        flash_attn_kernel<<<dim3(Ssz/64, Bsz*NHsz), 128>>>(qb, kb, vb, attn_mask, cb);

        gemm_res_kernel<<<dim3(Hsz/128, Tsz/128), 256, GEMM_SMEM>>>(
            cb, wo, bo + l*Hsz, x, t, Hsz, Hsz);
        ln_kernel<<<Tsz, 256>>>(t, ln1_s + l*Hsz, ln1_b + l*Hsz, x, xb);

        gemm_gelu_kernel<<<dim3(DFFsz/128, Tsz/128), 256, GEMM_SMEM>>>(
            xb, w1b + (size_t)l*Hsz*DFFsz, b1 + l*DFFsz, hb, DFFsz, Hsz);
        gemm_res_kernel<<<dim3(Hsz/128, Tsz/128), 256, GEMM_SMEM>>>(
            hb, w2b + (size_t)l*DFFsz*Hsz, b2 + l*Hsz, x, t, Hsz, DFFsz);
        ln_kernel<<<Tsz, 256>>>(t, ln2_s + l*Hsz, ln2_b + l*Hsz, x, xb);
    }

    sgemm_kernel<<<dim3(1, Tsz/64), 256>>>(x, cls_W, cls_b, lg, Tsz, NLsz, Hsz);
    crf_kernel<<<1, 256>>>(lg, labels, attn_mask, start_tr, end_tr, trans, (float*)d_out);
}

// round 16
// speedup vs baseline: 7.1888x; 1.0008x over previous
#include <cuda_runtime.h>
#include <cuda_bf16.h>
#include <math.h>
#include <stdint.h>

#define Bsz  8
#define Ssz  512
#define Hsz  768
#define Lsz  12
#define NHsz 12
#define DHsz 64
#define DFFsz 3072
#define NLsz 19
#define Tsz  (Bsz*Ssz)   // 4096 tokens

// ---------------- scratch ----------------
__device__ float          g_x [Tsz*Hsz];
__device__ float          g_t [Tsz*Hsz];
__device__ __nv_bfloat16  g_xb[Tsz*Hsz];
__device__ __nv_bfloat16  g_qb[Tsz*Hsz];
__device__ __nv_bfloat16  g_kb[Tsz*Hsz];
__device__ __nv_bfloat16  g_vb[Tsz*Hsz];
__device__ __nv_bfloat16  g_cb[Tsz*Hsz];
__device__ __nv_bfloat16  g_hb[Tsz*DFFsz];
__device__ float          g_lg[Tsz*NLsz];
// bf16 weights (pre-converted each launch)
__device__ __nv_bfloat16  g_wq[Lsz*Hsz*Hsz];
__device__ __nv_bfloat16  g_wk[Lsz*Hsz*Hsz];
__device__ __nv_bfloat16  g_wv[Lsz*Hsz*Hsz];
__device__ __nv_bfloat16  g_wo[Lsz*Hsz*Hsz];
__device__ __nv_bfloat16  g_w1[Lsz*Hsz*DFFsz];
__device__ __nv_bfloat16  g_w2[Lsz*DFFsz*Hsz];

// ---------------- fp32 -> bf16 convert (batched over 4 / 2 tensors) ----------------
__device__ __forceinline__ void cvt_body(const float* __restrict__ in,
                                         __nv_bfloat16* __restrict__ out, int n4)
{
    int i = blockIdx.x*blockDim.x + threadIdx.x;
    if (i < n4) {
        float4 f = ((const float4*)in)[i];
        __nv_bfloat162 a = __floats2bfloat162_rn(f.x, f.y);
        __nv_bfloat162 b = __floats2bfloat162_rn(f.z, f.w);
        uint2 o; o.x = *(uint32_t*)&a; o.y = *(uint32_t*)&b;
        ((uint2*)out)[i] = o;
    }
}
__global__ void cvt4_kernel(const float* __restrict__ w0, const float* __restrict__ w1,
                            const float* __restrict__ w2, const float* __restrict__ w3,
                            __nv_bfloat16* __restrict__ o0, __nv_bfloat16* __restrict__ o1,
                            __nv_bfloat16* __restrict__ o2, __nv_bfloat16* __restrict__ o3,
                            int n4)
{
    int z = blockIdx.y;
    const float* in = (z == 0) ? w0 : (z == 1) ? w1 : (z == 2) ? w2 : w3;
    __nv_bfloat16* out = (z == 0) ? o0 : (z == 1) ? o1 : (z == 2) ? o2 : o3;
    cvt_body(in, out, n4);
}
__global__ void cvt2_kernel(const float* __restrict__ w0, const float* __restrict__ w1,
                            __nv_bfloat16* __restrict__ o0, __nv_bfloat16* __restrict__ o1,
                            int n4)
{
    int z = blockIdx.y;
    cvt_body(z ? w1 : w0, z ? o1 : o0, n4);
}

// ---------------- embedding ----------------
__global__ void embed_kernel(const int* __restrict__ ids,
                             const float* __restrict__ tok,
                             const float* __restrict__ pos,
                             float* __restrict__ out)
{
    int t = blockIdx.x;
    int s = t & (Ssz-1);
    int id = ids[t];
    const float* tp = tok + (size_t)id*Hsz;
    const float* pp = pos + (size_t)s*Hsz;
    float* op = out + (size_t)t*Hsz;
    for (int c = threadIdx.x; c < Hsz; c += blockDim.x)
        op[c] = tp[c] + pp[c];
}

// ---------------- layernorm (writes fp32 + bf16) ----------------
__global__ void ln_kernel(const float* __restrict__ in,
                          const float* __restrict__ gamma,
                          const float* __restrict__ beta,
                          float* __restrict__ out,
                          __nv_bfloat16* __restrict__ outb)
{
    __shared__ float sh[32];
    int row = blockIdx.x;
    int tid = threadIdx.x;
    const float* p = in + (size_t)row*Hsz;
    float v0 = p[tid], v1 = p[tid+256], v2 = p[tid+512];
    float s = v0+v1+v2;
    int lane = tid & 31, w = tid >> 5;
    for (int o = 16; o; o >>= 1) s += __shfl_xor_sync(0xffffffffu, s, o);
    if (!lane) sh[w] = s;
    __syncthreads();
    if (w == 0) {
        s = (lane < 8) ? sh[lane] : 0.f;
        for (int o = 4; o; o >>= 1) s += __shfl_xor_sync(0xffffffffu, s, o);
        if (!lane) sh[0] = s;
    }
    __syncthreads();
    float mean = sh[0] * (1.0f/Hsz);
    __syncthreads();
    float d0 = v0-mean, d1 = v1-mean, d2 = v2-mean;
    float q = d0*d0 + d1*d1 + d2*d2;
    for (int o = 16; o; o >>= 1) q += __shfl_xor_sync(0xffffffffu, q, o);
    if (!lane) sh[w] = q;
    __syncthreads();
    if (w == 0) {
        q = (lane < 8) ? sh[lane] : 0.f;
        for (int o = 4; o; o >>= 1) q += __shfl_xor_sync(0xffffffffu, q, o);
        if (!lane) sh[0] = q;
    }
    __syncthreads();
    float var = sh[0] * (1.0f/Hsz);
    float inv = rsqrtf(var + 1e-12f);
    float* op = out + (size_t)row*Hsz;
    __nv_bfloat16* ob = outb + (size_t)row*Hsz;
    float r0 = d0*inv*gamma[tid    ] + beta[tid    ];
    float r1 = d1*inv*gamma[tid+256] + beta[tid+256];
    float r2 = d2*inv*gamma[tid+512] + beta[tid+512];
    op[tid] = r0; op[tid+256] = r1; op[tid+512] = r2;
    ob[tid] = __float2bfloat16(r0);
    ob[tid+256] = __float2bfloat16(r1);
    ob[tid+512] = __float2bfloat16(r2);
}

// ================= MMA / async primitives =================
__device__ __forceinline__ void ldsm_x4(uint32_t (&r)[4], uint32_t addr) {
    asm volatile("ldmatrix.sync.aligned.m8n8.x4.shared.b16 {%0,%1,%2,%3}, [%4];"
        : "=r"(r[0]),"=r"(r[1]),"=r"(r[2]),"=r"(r[3]) : "r"(addr));
}
__device__ __forceinline__ void ldsm_x4_t(uint32_t (&r)[4], uint32_t addr) {
    asm volatile("ldmatrix.sync.aligned.m8n8.x4.trans.shared.b16 {%0,%1,%2,%3}, [%4];"
        : "=r"(r[0]),"=r"(r[1]),"=r"(r[2]),"=r"(r[3]) : "r"(addr));
}
__device__ __forceinline__ void mma16816(float (&c)[4], const uint32_t (&a)[4],
                                         uint32_t b0, uint32_t b1) {
    asm volatile("mma.sync.aligned.m16n8k16.row.col.f32.bf16.bf16.f32 "
        "{%0,%1,%2,%3}, {%4,%5,%6,%7}, {%8,%9}, {%0,%1,%2,%3};"
        : "+f"(c[0]),"+f"(c[1]),"+f"(c[2]),"+f"(c[3])
        : "r"(a[0]),"r"(a[1]),"r"(a[2]),"r"(a[3]), "r"(b0),"r"(b1));
}
__device__ __forceinline__ uint32_t pack_bf16(float x, float y) {
    __nv_bfloat162 h = __floats2bfloat162_rn(x, y);
    return *(uint32_t*)&h;
}
__device__ __forceinline__ void cp16(uint32_t smem, const void* g) {
    asm volatile("cp.async.cg.shared.global [%0], [%1], 16;" :: "r"(smem), "l"(g));
}
__device__ __forceinline__ void cp_commit() { asm volatile("cp.async.commit_group;"); }
__device__ __forceinline__ void cp_wait2()  { asm volatile("cp.async.wait_group 2;"); }
__device__ __forceinline__ void cp_wait1()  { asm volatile("cp.async.wait_group 1;"); }
__device__ __forceinline__ void cp_wait0()  { asm volatile("cp.async.wait_group 0;"); }
__device__ __forceinline__ float fast_gelu(float v) {
    float z = 0.7978845608028654f*(v + 0.044715f*v*v*v);
    float t; asm("tanh.approx.f32 %0, %1;" : "=f"(t) : "f"(z));
    return 0.5f*v*(1.0f + t);
}

// ================= bf16 GEMM, 4-stage cp.async pipeline =================
// C = A[M,K](bf16) @ W[K,N](bf16) + bias; MODE: 1=gelu->bf16, 2=residual->fp32, 3=bias->bf16
#define APAD 40    // A smem row stride (bf16 elems), 80B
#define WPAD 136   // W smem row stride, 272B
#define NSTG 4
#define A_STG (128*APAD)
#define W_STG (32*WPAD)
#define GEMM_SMEM ((NSTG*(A_STG + W_STG))*2)   // 75776 bytes

template<int MODE>
__device__ __forceinline__ void gemm_core(
    const __nv_bfloat16* __restrict__ A, const __nv_bfloat16* __restrict__ W,
    const float* __restrict__ bias, const float* __restrict__ res,
    void* __restrict__ Cout, int N, int K, int m0, int n0)
{
    extern __shared__ __nv_bfloat16 dsm[];
    __nv_bfloat16* As = dsm;                 // NSTG stages of 128*APAD
    __nv_bfloat16* Ws = dsm + NSTG*A_STG;    // NSTG stages of 32*WPAD
    int tid = threadIdx.x;
    int warp = tid >> 5, lane = tid & 31;
    int wm = warp >> 2;
    int wn = warp & 3;
    uint32_t as_base = (uint32_t)__cvta_generic_to_shared(As);
    uint32_t ws_base = (uint32_t)__cvta_generic_to_shared(Ws);

    float acc[4][4][4];
    #pragma unroll
    for (int i = 0; i < 4; i++)
        #pragma unroll
        for (int j = 0; j < 4; j++)
            #pragma unroll
            for (int e = 0; e < 4; e++) acc[i][j][e] = 0.f;

    const int KT = K >> 5;

    // row/col assignments for loads (2 cp16 each for A and W)
    int ar0 = tid >> 2,          ac0 = (tid & 3)*8;
    int ar1 = (tid+256) >> 2,    ac1 = (tid & 3)*8;
    int wr0 = tid >> 4,          wc0 = (tid & 15)*8;
    int wr1 = (tid+256) >> 4,    wc1 = (tid & 15)*8;

    // prologue: stages 0..2
    #pragma unroll
    for (int st = 0; st < NSTG-1; st++) {
        int k0 = st << 5;
        cp16(as_base + (st*A_STG + ar0*APAD + ac0)*2, A + (size_t)(m0 + ar0)*K + k0 + ac0);
        cp16(as_base + (st*A_STG + ar1*APAD + ac1)*2, A + (size_t)(m0 + ar1)*K + k0 + ac1);
        cp16(ws_base + (st*W_STG + wr0*WPAD + wc0)*2, W + (size_t)(k0 + wr0)*N + n0 + wc0);
        cp16(ws_base + (st*W_STG + wr1*WPAD + wc1)*2, W + (size_t)(k0 + wr1)*N + n0 + wc1);
        cp_commit();
    }

    for (int kt = 0; kt < KT; kt++) {
        if (kt < KT-2)      cp_wait2();
        else if (kt == KT-2) cp_wait1();
        else                 cp_wait0();
        __syncthreads();

        int cur = kt & (NSTG-1);
        const __nv_bfloat16* Ac = As + cur*A_STG;
        const __nv_bfloat16* Wc = Ws + cur*W_STG;
        #pragma unroll
        for (int ks = 0; ks < 2; ks++) {
            uint32_t af[4][4];
            #pragma unroll
            for (int i = 0; i < 4; i++) {
                int r = wm*64 + i*16 + (lane & 15);
                int c = ks*16 + (lane >> 4)*8;
                ldsm_x4(af[i], (uint32_t)__cvta_generic_to_shared(Ac + r*APAD + c));
            }
            uint32_t bf[2][4];
            #pragma unroll
            for (int j2 = 0; j2 < 2; j2++) {
                int kk = ks*16 + ((lane>>3)&1)*8 + (lane&7);
                int nn = wn*32 + j2*16 + (lane>>4)*8;
                ldsm_x4_t(bf[j2], (uint32_t)__cvta_generic_to_shared(Wc + kk*WPAD + nn));
            }
            #pragma unroll
            for (int i = 0; i < 4; i++)
                #pragma unroll
                for (int j = 0; j < 4; j++)
                    mma16816(acc[i][j], af[i], bf[j>>1][(j&1)*2], bf[j>>1][(j&1)*2+1]);
        }

        if (kt + NSTG-1 < KT) {
            int st = (kt + NSTG-1) & (NSTG-1);
            int k0 = (kt + NSTG-1) << 5;
            cp16(as_base + (st*A_STG + ar0*APAD + ac0)*2, A + (size_t)(m0 + ar0)*K + k0 + ac0);
            cp16(as_base + (st*A_STG + ar1*APAD + ac1)*2, A + (size_t)(m0 + ar1)*K + k0 + ac1);
            cp16(ws_base + (st*W_STG + wr0*WPAD + wc0)*2, W + (size_t)(k0 + wr0)*N + n0 + wc0);
            cp16(ws_base + (st*W_STG + wr1*WPAD + wc1)*2, W + (size_t)(k0 + wr1)*N + n0 + wc1);
            cp_commit();
        }
    }

    // epilogue
    #pragma unroll
    for (int i = 0; i < 4; i++) {
        int mb = m0 + wm*64 + i*16 + (lane >> 2);
        #pragma unroll
        for (int j = 0; j < 4; j++) {
            int nb = n0 + wn*32 + j*8 + (lane & 3)*2;
            float b0 = bias[nb], b1 = bias[nb+1];
            #pragma unroll
            for (int half = 0; half < 2; half++) {
                int m = mb + half*8;
                float v0 = acc[i][j][half*2]   + b0;
                float v1 = acc[i][j][half*2+1] + b1;
                if (MODE == 1) {
                    v0 = fast_gelu(v0);
                    v1 = fast_gelu(v1);
                } else if (MODE == 2) {
                    float2 r2 = *(const float2*)(res + (size_t)m*N + nb);
                    v0 += r2.x; v1 += r2.y;
                }
                if (MODE == 1 || MODE == 3) {
                    *(__nv_bfloat162*)((__nv_bfloat16*)Cout + (size_t)m*N + nb) =
                        __floats2bfloat162_rn(v0, v1);
                } else {
                    float2 o; o.x = v0; o.y = v1;
                    *(float2*)((float*)Cout + (size_t)m*N + nb) = o;
                }
            }
        }
    }
}

__global__ __launch_bounds__(256,2) void gemm_gelu_kernel(
    const __nv_bfloat16* __restrict__ A, const __nv_bfloat16* __restrict__ W,
    const float* __restrict__ bias, __nv_bfloat16* __restrict__ C, int N, int K)
{
    gemm_core<1>(A, W, bias, nullptr, C, N, K, blockIdx.y*128, blockIdx.x*128);
}
__global__ __launch_bounds__(256,2) void gemm_res_kernel(
    const __nv_bfloat16* __restrict__ A, const __nv_bfloat16* __restrict__ W,
    const float* __restrict__ bias, const float* __restrict__ res,
    float* __restrict__ C, int N, int K)
{
    gemm_core<2>(A, W, bias, res, C, N, K, blockIdx.y*128, blockIdx.x*128);
}
__global__ __launch_bounds__(256,2) void mma_qkv_kernel(
    const __nv_bfloat16* __restrict__ A,
    const __nv_bfloat16* __restrict__ Wq, const __nv_bfloat16* __restrict__ Wk,
    const __nv_bfloat16* __restrict__ Wv,
    const float* __restrict__ bq, const float* __restrict__ bk, const float* __restrict__ bv,
    __nv_bfloat16* __restrict__ q, __nv_bfloat16* __restrict__ k, __nv_bfloat16* __restrict__ v)
{
    int z = blockIdx.z;
    const __nv_bfloat16* W = (z == 0) ? Wq : (z == 1) ? Wk : Wv;
    const float* bb = (z == 0) ? bq : (z == 1) ? bk : bv;
    __nv_bfloat16* C = (z == 0) ? q : (z == 1) ? k : v;
    gemm_core<3>(A, W, bb, nullptr, C, Hsz, Hsz, blockIdx.y*128, blockIdx.x*128);
}

// ================= flash attention (cp.async double-buffered KV) =================
#define FPAD 72

__global__ __launch_bounds__(128) void flash_attn_kernel(
    const __nv_bfloat16* __restrict__ q, const __nv_bfloat16* __restrict__ k,
    const __nv_bfloat16* __restrict__ v, const int* __restrict__ mask,
    __nv_bfloat16* __restrict__ ctx)
{
    __shared__ __nv_bfloat16 Qs[64*FPAD];
    __shared__ __nv_bfloat16 Ks[2][64*FPAD];
    __shared__ __nv_bfloat16 Vs[2][64*FPAD];
    __shared__ float s_bias[Ssz];

    int bh = blockIdx.y;
    int b = bh / NHsz, h = bh % NHsz;
    int i0 = blockIdx.x * 64;
    int tid = threadIdx.x;
    int warp = tid >> 5, lane = tid & 31;
    int g = lane >> 2, t4 = lane & 3;
    uint32_t ks_base = (uint32_t)__cvta_generic_to_shared(&Ks[0][0]);
    uint32_t vs_base = (uint32_t)__cvta_generic_to_shared(&Vs[0][0]);

    #pragma unroll
    for (int it = 0; it < 4; it++) {
        int j = tid + it*128;
        s_bias[j] = mask[b*Ssz + j] ? 0.f : -1e9f;
    }
    #pragma unroll
    for (int it = 0; it < 4; it++) {
        int idx = tid + it*128;
        int r = idx >> 3, c8 = idx & 7;
        *(uint4*)&Qs[r*FPAD + c8*8] =
            *(const uint4*)(q + (size_t)(b*Ssz + i0 + r)*Hsz + h*DHsz + c8*8);
    }
    __syncthreads();

    uint32_t qf[4][4];
    #pragma unroll
    for (int ks = 0; ks < 4; ks++) {
        int r = warp*16 + (lane & 15);
        int c = ks*16 + (lane >> 4)*8;
        ldsm_x4(qf[ks], (uint32_t)__cvta_generic_to_shared(&Qs[r*FPAD + c]));
    }

    #pragma unroll
    for (int it = 0; it < 4; it++) {
        int idx = tid + it*128;
        int r = idx >> 3, c8 = idx & 7;
        size_t goff = (size_t)(b*Ssz + r)*Hsz + h*DHsz + c8*8;
        cp16(ks_base + (r*FPAD + c8*8)*2, k + goff);
        cp16(vs_base + (r*FPAD + c8*8)*2, v + goff);
    }
    cp_commit();

    float oacc[8][4];
    #pragma unroll
    for (int n = 0; n < 8; n++)
        #pragma unroll
        for (int e = 0; e < 4; e++) oacc[n][e] = 0.f;
    float m0v = -1e30f, m1v = -1e30f, l0 = 0.f, l1 = 0.f;

    const int NT = Ssz/64;
    for (int jt = 0; jt < NT; jt++) {
        int cur = jt & 1;
        int j0 = jt*64;
        if (jt + 1 < NT) {
            int st = cur ^ 1;
            int j0n = j0 + 64;
            #pragma unroll
            for (int it = 0; it < 4; it++) {
                int idx = tid + it*128;
                int r = idx >> 3, c8 = idx & 7;
                size_t goff = (size_t)(b*Ssz + j0n + r)*Hsz + h*DHsz + c8*8;
                cp16(ks_base + (st*64*FPAD + r*FPAD + c8*8)*2, k + goff);
                cp16(vs_base + (st*64*FPAD + r*FPAD + c8*8)*2, v + goff);
            }
            cp_commit();
            cp_wait1();
        } else {
            cp_wait0();
        }
        __syncthreads();

        float acc[8][4];
        #pragma unroll
        for (int n = 0; n < 8; n++)
            #pragma unroll
            for (int e = 0; e < 4; e++) acc[n][e] = 0.f;
        #pragma unroll
        for (int jj = 0; jj < 4; jj++) {
            #pragma unroll
            for (int ks = 0; ks < 4; ks++) {
                uint32_t bf[4];
                int r = jj*16 + (lane & 15);
                int c = ks*16 + (lane >> 4)*8;
                ldsm_x4(bf, (uint32_t)__cvta_generic_to_shared(&Ks[cur][r*FPAD + c]));
                mma16816(acc[jj*2  ], qf[ks], bf[0], bf[2]);
                mma16816(acc[jj*2+1], qf[ks], bf[1], bf[3]);
            }
        }

        float p[8][4];
        float mx0 = -1e30f, mx1 = -1e30f;
        #pragma unroll
        for (int n = 0; n < 8; n++) {
            float b0 = s_bias[j0 + n*8 + t4*2];
            float b1 = s_bias[j0 + n*8 + t4*2 + 1];
            p[n][0] = acc[n][0]*0.125f + b0;
            p[n][1] = acc[n][1]*0.125f + b1;
            p[n][2] = acc[n][2]*0.125f + b0;
            p[n][3] = acc[n][3]*0.125f + b1;
            mx0 = fmaxf(mx0, fmaxf(p[n][0], p[n][1]));
            mx1 = fmaxf(mx1, fmaxf(p[n][2], p[n][3]));
        }
        mx0 = fmaxf(mx0, __shfl_xor_sync(0xffffffffu, mx0, 1));
        mx0 = fmaxf(mx0, __shfl_xor_sync(0xffffffffu, mx0, 2));
        mx1 = fmaxf(mx1, __shfl_xor_sync(0xffffffffu, mx1, 1));
        mx1 = fmaxf(mx1, __shfl_xor_sync(0xffffffffu, mx1, 2));
        float mn0 = fmaxf(m0v, mx0);
        float mn1 = fmaxf(m1v, mx1);
        float lt0 = 0.f, lt1 = 0.f;
        #pragma unroll
        for (int n = 0; n < 8; n++) {
            p[n][0] = __expf(p[n][0] - mn0);
            p[n][1] = __expf(p[n][1] - mn0);
            p[n][2] = __expf(p[n][2] - mn1);
            p[n][3] = __expf(p[n][3] - mn1);
            lt0 += p[n][0] + p[n][1];
            lt1 += p[n][2] + p[n][3];
        }
        lt0 += __shfl_xor_sync(0xffffffffu, lt0, 1);
        lt0 += __shfl_xor_sync(0xffffffffu, lt0, 2);
        lt1 += __shfl_xor_sync(0xffffffffu, lt1, 1);
        lt1 += __shfl_xor_sync(0xffffffffu, lt1, 2);
        float sc0 = __expf(m0v - mn0);
        float sc1 = __expf(m1v - mn1);
        l0 = l0*sc0 + lt0;
        l1 = l1*sc1 + lt1;
        m0v = mn0; m1v = mn1;
        #pragma unroll
        for (int n = 0; n < 8; n++) {
            oacc[n][0] *= sc0; oacc[n][1] *= sc0;
            oacc[n][2] *= sc1; oacc[n][3] *= sc1;
        }

        uint32_t pa[4][4];
        #pragma unroll
        for (int c = 0; c < 4; c++) {
            pa[c][0] = pack_bf16(p[2*c  ][0], p[2*c  ][1]);
            pa[c][1] = pack_bf16(p[2*c  ][2], p[2*c  ][3]);
            pa[c][2] = pack_bf16(p[2*c+1][0], p[2*c+1][1]);
            pa[c][3] = pack_bf16(p[2*c+1][2], p[2*c+1][3]);
        }

        #pragma unroll
        for (int db = 0; db < 4; db++) {
            #pragma unroll
            for (int c = 0; c < 4; c++) {
                uint32_t vf[4];
                int kk = c*16 + ((lane>>3)&1)*8 + (lane&7);
                int nn = db*16 + (lane>>4)*8;
                ldsm_x4_t(vf, (uint32_t)__cvta_generic_to_shared(&Vs[cur][kk*FPAD + nn]));
                mma16816(oacc[db*2  ], pa[c], vf[0], vf[1]);
                mma16816(oacc[db*2+1], pa[c], vf[2], vf[3]);
            }
        }
        __syncthreads();
    }

    float inv0 = 1.0f / l0, inv1 = 1.0f / l1;
    #pragma unroll
    for (int n = 0; n < 8; n++) {
        int d = n*8 + t4*2;
        int r0 = i0 + warp*16 + g;
        *(__nv_bfloat162*)(ctx + (size_t)(b*Ssz + r0)*Hsz + h*DHsz + d) =
            __floats2bfloat162_rn(oacc[n][0]*inv0, oacc[n][1]*inv0);
        *(__nv_bfloat162*)(ctx + (size_t)(b*Ssz + r0 + 8)*Hsz + h*DHsz + d) =
            __floats2bfloat162_rn(oacc[n][2]*inv1, oacc[n][3]*inv1);
    }
}

// ---------------- classifier (N=19, SIMT) ----------------
__global__ void sgemm_kernel(const float* __restrict__ A, const float* __restrict__ W,
                             const float* __restrict__ bias, float* __restrict__ C,
                             int M, int N, int K)
{
    __shared__ float As[64][17];
    __shared__ float Ws[16][64];
    int m0 = blockIdx.y * 64;
    int n0 = blockIdx.x * 64;
    int tid = threadIdx.x;
    int ty = tid >> 4, tx = tid & 15;
    float acc[4][4] = {};
    for (int k0 = 0; k0 < K; k0 += 16) {
        #pragma unroll
        for (int i = 0; i < 4; i++) {
            int idx = tid + i*256;
            int r = idx >> 4, c = idx & 15;
            As[r][c] = A[(size_t)(m0+r)*K + (k0+c)];
        }
        #pragma unroll
        for (int i = 0; i < 4; i++) {
            int idx = tid + i*256;
            int r = idx >> 6, c = idx & 63;
            int n = n0 + c;
            Ws[r][c] = (n < N) ? W[(size_t)(k0+r)*N + n] : 0.f;
        }
        __syncthreads();
        #pragma unroll
        for (int kk = 0; kk < 16; kk++) {
            float a[4], b[4];
            #pragma unroll
            for (int i = 0; i < 4; i++) a[i] = As[ty*4+i][kk];
            #pragma unroll
            for (int j = 0; j < 4; j++) b[j] = Ws[kk][tx*4+j];
            #pragma unroll
            for (int i = 0; i < 4; i++)
                #pragma unroll
                for (int j = 0; j < 4; j++)
                    acc[i][j] = fmaf(a[i], b[j], acc[i][j]);
        }
        __syncthreads();
    }
    #pragma unroll
    for (int i = 0; i < 4; i++) {
        int m = m0 + ty*4 + i;
        #pragma unroll
        for (int j = 0; j < 4; j++) {
            int n = n0 + tx*4 + j;
            if (n < N) C[(size_t)m*N + n] = acc[i][j] + bias[n];
        }
    }
}

// ---------------- CRF ----------------
__global__ void crf_kernel(const float* __restrict__ lg, const int* __restrict__ labels,
                           const int* __restrict__ mask, const float* __restrict__ st,
                           const float* __restrict__ en, const float* __restrict__ tr,
                           float* __restrict__ out)
{
    __shared__ float s_tr[NLsz*NLsz];
    __shared__ float s_res[Bsz];
    for (int i = threadIdx.x; i < NLsz*NLsz; i += blockDim.x) s_tr[i] = tr[i];
    __syncthreads();
    int warp = threadIdx.x >> 5, lane = threadIdx.x & 31;
    if (warp < Bsz) {
        int b = warp;
        const int* lab = labels + b*Ssz;
        const int* mk  = mask + b*Ssz;
        const float* lgb = lg + (size_t)b*Ssz*NLsz;
        float part = 0.f; int cnt = 0;
        for (int t = lane; t < Ssz; t += 32) {
            cnt += mk[t];
            if (t >= 1) {
                float mf = (float)mk[t];
                part += (s_tr[lab[t-1]*NLsz + lab[t]] + lgb[t*NLsz + lab[t]]) * mf;
            }
        }
        for (int o = 16; o; o >>= 1) {
            part += __shfl_xor_sync(0xffffffffu, part, o);
            cnt  += __shfl_xor_sync(0xffffffffu, cnt, o);
        }
        float num = 0.f;
        if (lane == 0) {
            int l0 = lab[0];
            num = st[l0] + lgb[l0] + part + en[lab[cnt-1]];
        }
        int j = lane;
        float alpha = (j < NLsz) ? st[j] + lgb[j] : -1e30f;
        for (int t = 1; t < Ssz; t++) {
            float g[NLsz];
            #pragma unroll
            for (int i = 0; i < NLsz; i++)
                g[i] = __shfl_sync(0xffffffffu, alpha, i) + ((j < NLsz) ? s_tr[i*NLsz + j] : 0.f);
            float mv = g[0];
            #pragma unroll
            for (int i = 1; i < NLsz; i++) mv = fmaxf(mv, g[i]);
            float sum = 0.f;
            #pragma unroll
            for (int i = 0; i < NLsz; i++) sum += expf(g[i] - mv);
            float nxt = mv + logf(sum) + ((j < NLsz) ? lgb[t*NLsz + j] : 0.f);
            if (mk[t] > 0 && j < NLsz) alpha = nxt;
        }
        float v = (j < NLsz) ? alpha + en[j] : -1e30f;
        float mv = v;
        for (int o = 16; o; o >>= 1) mv = fmaxf(mv, __shfl_xor_sync(0xffffffffu, mv, o));
        float s = (j < NLsz) ? expf(v - mv) : 0.f;
        for (int o = 16; o; o >>= 1) s += __shfl_xor_sync(0xffffffffu, s, o);
        if (lane == 0) s_res[b] = (mv + logf(s)) - num;
    }
    __syncthreads();
    if (threadIdx.x == 0) {
        float tot = 0.f;
        for (int b = 0; b < Bsz; b++) tot += s_res[b];
        out[0] = tot;
    }
}

// ---------------- host ----------------
extern "C" void kernel_launch(void* const* d_in, const int* in_sizes, int n_in,
                              void* d_out, int out_size)
{
    const int*   input_ids = (const int*)  d_in[0];
    const int*   attn_mask = (const int*)  d_in[1];
    const int*   labels    = (const int*)  d_in[2];
    const float* token_emb = (const float*)d_in[3];
    const float* pos_emb   = (const float*)d_in[4];
    const float* ln_emb_s  = (const float*)d_in[5];
    const float* ln_emb_b  = (const float*)d_in[6];
    const float* Wq        = (const float*)d_in[7];
    const float* bq        = (const float*)d_in[8];
    const float* Wk        = (const float*)d_in[9];
    const float* bk        = (const float*)d_in[10];
    const float* Wv        = (const float*)d_in[11];
    const float* bv        = (const float*)d_in[12];
    const float* Wo        = (const float*)d_in[13];
    const float* bo        = (const float*)d_in[14];
    const float* ln1_s     = (const float*)d_in[15];
    const float* ln1_b     = (const float*)d_in[16];
    const float* W1        = (const float*)d_in[17];
    const float* b1        = (const float*)d_in[18];
    const float* W2        = (const float*)d_in[19];
    const float* b2        = (const float*)d_in[20];
    const float* ln2_s     = (const float*)d_in[21];
    const float* ln2_b     = (const float*)d_in[22];
    const float* cls_W     = (const float*)d_in[23];
    const float* cls_b     = (const float*)d_in[24];
    const float* start_tr  = (const float*)d_in[25];
    const float* end_tr    = (const float*)d_in[26];
    const float* trans     = (const float*)d_in[27];

    float *x, *t, *lg;
    __nv_bfloat16 *xb, *qb, *kb, *vb, *cb, *hb;
    __nv_bfloat16 *wqb, *wkb, *wvb, *wob, *w1b, *w2b;
    { void* p; cudaGetSymbolAddress(&p, g_x);  x  = (float*)p; }
    { void* p; cudaGetSymbolAddress(&p, g_t);  t  = (float*)p; }
    { void* p; cudaGetSymbolAddress(&p, g_lg); lg = (float*)p; }
    { void* p; cudaGetSymbolAddress(&p, g_xb); xb = (__nv_bfloat16*)p; }
    { void* p; cudaGetSymbolAddress(&p, g_qb); qb = (__nv_bfloat16*)p; }
    { void* p; cudaGetSymbolAddress(&p, g_kb); kb = (__nv_bfloat16*)p; }
    { void* p; cudaGetSymbolAddress(&p, g_vb); vb = (__nv_bfloat16*)p; }
    { void* p; cudaGetSymbolAddress(&p, g_cb); cb = (__nv_bfloat16*)p; }
    { void* p; cudaGetSymbolAddress(&p, g_hb); hb = (__nv_bfloat16*)p; }
    { void* p; cudaGetSymbolAddress(&p, g_wq); wqb = (__nv_bfloat16*)p; }
    { void* p; cudaGetSymbolAddress(&p, g_wk); wkb = (__nv_bfloat16*)p; }
    { void* p; cudaGetSymbolAddress(&p, g_wv); wvb = (__nv_bfloat16*)p; }
    { void* p; cudaGetSymbolAddress(&p, g_wo); wob = (__nv_bfloat16*)p; }
    { void* p; cudaGetSymbolAddress(&p, g_w1); w1b = (__nv_bfloat16*)p; }
    { void* p; cudaGetSymbolAddress(&p, g_w2); w2b = (__nv_bfloat16*)p; }

    // allow >48KB dynamic smem on the gemm kernels (idempotent)
    cudaFuncSetAttribute(gemm_gelu_kernel, cudaFuncAttributeMaxDynamicSharedMemorySize, GEMM_SMEM);
    cudaFuncSetAttribute(gemm_res_kernel,  cudaFuncAttributeMaxDynamicSharedMemorySize, GEMM_SMEM);
    cudaFuncSetAttribute(mma_qkv_kernel,   cudaFuncAttributeMaxDynamicSharedMemorySize, GEMM_SMEM);

    // weight pre-conversion (2 batched launches)
    {
        int n4a = Lsz*Hsz*Hsz/4;
        int n4f = Lsz*Hsz*DFFsz/4;
        cvt4_kernel<<<dim3((n4a+255)/256, 4), 256>>>(Wq, Wk, Wv, Wo, wqb, wkb, wvb, wob, n4a);
        cvt2_kernel<<<dim3((n4f+255)/256, 2), 256>>>(W1, W2, w1b, w2b, n4f);
    }

    embed_kernel<<<Tsz, 256>>>(input_ids, token_emb, pos_emb, t);
    ln_kernel<<<Tsz, 256>>>(t, ln_emb_s, ln_emb_b, x, xb);

    for (int l = 0; l < Lsz; l++) {
        const __nv_bfloat16* wq = wqb + (size_t)l*Hsz*Hsz;
        const __nv_bfloat16* wk = wkb + (size_t)l*Hsz*Hsz;
        const __nv_bfloat16* wv = wvb + (size_t)l*Hsz*Hsz;
        const __nv_bfloat16* wo = wob + (size_t)l*Hsz*Hsz;

        mma_qkv_kernel<<<dim3(Hsz/128, Tsz/128, 3), 256, GEMM_SMEM>>>(
            xb, wq, wk, wv, bq + l*Hsz, bk + l*Hsz, bv + l*Hsz, qb, kb, vb);

        flash_attn_kernel<<<dim3(Ssz/64, Bsz*NHsz), 128>>>(qb, kb, vb, attn_mask, cb);

        gemm_res_kernel<<<dim3(Hsz/128, Tsz/128), 256, GEMM_SMEM>>>(
            cb, wo, bo + l*Hsz, x, t, Hsz, Hsz);
        ln_kernel<<<Tsz, 256>>>(t, ln1_s + l*Hsz, ln1_b + l*Hsz, x, xb);

        gemm_gelu_kernel<<<dim3(DFFsz/128, Tsz/128), 256, GEMM_SMEM>>>(
            xb, w1b + (size_t)l*Hsz*DFFsz, b1 + l*DFFsz, hb, DFFsz, Hsz);
        gemm_res_kernel<<<dim3(Hsz/128, Tsz/128), 256, GEMM_SMEM>>>(
            hb, w2b + (size_t)l*DFFsz*Hsz, b2 + l*Hsz, x, t, Hsz, DFFsz);
        ln_kernel<<<Tsz, 256>>>(t, ln2_s + l*Hsz, ln2_b + l*Hsz, x, xb);
    }

    sgemm_kernel<<<dim3(1, Tsz/64), 256>>>(x, cls_W, cls_b, lg, Tsz, NLsz, Hsz);
    crf_kernel<<<1, 256>>>(lg, labels, attn_mask, start_tr, end_tr, trans, (float*)d_out);
}